// round 11
// baseline (speedup 1.0000x reference)
#include <cuda_runtime.h>
#include <cuda_bf16.h>
#include <math.h>
#include <cstdint>

// ---------------------------------------------------------------------------
// PhysicsGuidedAttentionCorrected
// B=8, N=1024, C=256, NUM_HEADS=8, hd=32
// R11: QKV GEMM on 64x128 tiles (768 CTAs, full waves);
//      attention warps 4M x 2N (halved K/V ldmatrix redundancy, end-merge
//      of partial O/l through smem); bias permuted to the new layout.
// ---------------------------------------------------------------------------

#define B_ 8
#define N_ 1024
#define C_ 256
#define NH_ 8
#define HD_ 32

// scratch (device globals; no allocations allowed)
__device__ float g_ws[B_ * N_];
__device__ float4 g_bias4[B_ * N_ * N_ / 4];       // fragment-ordered bias
__device__ __nv_bfloat16 g_xh[B_ * N_ * C_];
__device__ __nv_bfloat16 g_xl[B_ * N_ * C_];
__device__ __nv_bfloat16 g_wqkvh[3 * C_ * C_];
__device__ __nv_bfloat16 g_wqkvl[3 * C_ * C_];
__device__ __nv_bfloat16 g_wprojh[C_ * C_];
__device__ __nv_bfloat16 g_wprojl[C_ * C_];
__device__ __nv_bfloat16 g_qkvh[B_ * N_ * 3 * C_];
__device__ __nv_bfloat16 g_qkvl[B_ * N_ * 3 * C_];
__device__ __nv_bfloat16 g_attnh[B_ * N_ * C_];
__device__ __nv_bfloat16 g_attnl[B_ * N_ * C_];

// ---------------------------------------------------------------------------
// helpers
// ---------------------------------------------------------------------------
__device__ __forceinline__ uint32_t smem_u32(const void* p) {
    uint32_t a;
    asm("{ .reg .u64 t; cvta.to.shared.u64 t, %1; cvt.u32.u64 %0, t; }"
        : "=r"(a) : "l"(p));
    return a;
}

#define LDSM_X4(r0, r1, r2, r3, addr)                                        \
    asm volatile("ldmatrix.sync.aligned.m8n8.x4.shared.b16 {%0,%1,%2,%3}, [%4];" \
                 : "=r"(r0), "=r"(r1), "=r"(r2), "=r"(r3) : "r"(addr))

#define LDSM_X4T(r0, r1, r2, r3, addr)                                       \
    asm volatile("ldmatrix.sync.aligned.m8n8.x4.trans.shared.b16 {%0,%1,%2,%3}, [%4];" \
                 : "=r"(r0), "=r"(r1), "=r"(r2), "=r"(r3) : "r"(addr))

#define MMA_BF16(d, a0, a1, a2, a3, b0, b1)                                  \
    asm volatile("mma.sync.aligned.m16n8k16.row.col.f32.bf16.bf16.f32 "      \
                 "{%0,%1,%2,%3}, {%4,%5,%6,%7}, {%8,%9}, {%0,%1,%2,%3};"     \
                 : "+f"((d)[0]), "+f"((d)[1]), "+f"((d)[2]), "+f"((d)[3])    \
                 : "r"(a0), "r"(a1), "r"(a2), "r"(a3), "r"(b0), "r"(b1))

#define CP_ASYNC16(saddr, gptr)                                              \
    asm volatile("cp.async.cg.shared.global [%0], [%1], 16;"                 \
                 :: "r"(saddr), "l"(gptr))
#define CP_COMMIT() asm volatile("cp.async.commit_group;" ::: "memory")
#define CP_WAIT0()  asm volatile("cp.async.wait_group 0;" ::: "memory")

__device__ __forceinline__ void split2(float x, float y,
                                       __nv_bfloat162& hi, __nv_bfloat162& lo) {
    __nv_bfloat16 hx = __float2bfloat16_rn(x);
    __nv_bfloat16 hy = __float2bfloat16_rn(y);
    hi = __nv_bfloat162(hx, hy);
    lo = __nv_bfloat162(__float2bfloat16_rn(x - __bfloat162float(hx)),
                        __float2bfloat16_rn(y - __bfloat162float(hy)));
}
__device__ __forceinline__ uint32_t u32of(__nv_bfloat162 v) {
    return *reinterpret_cast<uint32_t*>(&v);
}

// ---------------------------------------------------------------------------
// bias precompute in MMA-fragment order for the 4Mx2N attn layout.
// float4 index t: lane(0..4) | nt(5..6) | mt(7) | w(8..10) | kt(11..14) |
//                 qt(15..17) | b(18..20)
// i0 = qt*128 + (w&3)*32 + mt*16 + (lane>>2)
// j0 = kt*64 + (w>>2)*32 + nt*8 + 2*(lane&3)
// float4 = { bias(i0,j0), bias(i0,j0+1), bias(i0+8,j0), bias(i0+8,j0+1) }
// ---------------------------------------------------------------------------
__device__ __forceinline__ float bias_val(float ei, float wi, float ej,
                                          float wj, float alpha, float beta) {
    float ed = fmaxf((ej - ei) * 1e-3f, 0.0f);
    float z = (wi + wj) * 0.5f - 5.0f;
    float wf = 1.0f / (1.0f + __expf(-z));
    float bia = -alpha * ed * (1.0f - beta * wf);
    return fminf(fmaxf(bia, -10.0f), 0.0f);
}

__global__ __launch_bounds__(256)
void bias_perm_kernel(const float* __restrict__ elev, const float* __restrict__ ws,
                      const float* __restrict__ alpha_p,
                      const float* __restrict__ beta_p,
                      float4* __restrict__ bias4) {
    const int t = blockIdx.x * blockDim.x + threadIdx.x;
    const int lane = t & 31;
    const int nt = (t >> 5) & 3;
    const int mt = (t >> 7) & 1;
    const int w  = (t >> 8) & 7;
    const int kt = (t >> 11) & 15;
    const int qt = (t >> 15) & 7;
    const int b  = t >> 18;
    const float alpha = *alpha_p;
    const float beta = *beta_p;

    const int i0 = qt * 128 + (w & 3) * 32 + mt * 16 + (lane >> 2);
    const int j0 = kt * 64 + (w >> 2) * 32 + nt * 8 + 2 * (lane & 3);
    const float* e = elev + b * 1024;
    const float* wsb = ws + b * 1024;
    float ei0 = e[i0], ei1 = e[i0 + 8];
    float wi0 = wsb[i0], wi1 = wsb[i0 + 8];
    float ej0 = e[j0], ej1 = e[j0 + 1];
    float wj0 = wsb[j0], wj1 = wsb[j0 + 1];

    float4 o;
    o.x = bias_val(ei0, wi0, ej0, wj0, alpha, beta);
    o.y = bias_val(ei0, wi0, ej1, wj1, alpha, beta);
    o.z = bias_val(ei1, wi1, ej0, wj0, alpha, beta);
    o.w = bias_val(ei1, wi1, ej1, wj1, alpha, beta);
    bias4[t] = o;
}

// ---------------------------------------------------------------------------
// merged converter (x | wqkv | wproj) + fused wind strength
// ---------------------------------------------------------------------------
#define N4_X (B_ * N_ * C_ / 4)
#define N4_WQKV (3 * C_ * C_ / 4)
#define N4_WPROJ (C_ * C_ / 4)
#define N4_TOTAL (N4_X + N4_WQKV + N4_WPROJ)

__global__ void convert_all(const float* __restrict__ x,
                            const float* __restrict__ wqkv,
                            const float* __restrict__ wproj,
                            const float* __restrict__ uwind,
                            const float* __restrict__ vwind,
                            __nv_bfloat16* __restrict__ xh, __nv_bfloat16* __restrict__ xl,
                            __nv_bfloat16* __restrict__ wqh, __nv_bfloat16* __restrict__ wql,
                            __nv_bfloat16* __restrict__ wph, __nv_bfloat16* __restrict__ wpl,
                            float* __restrict__ ws) {
    int i = blockIdx.x * blockDim.x + threadIdx.x;
    if (i >= N4_TOTAL) {
        int t = i - N4_TOTAL;
        if (t >= B_ * N_) return;
        int b = t >> 10;
        int n = t & 1023;
        int r = n >> 5;
        int c = n & 31;
        const float* ub = uwind + b * 4096;
        const float* vb = vwind + b * 4096;
        float s = 0.0f;
#pragma unroll
        for (int dr = 0; dr < 2; ++dr)
#pragma unroll
            for (int dc = 0; dc < 2; ++dc) {
                int idx = (2 * r + dr) * 64 + (2 * c + dc);
                float uu = ub[idx], vv = vb[idx];
                s += sqrtf(uu * uu + vv * vv + 1e-8f);
            }
        ws[t] = s * 0.25f;
        return;
    }
    const float* in;
    __nv_bfloat16 *hi, *lo;
    int off;
    if (i < N4_X) { in = x; hi = xh; lo = xl; off = i; }
    else if (i < N4_X + N4_WQKV) { in = wqkv; hi = wqh; lo = wql; off = i - N4_X; }
    else { in = wproj; hi = wph; lo = wpl; off = i - N4_X - N4_WQKV; }
    float4 v = reinterpret_cast<const float4*>(in)[off];
    __nv_bfloat162 h01, l01, h23, l23;
    split2(v.x, v.y, h01, l01);
    split2(v.z, v.w, h23, l23);
    uint2 hv = make_uint2(u32of(h01), u32of(h23));
    uint2 lv = make_uint2(u32of(l01), u32of(l23));
    *reinterpret_cast<uint2*>(hi + 4 * off) = hv;
    *reinterpret_cast<uint2*>(lo + 4 * off) = lv;
}

// ---------------------------------------------------------------------------
// 64x128-tile bf16-split GEMM, cp.async double-buffered.
// SPLIT_OUT: bf16 hi/lo output (QKV); else f32+bias (proj).
// 8 warps: wm = wid&1 (32-row half), wn = wid>>1 (32-col block).
// ---------------------------------------------------------------------------
#define PITCH 40
#define G64_BUF_BYTES (2 * 64 * PITCH * 2 + 2 * 128 * PITCH * 2)   // 30720
#define G64_SMEM_BYTES (2 * G64_BUF_BYTES)                          // 61440

template <bool SPLIT_OUT>
__global__ __launch_bounds__(256, 2)
void gemm64(const __nv_bfloat16* __restrict__ Ah, const __nv_bfloat16* __restrict__ Al,
            const __nv_bfloat16* __restrict__ Bh, const __nv_bfloat16* __restrict__ Bl,
            const float* __restrict__ bias, float* __restrict__ C,
            __nv_bfloat16* __restrict__ Ch, __nv_bfloat16* __restrict__ Cl, int N) {
    extern __shared__ __align__(16) char smem_raw[];
    const uint32_t uS = smem_u32(smem_raw);

    const int tid = threadIdx.x;
    const int lane = tid & 31;
    const int wid = tid >> 5;
    const int wm = wid & 1;
    const int wn = wid >> 1;
    const int bx = blockIdx.x;   // N tiles of 128
    const int by = blockIdx.y;   // M tiles of 64

    const __nv_bfloat16* Agh = Ah + (size_t)by * 64 * 256;
    const __nv_bfloat16* Agl = Al + (size_t)by * 64 * 256;
    const __nv_bfloat16* Bgh = Bh + (size_t)bx * 128 * 256;
    const __nv_bfloat16* Bgl = Bl + (size_t)bx * 128 * 256;

    float acc[2][4][4];
#pragma unroll
    for (int mt = 0; mt < 2; ++mt)
#pragma unroll
        for (int nt = 0; nt < 4; ++nt)
#pragma unroll
            for (int i = 0; i < 4; ++i) acc[mt][nt][i] = 0.0f;

    const uint32_t aoff =
        (uint32_t)((wm * 32 + (lane & 15)) * PITCH + ((lane & 16) ? 8 : 0)) * 2;
    const uint32_t boff =
        (uint32_t)((wn * 32 + (lane & 7) + ((lane & 16) ? 8 : 0)) * PITCH +
                   ((lane & 8) ? 8 : 0)) * 2;

    const int arow = tid >> 2;           // 0..63
    const int ac8 = (tid & 3) * 8;
    const uint32_t aso = (uint32_t)(arow * PITCH + ac8) * 2;
    const int brow0 = tid >> 2;

#pragma unroll 1
    for (int kb = -1; kb < 8; ++kb) {
        if (kb < 7) {
            const uint32_t nb = uS + (uint32_t)((kb + 1) & 1) * G64_BUF_BYTES;
            int kof = (kb + 1) * 32;
            {
                size_t g = (size_t)arow * 256 + kof + ac8;
                CP_ASYNC16(nb + aso, Agh + g);
                CP_ASYNC16(nb + 5120 + aso, Agl + g);
            }
#pragma unroll
            for (int i = 0; i < 2; ++i) {
                int row = brow0 + i * 64;
                size_t g = (size_t)row * 256 + kof + ac8;
                uint32_t so = (uint32_t)(row * PITCH + ac8) * 2;
                CP_ASYNC16(nb + 10240 + so, Bgh + g);
                CP_ASYNC16(nb + 20480 + so, Bgl + g);
            }
            CP_COMMIT();
        }
        if (kb < 0) { CP_WAIT0(); __syncthreads(); continue; }

        const uint32_t bufb = uS + (uint32_t)(kb & 1) * G64_BUF_BYTES;
        const uint32_t uAh = bufb, uAl = bufb + 5120;
        const uint32_t uBh = bufb + 10240, uBl = bufb + 20480;

#pragma unroll
        for (int kk = 0; kk < 2; ++kk) {
            const uint32_t kof = (uint32_t)(kk * 16) * 2;
            uint32_t bhf[2][4], blf[2][4];
#pragma unroll
            for (int ntp = 0; ntp < 2; ++ntp) {
                uint32_t ba = boff + (uint32_t)(ntp * 16 * PITCH) * 2 + kof;
                LDSM_X4(bhf[ntp][0], bhf[ntp][1], bhf[ntp][2], bhf[ntp][3], uBh + ba);
                LDSM_X4(blf[ntp][0], blf[ntp][1], blf[ntp][2], blf[ntp][3], uBl + ba);
            }
#pragma unroll
            for (int mt = 0; mt < 2; ++mt) {
                uint32_t aa = aoff + (uint32_t)(mt * 16 * PITCH) * 2 + kof;
                uint32_t ah0, ah1, ah2, ah3, al0, al1, al2, al3;
                LDSM_X4(ah0, ah1, ah2, ah3, uAh + aa);
                LDSM_X4(al0, al1, al2, al3, uAl + aa);
#pragma unroll
                for (int nt = 0; nt < 4; ++nt) {
                    const int ntp = nt >> 1;
                    const int hb = (nt & 1) * 2;
                    MMA_BF16(acc[mt][nt], ah0, ah1, ah2, ah3,
                             bhf[ntp][hb], bhf[ntp][hb + 1]);
                    MMA_BF16(acc[mt][nt], ah0, ah1, ah2, ah3,
                             blf[ntp][hb], blf[ntp][hb + 1]);
                    MMA_BF16(acc[mt][nt], al0, al1, al2, al3,
                             bhf[ntp][hb], bhf[ntp][hb + 1]);
                }
            }
        }

        if (kb < 7) CP_WAIT0();
        __syncthreads();
    }

    const int gid = lane >> 2;
    const int tig = lane & 3;
#pragma unroll
    for (int mt = 0; mt < 2; ++mt) {
        int row = by * 64 + wm * 32 + mt * 16 + gid;
#pragma unroll
        for (int nt = 0; nt < 4; ++nt) {
            int col = bx * 128 + wn * 32 + nt * 8 + 2 * tig;
            if (SPLIT_OUT) {
                __nv_bfloat162 hh, ll;
                split2(acc[mt][nt][0], acc[mt][nt][1], hh, ll);
                *reinterpret_cast<uint32_t*>(Ch + (size_t)row * N + col) = u32of(hh);
                *reinterpret_cast<uint32_t*>(Cl + (size_t)row * N + col) = u32of(ll);
                split2(acc[mt][nt][2], acc[mt][nt][3], hh, ll);
                *reinterpret_cast<uint32_t*>(Ch + (size_t)(row + 8) * N + col) = u32of(hh);
                *reinterpret_cast<uint32_t*>(Cl + (size_t)(row + 8) * N + col) = u32of(ll);
            } else {
                float2 bb = *reinterpret_cast<const float2*>(bias + col);
                float2 v0 = make_float2(acc[mt][nt][0] + bb.x, acc[mt][nt][1] + bb.y);
                float2 v1 = make_float2(acc[mt][nt][2] + bb.x, acc[mt][nt][3] + bb.y);
                *reinterpret_cast<float2*>(C + (size_t)row * N + col) = v0;
                *reinterpret_cast<float2*>(C + (size_t)(row + 8) * N + col) = v1;
            }
        }
    }
}

// ---------------------------------------------------------------------------
// tensor-core flash attention, 4M x 2N warp layout.
// warp w: wm=w&3 (rows wm*32..+31), wn=w>>2 (keys wn*32..+31 of each tile).
// Partial O and l merged across the wn pair at the end via smem (dead KV buf).
// No online max (bounded scores, shift-invariant softmax).
// ---------------------------------------------------------------------------
#define ATTN_Q_BYTES (2 * 128 * PITCH * 2)        // 20480
#define ATTN_BUF_BYTES (4 * 64 * PITCH * 2)       // 20480 per buffer
#define ATTN_SMEM_BYTES (ATTN_Q_BYTES + 2 * ATTN_BUF_BYTES)

__global__ __launch_bounds__(256, 2)
void attn_mma(const __nv_bfloat16* __restrict__ qkvh,
              const __nv_bfloat16* __restrict__ qkvl,
              const float4* __restrict__ bias4,
              __nv_bfloat16* __restrict__ outh,
              __nv_bfloat16* __restrict__ outl) {
    extern __shared__ __align__(16) char smem_raw[];
    __nv_bfloat16* Qh = reinterpret_cast<__nv_bfloat16*>(smem_raw);
    __nv_bfloat16* Ql = Qh + 128 * PITCH;
    const uint32_t uQh = smem_u32(Qh);
    const uint32_t uQl = uQh + 128 * PITCH * 2;
    const uint32_t uKV = uQl + 128 * PITCH * 2;

    const int tid = threadIdx.x;
    const int lane = tid & 31;
    const int w = tid >> 5;
    const int wm = w & 3;
    const int wn = w >> 2;
    const int gid = lane >> 2;
    const int tig = lane & 3;
    const int qc = blockIdx.x;
    const int h  = blockIdx.y;
    const int b  = blockIdx.z;

    const float scale = 0.17677669529663687f;   // 1/sqrt(32)
    const int qrow0 = b * N_ + qc * 128;

    const int krow = tid >> 2;
    const int kc8 = (tid & 3) * 8;
    const uint32_t kso = (uint32_t)(krow * PITCH + kc8) * 2;

    // prologue: stage kt=0 into buffer 0
    {
        size_t g = (size_t)(b * N_ + krow) * 768 + 256 + h * HD_ + kc8;
        CP_ASYNC16(uKV + kso, qkvh + g);
        CP_ASYNC16(uKV + 5120 + kso, qkvl + g);
        CP_ASYNC16(uKV + 10240 + kso, qkvh + g + 256);
        CP_ASYNC16(uKV + 15360 + kso, qkvl + g + 256);
        CP_COMMIT();
    }

    // stage Q
#pragma unroll
    for (int i = 0; i < 2; ++i) {
        int slot = tid + i * 256;
        int row = slot >> 2;
        int c8 = (slot & 3) * 8;
        size_t g = (size_t)(qrow0 + row) * 768 + h * HD_ + c8;
        int so = row * PITCH + c8;
        *reinterpret_cast<uint4*>(&Qh[so]) =
            *reinterpret_cast<const uint4*>(qkvh + g);
        *reinterpret_cast<uint4*>(&Ql[so]) =
            *reinterpret_cast<const uint4*>(qkvl + g);
    }
    CP_WAIT0();
    __syncthreads();

    // fragment addresses
    const uint32_t aoff =
        (uint32_t)((wm * 32 + (lane & 15)) * PITCH + ((lane & 16) ? 8 : 0)) * 2;
    const uint32_t koff =
        (uint32_t)((wn * 32 + (lane & 7) + ((lane & 16) ? 8 : 0)) * PITCH +
                   ((lane & 8) ? 8 : 0)) * 2;
    const uint32_t voffb =
        (uint32_t)((wn * 32 + (lane & 15)) * PITCH + ((lane & 16) ? 8 : 0)) * 2;

    float lac[2][2];
    lac[0][0] = lac[0][1] = lac[1][0] = lac[1][1] = 0.0f;
    float oacc[2][4][4];
#pragma unroll
    for (int mt = 0; mt < 2; ++mt)
#pragma unroll
        for (int nt = 0; nt < 4; ++nt)
#pragma unroll
            for (int i = 0; i < 4; ++i) oacc[mt][nt][i] = 0.0f;

    const float4* bias_tb =
        bias4 + ((size_t)((b * 8 + qc) * 16)) * 2048 + w * 256 + lane;

#pragma unroll 1
    for (int kt = 0; kt < 16; ++kt) {
        const int p = kt & 1;
        const uint32_t bufb = uKV + (uint32_t)p * ATTN_BUF_BYTES;

        if (kt < 15) {
            const uint32_t nb = uKV + (uint32_t)(1 - p) * ATTN_BUF_BYTES;
            size_t g = (size_t)(b * N_ + (kt + 1) * 64 + krow) * 768 + 256 +
                       h * HD_ + kc8;
            CP_ASYNC16(nb + kso, qkvh + g);
            CP_ASYNC16(nb + 5120 + kso, qkvl + g);
            CP_ASYNC16(nb + 10240 + kso, qkvh + g + 256);
            CP_ASYNC16(nb + 15360 + kso, qkvl + g + 256);
            CP_COMMIT();
        }

        const uint32_t uKh = bufb, uKl = bufb + 5120;
        const uint32_t uVh = bufb + 10240, uVl = bufb + 15360;

        // ---- S = Q K^T (3-term split) : 2mt x 4nt over warp's 32 keys ----
        float sacc[2][4][4];
#pragma unroll
        for (int mt = 0; mt < 2; ++mt)
#pragma unroll
            for (int nt = 0; nt < 4; ++nt)
#pragma unroll
                for (int i = 0; i < 4; ++i) sacc[mt][nt][i] = 0.0f;

#pragma unroll
        for (int kk = 0; kk < 2; ++kk) {
            const uint32_t kof = (uint32_t)(kk * 16) * 2;
            uint32_t qhf[2][4], qlf[2][4];
#pragma unroll
            for (int mt = 0; mt < 2; ++mt) {
                uint32_t aa = aoff + (uint32_t)(mt * 16 * PITCH) * 2 + kof;
                LDSM_X4(qhf[mt][0], qhf[mt][1], qhf[mt][2], qhf[mt][3], uQh + aa);
                LDSM_X4(qlf[mt][0], qlf[mt][1], qlf[mt][2], qlf[mt][3], uQl + aa);
            }
            uint32_t bh[2][4], bl[2][4];
#pragma unroll
            for (int ntp = 0; ntp < 2; ++ntp) {
                uint32_t ba = koff + (uint32_t)(ntp * 16 * PITCH) * 2 + kof;
                LDSM_X4(bh[ntp][0], bh[ntp][1], bh[ntp][2], bh[ntp][3], uKh + ba);
                LDSM_X4(bl[ntp][0], bl[ntp][1], bl[ntp][2], bl[ntp][3], uKl + ba);
            }
#pragma unroll
            for (int mt = 0; mt < 2; ++mt)
#pragma unroll
                for (int nt = 0; nt < 4; ++nt) {
                    const int ntp = nt >> 1;
                    const int hb = (nt & 1) * 2;
                    MMA_BF16(sacc[mt][nt], qhf[mt][0], qhf[mt][1], qhf[mt][2],
                             qhf[mt][3], bh[ntp][hb], bh[ntp][hb + 1]);
                    MMA_BF16(sacc[mt][nt], qhf[mt][0], qhf[mt][1], qhf[mt][2],
                             qhf[mt][3], bl[ntp][hb], bl[ntp][hb + 1]);
                    MMA_BF16(sacc[mt][nt], qlf[mt][0], qlf[mt][1], qlf[mt][2],
                             qlf[mt][3], bh[ntp][hb], bh[ntp][hb + 1]);
                }
        }

        // ---- scale + bias + exp (no max shift; bounded inputs) ----
        const float4* bt = bias_tb + kt * 2048;
#pragma unroll
        for (int mt = 0; mt < 2; ++mt)
#pragma unroll
            for (int nt = 0; nt < 4; ++nt) {
                float4 bb = bt[(mt * 4 + nt) * 32];
                float p0 = __expf(fmaf(sacc[mt][nt][0], scale, bb.x));
                float p1 = __expf(fmaf(sacc[mt][nt][1], scale, bb.y));
                float p2 = __expf(fmaf(sacc[mt][nt][2], scale, bb.z));
                float p3 = __expf(fmaf(sacc[mt][nt][3], scale, bb.w));
                sacc[mt][nt][0] = p0; sacc[mt][nt][1] = p1;
                sacc[mt][nt][2] = p2; sacc[mt][nt][3] = p3;
                lac[mt][0] += p0 + p1;
                lac[mt][1] += p2 + p3;
            }

        // ---- O += P V (warp's 32 keys, 2 chunks of 16) ----
#pragma unroll
        for (int ks = 0; ks < 2; ++ks) {
            uint32_t vh[2][4], vl[2][4];
#pragma unroll
            for (int ntp = 0; ntp < 2; ++ntp) {
                uint32_t va = voffb + (uint32_t)(ks * 16 * PITCH + ntp * 16) * 2;
                LDSM_X4T(vh[ntp][0], vh[ntp][1], vh[ntp][2], vh[ntp][3], uVh + va);
                LDSM_X4T(vl[ntp][0], vl[ntp][1], vl[ntp][2], vl[ntp][3], uVl + va);
            }
#pragma unroll
            for (int mt = 0; mt < 2; ++mt) {
                __nv_bfloat162 hh, ll;
                uint32_t pah[4], pal[4];
                split2(sacc[mt][2 * ks][0],     sacc[mt][2 * ks][1],     hh, ll);
                pah[0] = u32of(hh); pal[0] = u32of(ll);
                split2(sacc[mt][2 * ks][2],     sacc[mt][2 * ks][3],     hh, ll);
                pah[1] = u32of(hh); pal[1] = u32of(ll);
                split2(sacc[mt][2 * ks + 1][0], sacc[mt][2 * ks + 1][1], hh, ll);
                pah[2] = u32of(hh); pal[2] = u32of(ll);
                split2(sacc[mt][2 * ks + 1][2], sacc[mt][2 * ks + 1][3], hh, ll);
                pah[3] = u32of(hh); pal[3] = u32of(ll);
#pragma unroll
                for (int nt = 0; nt < 4; ++nt) {
                    const int ntp = nt >> 1;
                    const int hb = (nt & 1) * 2;
                    MMA_BF16(oacc[mt][nt], pah[0], pah[1], pah[2], pah[3],
                             vh[ntp][hb], vh[ntp][hb + 1]);
                    MMA_BF16(oacc[mt][nt], pah[0], pah[1], pah[2], pah[3],
                             vl[ntp][hb], vl[ntp][hb + 1]);
                    MMA_BF16(oacc[mt][nt], pal[0], pal[1], pal[2], pal[3],
                             vh[ntp][hb], vh[ntp][hb + 1]);
                }
            }
        }

        if (kt < 15) CP_WAIT0();
        __syncthreads();
    }

    // ---- merge partials across the wn pair (reuse dead KV smem) ----
    float* mg = reinterpret_cast<float*>(smem_raw + ATTN_Q_BYTES);
    if (wn == 1) {
        float* d = mg + (wm * 32 + lane) * 36;
#pragma unroll
        for (int mt = 0; mt < 2; ++mt)
#pragma unroll
            for (int nt = 0; nt < 4; ++nt)
#pragma unroll
                for (int i = 0; i < 4; ++i)
                    d[(mt * 4 + nt) * 4 + i] = oacc[mt][nt][i];
        d[32] = lac[0][0]; d[33] = lac[0][1];
        d[34] = lac[1][0]; d[35] = lac[1][1];
    }
    __syncthreads();
    if (wn == 0) {
        const float* s = mg + (wm * 32 + lane) * 36;
#pragma unroll
        for (int mt = 0; mt < 2; ++mt)
#pragma unroll
            for (int nt = 0; nt < 4; ++nt)
#pragma unroll
                for (int i = 0; i < 4; ++i)
                    oacc[mt][nt][i] += s[(mt * 4 + nt) * 4 + i];
        lac[0][0] += s[32]; lac[0][1] += s[33];
        lac[1][0] += s[34]; lac[1][1] += s[35];

        // reduce l over the 4-lane row group
#pragma unroll
        for (int mt = 0; mt < 2; ++mt)
#pragma unroll
            for (int hh = 0; hh < 2; ++hh) {
                lac[mt][hh] += __shfl_xor_sync(0xffffffffu, lac[mt][hh], 1);
                lac[mt][hh] += __shfl_xor_sync(0xffffffffu, lac[mt][hh], 2);
            }

        // epilogue
#pragma unroll
        for (int mt = 0; mt < 2; ++mt) {
            const float inv0 = 1.0f / lac[mt][0];
            const float inv1 = 1.0f / lac[mt][1];
            const int row0 = qrow0 + wm * 32 + mt * 16 + gid;
#pragma unroll
            for (int nt = 0; nt < 4; ++nt) {
                int col = h * HD_ + nt * 8 + 2 * tig;
                __nv_bfloat162 hv, lv;
                split2(oacc[mt][nt][0] * inv0, oacc[mt][nt][1] * inv0, hv, lv);
                *reinterpret_cast<uint32_t*>(outh + (size_t)row0 * C_ + col) = u32of(hv);
                *reinterpret_cast<uint32_t*>(outl + (size_t)row0 * C_ + col) = u32of(lv);
                split2(oacc[mt][nt][2] * inv1, oacc[mt][nt][3] * inv1, hv, lv);
                *reinterpret_cast<uint32_t*>(outh + (size_t)(row0 + 8) * C_ + col) = u32of(hv);
                *reinterpret_cast<uint32_t*>(outl + (size_t)(row0 + 8) * C_ + col) = u32of(lv);
            }
        }
    }
}

// ---------------------------------------------------------------------------
// launch
// ---------------------------------------------------------------------------
extern "C" void kernel_launch(void* const* d_in, const int* in_sizes, int n_in,
                              void* d_out, int out_size) {
    const float* x     = (const float*)d_in[0];
    const float* elev  = (const float*)d_in[1];
    const float* uw    = (const float*)d_in[2];
    const float* vw    = (const float*)d_in[3];
    const float* wqkv  = (const float*)d_in[4];
    const float* wproj = (const float*)d_in[5];
    const float* bproj = (const float*)d_in[6];
    const float* alpha = (const float*)d_in[7];
    const float* beta  = (const float*)d_in[8];
    float* out = (float*)d_out;

    float *ws_p;
    float4* bias4_p;
    __nv_bfloat16 *xh, *xl, *wqkvh, *wqkvl, *wprojh, *wprojl;
    __nv_bfloat16 *qkvh, *qkvl, *attnh, *attnl;
    cudaGetSymbolAddress((void**)&ws_p, g_ws);
    cudaGetSymbolAddress((void**)&bias4_p, g_bias4);
    cudaGetSymbolAddress((void**)&xh, g_xh);
    cudaGetSymbolAddress((void**)&xl, g_xl);
    cudaGetSymbolAddress((void**)&wqkvh, g_wqkvh);
    cudaGetSymbolAddress((void**)&wqkvl, g_wqkvl);
    cudaGetSymbolAddress((void**)&wprojh, g_wprojh);
    cudaGetSymbolAddress((void**)&wprojl, g_wprojl);
    cudaGetSymbolAddress((void**)&qkvh, g_qkvh);
    cudaGetSymbolAddress((void**)&qkvl, g_qkvl);
    cudaGetSymbolAddress((void**)&attnh, g_attnh);
    cudaGetSymbolAddress((void**)&attnl, g_attnl);

    cudaFuncSetAttribute(gemm64<true>,
                         cudaFuncAttributeMaxDynamicSharedMemorySize,
                         G64_SMEM_BYTES);
    cudaFuncSetAttribute(gemm64<false>,
                         cudaFuncAttributeMaxDynamicSharedMemorySize,
                         G64_SMEM_BYTES);
    cudaFuncSetAttribute(attn_mma,
                         cudaFuncAttributeMaxDynamicSharedMemorySize,
                         ATTN_SMEM_BYTES);

    // 1) merged converts + wind strength (fused)
    convert_all<<<(N4_TOTAL + B_ * N_ + 255) / 256, 256>>>(
        x, wqkv, wproj, uw, vw, xh, xl, wqkvh, wqkvl, wprojh, wprojl, ws_p);

    // 2) fragment-ordered bias (4Mx2N layout)
    bias_perm_kernel<<<B_ * N_ * N_ / 4 / 256, 256>>>(elev, ws_p, alpha, beta,
                                                      bias4_p);

    // 3) qkv = x @ w_qkv^T (64x128 tiles, split output)
    gemm64<true><<<dim3(6, 128), 256, G64_SMEM_BYTES>>>(
        xh, xl, wqkvh, wqkvl, nullptr, nullptr, qkvh, qkvl, 768);

    // 4) flash attention (4Mx2N warps, split output)
    attn_mma<<<dim3(8, NH_, B_), 256, ATTN_SMEM_BYTES>>>(
        qkvh, qkvl, bias4_p, attnh, attnl);

    // 5) out = attn @ w_proj^T + b_proj (64x128 tiles, f32 output)
    gemm64<false><<<dim3(2, 128), 256, G64_SMEM_BYTES>>>(
        attnh, attnl, wprojh, wprojl, bproj, out, nullptr, nullptr, 256);
}

// round 12
// speedup vs baseline: 1.0401x; 1.0401x over previous
#include <cuda_runtime.h>
#include <cuda_bf16.h>
#include <math.h>
#include <cstdint>

// ---------------------------------------------------------------------------
// PhysicsGuidedAttentionCorrected
// B=8, N=1024, C=256, NUM_HEADS=8, hd=32
// R12: exact R10 structure (proven 163.9us) + packed bf16 hi/lo split
//      (cvt.rn.bf16x2.f32 + bit-trick hi reconstruction; bit-identical,
//      ~40% fewer split instructions) in attn P-split and all epilogues.
// ---------------------------------------------------------------------------

#define B_ 8
#define N_ 1024
#define C_ 256
#define NH_ 8
#define HD_ 32

// scratch (device globals; no allocations allowed)
__device__ float g_ws[B_ * N_];
__device__ float4 g_bias4[B_ * N_ * N_ / 4];       // fragment-ordered bias
__device__ __nv_bfloat16 g_xh[B_ * N_ * C_];
__device__ __nv_bfloat16 g_xl[B_ * N_ * C_];
__device__ __nv_bfloat16 g_wqkvh[3 * C_ * C_];
__device__ __nv_bfloat16 g_wqkvl[3 * C_ * C_];
__device__ __nv_bfloat16 g_wprojh[C_ * C_];
__device__ __nv_bfloat16 g_wprojl[C_ * C_];
__device__ __nv_bfloat16 g_qkvh[B_ * N_ * 3 * C_];
__device__ __nv_bfloat16 g_qkvl[B_ * N_ * 3 * C_];
__device__ __nv_bfloat16 g_attnh[B_ * N_ * C_];
__device__ __nv_bfloat16 g_attnl[B_ * N_ * C_];

// ---------------------------------------------------------------------------
// helpers
// ---------------------------------------------------------------------------
__device__ __forceinline__ uint32_t smem_u32(const void* p) {
    uint32_t a;
    asm("{ .reg .u64 t; cvta.to.shared.u64 t, %1; cvt.u32.u64 %0, t; }"
        : "=r"(a) : "l"(p));
    return a;
}

#define LDSM_X4(r0, r1, r2, r3, addr)                                        \
    asm volatile("ldmatrix.sync.aligned.m8n8.x4.shared.b16 {%0,%1,%2,%3}, [%4];" \
                 : "=r"(r0), "=r"(r1), "=r"(r2), "=r"(r3) : "r"(addr))

#define LDSM_X4T(r0, r1, r2, r3, addr)                                       \
    asm volatile("ldmatrix.sync.aligned.m8n8.x4.trans.shared.b16 {%0,%1,%2,%3}, [%4];" \
                 : "=r"(r0), "=r"(r1), "=r"(r2), "=r"(r3) : "r"(addr))

#define MMA_BF16(d, a0, a1, a2, a3, b0, b1)                                  \
    asm volatile("mma.sync.aligned.m16n8k16.row.col.f32.bf16.bf16.f32 "      \
                 "{%0,%1,%2,%3}, {%4,%5,%6,%7}, {%8,%9}, {%0,%1,%2,%3};"     \
                 : "+f"((d)[0]), "+f"((d)[1]), "+f"((d)[2]), "+f"((d)[3])    \
                 : "r"(a0), "r"(a1), "r"(a2), "r"(a3), "r"(b0), "r"(b1))

#define CP_ASYNC16(saddr, gptr)                                              \
    asm volatile("cp.async.cg.shared.global [%0], [%1], 16;"                 \
                 :: "r"(saddr), "l"(gptr))
#define CP_COMMIT() asm volatile("cp.async.commit_group;" ::: "memory")
#define CP_WAIT0()  asm volatile("cp.async.wait_group 0;" ::: "memory")

// legacy split (cold paths)
__device__ __forceinline__ void split2(float x, float y,
                                       __nv_bfloat162& hi, __nv_bfloat162& lo) {
    __nv_bfloat16 hx = __float2bfloat16_rn(x);
    __nv_bfloat16 hy = __float2bfloat16_rn(y);
    hi = __nv_bfloat162(hx, hy);
    lo = __nv_bfloat162(__float2bfloat16_rn(x - __bfloat162float(hx)),
                        __float2bfloat16_rn(y - __bfloat162float(hy)));
}
__device__ __forceinline__ uint32_t u32of(__nv_bfloat162 v) {
    return *reinterpret_cast<uint32_t*>(&v);
}

// packed split: bit-identical to split2, ~40% fewer instructions.
// hi = bf16x2{rn(x) lo-half, rn(y) hi-half}; hi-as-f32 rebuilt by bit ops.
__device__ __forceinline__ void split2p(float x, float y,
                                        uint32_t& hi, uint32_t& lo) {
    uint32_t h;
    asm("cvt.rn.bf16x2.f32 %0, %1, %2;" : "=r"(h) : "f"(y), "f"(x));
    float fx = __uint_as_float(h << 16);
    float fy = __uint_as_float(h & 0xFFFF0000u);
    uint32_t l;
    asm("cvt.rn.bf16x2.f32 %0, %1, %2;" : "=r"(l) : "f"(y - fy), "f"(x - fx));
    hi = h; lo = l;
}

// ---------------------------------------------------------------------------
// bias precompute in MMA-fragment order (R8/R10 layout).
// ---------------------------------------------------------------------------
__device__ __forceinline__ float bias_val(float ei, float wi, float ej,
                                          float wj, float alpha, float beta) {
    float ed = fmaxf((ej - ei) * 1e-3f, 0.0f);
    float z = (wi + wj) * 0.5f - 5.0f;
    float wf = 1.0f / (1.0f + __expf(-z));
    float bia = -alpha * ed * (1.0f - beta * wf);
    return fminf(fmaxf(bia, -10.0f), 0.0f);
}

__global__ __launch_bounds__(256)
void bias_perm_kernel(const float* __restrict__ elev, const float* __restrict__ ws,
                      const float* __restrict__ alpha_p,
                      const float* __restrict__ beta_p,
                      float4* __restrict__ bias4) {
    const int t = blockIdx.x * blockDim.x + threadIdx.x;
    const int lane = t & 31;
    const int nt = (t >> 5) & 7;
    const int w  = (t >> 8) & 7;
    const int kt = (t >> 11) & 15;
    const int qt = (t >> 15) & 7;
    const int b  = t >> 18;
    const float alpha = *alpha_p;
    const float beta = *beta_p;

    const int i0 = qt * 128 + w * 16 + (lane >> 2);
    const int j0 = kt * 64 + nt * 8 + 2 * (lane & 3);
    const float* e = elev + b * 1024;
    const float* wsb = ws + b * 1024;
    float ei0 = e[i0], ei1 = e[i0 + 8];
    float wi0 = wsb[i0], wi1 = wsb[i0 + 8];
    float ej0 = e[j0], ej1 = e[j0 + 1];
    float wj0 = wsb[j0], wj1 = wsb[j0 + 1];

    float4 o;
    o.x = bias_val(ei0, wi0, ej0, wj0, alpha, beta);
    o.y = bias_val(ei0, wi0, ej1, wj1, alpha, beta);
    o.z = bias_val(ei1, wi1, ej0, wj0, alpha, beta);
    o.w = bias_val(ei1, wi1, ej1, wj1, alpha, beta);
    bias4[t] = o;
}

// ---------------------------------------------------------------------------
// merged converter (x | wqkv | wproj) + fused wind strength
// ---------------------------------------------------------------------------
#define N4_X (B_ * N_ * C_ / 4)
#define N4_WQKV (3 * C_ * C_ / 4)
#define N4_WPROJ (C_ * C_ / 4)
#define N4_TOTAL (N4_X + N4_WQKV + N4_WPROJ)

__global__ void convert_all(const float* __restrict__ x,
                            const float* __restrict__ wqkv,
                            const float* __restrict__ wproj,
                            const float* __restrict__ uwind,
                            const float* __restrict__ vwind,
                            __nv_bfloat16* __restrict__ xh, __nv_bfloat16* __restrict__ xl,
                            __nv_bfloat16* __restrict__ wqh, __nv_bfloat16* __restrict__ wql,
                            __nv_bfloat16* __restrict__ wph, __nv_bfloat16* __restrict__ wpl,
                            float* __restrict__ ws) {
    int i = blockIdx.x * blockDim.x + threadIdx.x;
    if (i >= N4_TOTAL) {
        int t = i - N4_TOTAL;
        if (t >= B_ * N_) return;
        int b = t >> 10;
        int n = t & 1023;
        int r = n >> 5;
        int c = n & 31;
        const float* ub = uwind + b * 4096;
        const float* vb = vwind + b * 4096;
        float s = 0.0f;
#pragma unroll
        for (int dr = 0; dr < 2; ++dr)
#pragma unroll
            for (int dc = 0; dc < 2; ++dc) {
                int idx = (2 * r + dr) * 64 + (2 * c + dc);
                float uu = ub[idx], vv = vb[idx];
                s += sqrtf(uu * uu + vv * vv + 1e-8f);
            }
        ws[t] = s * 0.25f;
        return;
    }
    const float* in;
    __nv_bfloat16 *hi, *lo;
    int off;
    if (i < N4_X) { in = x; hi = xh; lo = xl; off = i; }
    else if (i < N4_X + N4_WQKV) { in = wqkv; hi = wqh; lo = wql; off = i - N4_X; }
    else { in = wproj; hi = wph; lo = wpl; off = i - N4_X - N4_WQKV; }
    float4 v = reinterpret_cast<const float4*>(in)[off];
    uint32_t h01, l01, h23, l23;
    split2p(v.x, v.y, h01, l01);
    split2p(v.z, v.w, h23, l23);
    *reinterpret_cast<uint2*>(hi + 4 * off) = make_uint2(h01, h23);
    *reinterpret_cast<uint2*>(lo + 4 * off) = make_uint2(l01, l23);
}

// ---------------------------------------------------------------------------
// bf16-split tensor-core GEMM 128x128, cp.async double-buffered (proven).
// Used for QKV (split output).
// ---------------------------------------------------------------------------
#define PITCH 40
#define GEMM_BUF_BYTES (4 * 128 * PITCH * 2)
#define GEMM_SMEM_BYTES (2 * GEMM_BUF_BYTES)

__global__ __launch_bounds__(256, 2)
void gemm_qkv(const __nv_bfloat16* __restrict__ Ah, const __nv_bfloat16* __restrict__ Al,
              const __nv_bfloat16* __restrict__ Bh, const __nv_bfloat16* __restrict__ Bl,
              __nv_bfloat16* __restrict__ Ch, __nv_bfloat16* __restrict__ Cl) {
    const int N = 768;
    extern __shared__ __align__(16) char smem_raw[];
    const uint32_t uS = smem_u32(smem_raw);

    const int tid = threadIdx.x;
    const int lane = tid & 31;
    const int wid = tid >> 5;
    const int wm = wid & 1;
    const int wn = wid >> 1;
    const int bx = blockIdx.x;
    const int by = blockIdx.y;

    const __nv_bfloat16* Agh = Ah + (size_t)by * 128 * 256;
    const __nv_bfloat16* Agl = Al + (size_t)by * 128 * 256;
    const __nv_bfloat16* Bgh = Bh + (size_t)bx * 128 * 256;
    const __nv_bfloat16* Bgl = Bl + (size_t)bx * 128 * 256;

    float acc[4][4][4];
#pragma unroll
    for (int mt = 0; mt < 4; ++mt)
#pragma unroll
        for (int nt = 0; nt < 4; ++nt)
#pragma unroll
            for (int i = 0; i < 4; ++i) acc[mt][nt][i] = 0.0f;

    const uint32_t aoff =
        (uint32_t)((wm * 64 + (lane & 15)) * PITCH + ((lane & 16) ? 8 : 0)) * 2;
    const uint32_t boff =
        (uint32_t)((wn * 32 + (lane & 7) + ((lane & 16) ? 8 : 0)) * PITCH +
                   ((lane & 8) ? 8 : 0)) * 2;

    const int row0 = tid >> 2;
    const int c8 = (tid & 3) * 8;

#pragma unroll
    for (int i = 0; i < 2; ++i) {
        int row = row0 + i * 64;
        size_t g = (size_t)row * 256 + c8;
        uint32_t so = (uint32_t)(row * PITCH + c8) * 2;
        CP_ASYNC16(uS + so, Agh + g);
        CP_ASYNC16(uS + 10240 + so, Agl + g);
        CP_ASYNC16(uS + 20480 + so, Bgh + g);
        CP_ASYNC16(uS + 30720 + so, Bgl + g);
    }
    CP_COMMIT();
    CP_WAIT0();
    __syncthreads();

#pragma unroll 1
    for (int kb = 0; kb < 8; ++kb) {
        const int p = kb & 1;
        const uint32_t bufb = uS + (uint32_t)p * GEMM_BUF_BYTES;

        if (kb < 7) {
            const uint32_t nb = uS + (uint32_t)(1 - p) * GEMM_BUF_BYTES;
#pragma unroll
            for (int i = 0; i < 2; ++i) {
                int row = row0 + i * 64;
                size_t g = (size_t)row * 256 + (kb + 1) * 32 + c8;
                uint32_t so = (uint32_t)(row * PITCH + c8) * 2;
                CP_ASYNC16(nb + so, Agh + g);
                CP_ASYNC16(nb + 10240 + so, Agl + g);
                CP_ASYNC16(nb + 20480 + so, Bgh + g);
                CP_ASYNC16(nb + 30720 + so, Bgl + g);
            }
            CP_COMMIT();
        }

        const uint32_t uAh = bufb, uAl = bufb + 10240;
        const uint32_t uBh = bufb + 20480, uBl = bufb + 30720;

#pragma unroll
        for (int kk = 0; kk < 2; ++kk) {
            const uint32_t kof = (uint32_t)(kk * 16) * 2;
            uint32_t bhf[2][4], blf[2][4];
#pragma unroll
            for (int ntp = 0; ntp < 2; ++ntp) {
                uint32_t ba = boff + (uint32_t)(ntp * 16 * PITCH) * 2 + kof;
                LDSM_X4(bhf[ntp][0], bhf[ntp][1], bhf[ntp][2], bhf[ntp][3], uBh + ba);
                LDSM_X4(blf[ntp][0], blf[ntp][1], blf[ntp][2], blf[ntp][3], uBl + ba);
            }
#pragma unroll
            for (int mt = 0; mt < 4; ++mt) {
                uint32_t aa = aoff + (uint32_t)(mt * 16 * PITCH) * 2 + kof;
                uint32_t ah0, ah1, ah2, ah3, al0, al1, al2, al3;
                LDSM_X4(ah0, ah1, ah2, ah3, uAh + aa);
                LDSM_X4(al0, al1, al2, al3, uAl + aa);
#pragma unroll
                for (int nt = 0; nt < 4; ++nt) {
                    const int ntp = nt >> 1;
                    const int hb = (nt & 1) * 2;
                    MMA_BF16(acc[mt][nt], ah0, ah1, ah2, ah3,
                             bhf[ntp][hb], bhf[ntp][hb + 1]);
                    MMA_BF16(acc[mt][nt], ah0, ah1, ah2, ah3,
                             blf[ntp][hb], blf[ntp][hb + 1]);
                    MMA_BF16(acc[mt][nt], al0, al1, al2, al3,
                             bhf[ntp][hb], bhf[ntp][hb + 1]);
                }
            }
        }

        if (kb < 7) CP_WAIT0();
        __syncthreads();
    }

    const int gid = lane >> 2;
    const int tig = lane & 3;
#pragma unroll
    for (int mt = 0; mt < 4; ++mt) {
        int row = by * 128 + wm * 64 + mt * 16 + gid;
#pragma unroll
        for (int nt = 0; nt < 4; ++nt) {
            int col = bx * 128 + wn * 32 + nt * 8 + 2 * tig;
            uint32_t hh, ll;
            split2p(acc[mt][nt][0], acc[mt][nt][1], hh, ll);
            *reinterpret_cast<uint32_t*>(Ch + (size_t)row * N + col) = hh;
            *reinterpret_cast<uint32_t*>(Cl + (size_t)row * N + col) = ll;
            split2p(acc[mt][nt][2], acc[mt][nt][3], hh, ll);
            *reinterpret_cast<uint32_t*>(Ch + (size_t)(row + 8) * N + col) = hh;
            *reinterpret_cast<uint32_t*>(Cl + (size_t)(row + 8) * N + col) = ll;
        }
    }
}

// ---------------------------------------------------------------------------
// proj GEMM: 64x128 tiles (256 CTAs -> full wave), f32 + bias output.
// ---------------------------------------------------------------------------
#define P64_BUF_BYTES (2 * 64 * PITCH * 2 + 2 * 128 * PITCH * 2)   // 30720
#define P64_SMEM_BYTES (2 * P64_BUF_BYTES)                          // 61440

__global__ __launch_bounds__(256, 2)
void gemm_proj(const __nv_bfloat16* __restrict__ Ah, const __nv_bfloat16* __restrict__ Al,
               const __nv_bfloat16* __restrict__ Bh, const __nv_bfloat16* __restrict__ Bl,
               const float* __restrict__ bias, float* __restrict__ C) {
    const int N = 256;
    extern __shared__ __align__(16) char smem_raw[];
    const uint32_t uS = smem_u32(smem_raw);

    const int tid = threadIdx.x;
    const int lane = tid & 31;
    const int wid = tid >> 5;
    const int wm = wid & 1;
    const int wn = wid >> 1;
    const int bx = blockIdx.x;
    const int by = blockIdx.y;

    const __nv_bfloat16* Agh = Ah + (size_t)by * 64 * 256;
    const __nv_bfloat16* Agl = Al + (size_t)by * 64 * 256;
    const __nv_bfloat16* Bgh = Bh + (size_t)bx * 128 * 256;
    const __nv_bfloat16* Bgl = Bl + (size_t)bx * 128 * 256;

    float acc[2][4][4];
#pragma unroll
    for (int mt = 0; mt < 2; ++mt)
#pragma unroll
        for (int nt = 0; nt < 4; ++nt)
#pragma unroll
            for (int i = 0; i < 4; ++i) acc[mt][nt][i] = 0.0f;

    const uint32_t aoff =
        (uint32_t)((wm * 32 + (lane & 15)) * PITCH + ((lane & 16) ? 8 : 0)) * 2;
    const uint32_t boff =
        (uint32_t)((wn * 32 + (lane & 7) + ((lane & 16) ? 8 : 0)) * PITCH +
                   ((lane & 8) ? 8 : 0)) * 2;

    const int arow = tid >> 2;
    const int ac8 = (tid & 3) * 8;
    const uint32_t aso = (uint32_t)(arow * PITCH + ac8) * 2;
    const int brow0 = tid >> 2;

#pragma unroll 1
    for (int kb = -1; kb < 8; ++kb) {
        if (kb < 7) {
            const uint32_t nb = uS + (uint32_t)((kb + 1) & 1) * P64_BUF_BYTES;
            int kof = (kb + 1) * 32;
            {
                size_t g = (size_t)arow * 256 + kof + ac8;
                CP_ASYNC16(nb + aso, Agh + g);
                CP_ASYNC16(nb + 5120 + aso, Agl + g);
            }
#pragma unroll
            for (int i = 0; i < 2; ++i) {
                int row = brow0 + i * 64;
                size_t g = (size_t)row * 256 + kof + ac8;
                uint32_t so = (uint32_t)(row * PITCH + ac8) * 2;
                CP_ASYNC16(nb + 10240 + so, Bgh + g);
                CP_ASYNC16(nb + 20480 + so, Bgl + g);
            }
            CP_COMMIT();
        }
        if (kb < 0) { CP_WAIT0(); __syncthreads(); continue; }

        const uint32_t bufb = uS + (uint32_t)(kb & 1) * P64_BUF_BYTES;
        const uint32_t uAh = bufb, uAl = bufb + 5120;
        const uint32_t uBh = bufb + 10240, uBl = bufb + 20480;

#pragma unroll
        for (int kk = 0; kk < 2; ++kk) {
            const uint32_t kof = (uint32_t)(kk * 16) * 2;
            uint32_t bhf[2][4], blf[2][4];
#pragma unroll
            for (int ntp = 0; ntp < 2; ++ntp) {
                uint32_t ba = boff + (uint32_t)(ntp * 16 * PITCH) * 2 + kof;
                LDSM_X4(bhf[ntp][0], bhf[ntp][1], bhf[ntp][2], bhf[ntp][3], uBh + ba);
                LDSM_X4(blf[ntp][0], blf[ntp][1], blf[ntp][2], blf[ntp][3], uBl + ba);
            }
#pragma unroll
            for (int mt = 0; mt < 2; ++mt) {
                uint32_t aa = aoff + (uint32_t)(mt * 16 * PITCH) * 2 + kof;
                uint32_t ah0, ah1, ah2, ah3, al0, al1, al2, al3;
                LDSM_X4(ah0, ah1, ah2, ah3, uAh + aa);
                LDSM_X4(al0, al1, al2, al3, uAl + aa);
#pragma unroll
                for (int nt = 0; nt < 4; ++nt) {
                    const int ntp = nt >> 1;
                    const int hb = (nt & 1) * 2;
                    MMA_BF16(acc[mt][nt], ah0, ah1, ah2, ah3,
                             bhf[ntp][hb], bhf[ntp][hb + 1]);
                    MMA_BF16(acc[mt][nt], ah0, ah1, ah2, ah3,
                             blf[ntp][hb], blf[ntp][hb + 1]);
                    MMA_BF16(acc[mt][nt], al0, al1, al2, al3,
                             bhf[ntp][hb], bhf[ntp][hb + 1]);
                }
            }
        }

        if (kb < 7) CP_WAIT0();
        __syncthreads();
    }

    const int gid = lane >> 2;
    const int tig = lane & 3;
#pragma unroll
    for (int mt = 0; mt < 2; ++mt) {
        int row = by * 64 + wm * 32 + mt * 16 + gid;
#pragma unroll
        for (int nt = 0; nt < 4; ++nt) {
            int col = bx * 128 + wn * 32 + nt * 8 + 2 * tig;
            float2 bb = *reinterpret_cast<const float2*>(bias + col);
            float2 v0 = make_float2(acc[mt][nt][0] + bb.x, acc[mt][nt][1] + bb.y);
            float2 v1 = make_float2(acc[mt][nt][2] + bb.x, acc[mt][nt][3] + bb.y);
            *reinterpret_cast<float2*>(C + (size_t)row * N + col) = v0;
            *reinterpret_cast<float2*>(C + (size_t)(row + 8) * N + col) = v1;
        }
    }
}

// ---------------------------------------------------------------------------
// tensor-core flash attention (R10, proven): no online max, fragment bias,
// cp.async double-buffered K/V; packed P-split.
// ---------------------------------------------------------------------------
#define ATTN_Q_BYTES (2 * 128 * PITCH * 2)
#define ATTN_BUF_BYTES (4 * 64 * PITCH * 2)
#define ATTN_SMEM_BYTES (ATTN_Q_BYTES + 2 * ATTN_BUF_BYTES)

__global__ __launch_bounds__(256, 2)
void attn_mma(const __nv_bfloat16* __restrict__ qkvh,
              const __nv_bfloat16* __restrict__ qkvl,
              const float4* __restrict__ bias4,
              __nv_bfloat16* __restrict__ outh,
              __nv_bfloat16* __restrict__ outl) {
    extern __shared__ __align__(16) char smem_raw[];
    __nv_bfloat16* Qh = reinterpret_cast<__nv_bfloat16*>(smem_raw);
    __nv_bfloat16* Ql = Qh + 128 * PITCH;
    const uint32_t uQh = smem_u32(Qh);
    const uint32_t uQl = uQh + 128 * PITCH * 2;
    const uint32_t uKV = uQl + 128 * PITCH * 2;

    const int tid = threadIdx.x;
    const int lane = tid & 31;
    const int w = tid >> 5;
    const int gid = lane >> 2;
    const int tig = lane & 3;
    const int qc = blockIdx.x;
    const int h  = blockIdx.y;
    const int b  = blockIdx.z;

    const float scale = 0.17677669529663687f;   // 1/sqrt(32)
    const int qrow0 = b * N_ + qc * 128;

    const int krow = tid >> 2;
    const int kc8 = (tid & 3) * 8;
    const uint32_t kso = (uint32_t)(krow * PITCH + kc8) * 2;

    // prologue: stage kt=0 into buffer 0
    {
        size_t g = (size_t)(b * N_ + krow) * 768 + 256 + h * HD_ + kc8;
        CP_ASYNC16(uKV + kso, qkvh + g);
        CP_ASYNC16(uKV + 5120 + kso, qkvl + g);
        CP_ASYNC16(uKV + 10240 + kso, qkvh + g + 256);
        CP_ASYNC16(uKV + 15360 + kso, qkvl + g + 256);
        CP_COMMIT();
    }

    // stage Q
#pragma unroll
    for (int i = 0; i < 2; ++i) {
        int slot = tid + i * 256;
        int row = slot >> 2;
        int c8 = (slot & 3) * 8;
        size_t g = (size_t)(qrow0 + row) * 768 + h * HD_ + c8;
        int so = row * PITCH + c8;
        *reinterpret_cast<uint4*>(&Qh[so]) =
            *reinterpret_cast<const uint4*>(qkvh + g);
        *reinterpret_cast<uint4*>(&Ql[so]) =
            *reinterpret_cast<const uint4*>(qkvl + g);
    }
    CP_WAIT0();
    __syncthreads();

    const uint32_t aoff =
        (uint32_t)((w * 16 + (lane & 15)) * PITCH + ((lane & 16) ? 8 : 0)) * 2;
    const uint32_t koff =
        (uint32_t)(((lane & 7) + ((lane & 16) ? 8 : 0)) * PITCH +
                   ((lane & 8) ? 8 : 0)) * 2;
    const uint32_t voff =
        (uint32_t)((lane & 15) * PITCH + ((lane & 16) ? 8 : 0)) * 2;

    // hoisted Q fragments
    uint32_t qh[2][4], ql[2][4];
#pragma unroll
    for (int kk = 0; kk < 2; ++kk) {
        const uint32_t kof = (uint32_t)(kk * 16) * 2;
        LDSM_X4(qh[kk][0], qh[kk][1], qh[kk][2], qh[kk][3], uQh + aoff + kof);
        LDSM_X4(ql[kk][0], ql[kk][1], ql[kk][2], ql[kk][3], uQl + aoff + kof);
    }

    float l0 = 0.0f, l1 = 0.0f;
    float oacc[4][4];
#pragma unroll
    for (int nt = 0; nt < 4; ++nt)
#pragma unroll
        for (int i = 0; i < 4; ++i) oacc[nt][i] = 0.0f;

    const float4* bias_tb =
        bias4 + ((size_t)((b * 8 + qc) * 16)) * 2048 + (w * 8) * 32 + lane;

#pragma unroll 1
    for (int kt = 0; kt < 16; ++kt) {
        const int p = kt & 1;
        const uint32_t bufb = uKV + (uint32_t)p * ATTN_BUF_BYTES;

        if (kt < 15) {
            const uint32_t nb = uKV + (uint32_t)(1 - p) * ATTN_BUF_BYTES;
            size_t g = (size_t)(b * N_ + (kt + 1) * 64 + krow) * 768 + 256 +
                       h * HD_ + kc8;
            CP_ASYNC16(nb + kso, qkvh + g);
            CP_ASYNC16(nb + 5120 + kso, qkvl + g);
            CP_ASYNC16(nb + 10240 + kso, qkvh + g + 256);
            CP_ASYNC16(nb + 15360 + kso, qkvl + g + 256);
            CP_COMMIT();
        }

        const uint32_t uKh = bufb, uKl = bufb + 5120;
        const uint32_t uVh = bufb + 10240, uVl = bufb + 15360;

        // ---- S = Q K^T (3-term split) ----
        float sacc[8][4];
#pragma unroll
        for (int nt = 0; nt < 8; ++nt)
#pragma unroll
            for (int i = 0; i < 4; ++i) sacc[nt][i] = 0.0f;

#pragma unroll
        for (int kk = 0; kk < 2; ++kk) {
            const uint32_t kof = (uint32_t)(kk * 16) * 2;
            uint32_t bh[4][4], bl[4][4];
#pragma unroll
            for (int ntp = 0; ntp < 4; ++ntp) {
                uint32_t ba = koff + (uint32_t)(ntp * 16 * PITCH) * 2 + kof;
                LDSM_X4(bh[ntp][0], bh[ntp][1], bh[ntp][2], bh[ntp][3], uKh + ba);
                LDSM_X4(bl[ntp][0], bl[ntp][1], bl[ntp][2], bl[ntp][3], uKl + ba);
            }
#pragma unroll
            for (int nt = 0; nt < 8; ++nt) {
                const int ntp = nt >> 1;
                const int hb = (nt & 1) * 2;
                MMA_BF16(sacc[nt], qh[kk][0], qh[kk][1], qh[kk][2], qh[kk][3],
                         bh[ntp][hb], bh[ntp][hb + 1]);
                MMA_BF16(sacc[nt], qh[kk][0], qh[kk][1], qh[kk][2], qh[kk][3],
                         bl[ntp][hb], bl[ntp][hb + 1]);
                MMA_BF16(sacc[nt], ql[kk][0], ql[kk][1], ql[kk][2], ql[kk][3],
                         bh[ntp][hb], bh[ntp][hb + 1]);
            }
        }

        // ---- scale + bias + exp (no max shift; bounded inputs) ----
        const float4* bt = bias_tb + kt * 2048;
#pragma unroll
        for (int nt = 0; nt < 8; ++nt) {
            float4 bb = bt[nt * 32];
            float p0 = __expf(fmaf(sacc[nt][0], scale, bb.x));
            float p1 = __expf(fmaf(sacc[nt][1], scale, bb.y));
            float p2 = __expf(fmaf(sacc[nt][2], scale, bb.z));
            float p3 = __expf(fmaf(sacc[nt][3], scale, bb.w));
            sacc[nt][0] = p0; sacc[nt][1] = p1;
            sacc[nt][2] = p2; sacc[nt][3] = p3;
            l0 += p0 + p1;
            l1 += p2 + p3;
        }

        // ---- O += P V (packed split) ----
#pragma unroll
        for (int ks = 0; ks < 4; ++ks) {
            uint32_t pah[4], pal[4];
            split2p(sacc[2 * ks][0],     sacc[2 * ks][1],     pah[0], pal[0]);
            split2p(sacc[2 * ks][2],     sacc[2 * ks][3],     pah[1], pal[1]);
            split2p(sacc[2 * ks + 1][0], sacc[2 * ks + 1][1], pah[2], pal[2]);
            split2p(sacc[2 * ks + 1][2], sacc[2 * ks + 1][3], pah[3], pal[3]);

            uint32_t vh[2][4], vl[2][4];
#pragma unroll
            for (int ntp = 0; ntp < 2; ++ntp) {
                uint32_t va = voff + (uint32_t)(ks * 16 * PITCH + ntp * 16) * 2;
                LDSM_X4T(vh[ntp][0], vh[ntp][1], vh[ntp][2], vh[ntp][3], uVh + va);
                LDSM_X4T(vl[ntp][0], vl[ntp][1], vl[ntp][2], vl[ntp][3], uVl + va);
            }
#pragma unroll
            for (int nt = 0; nt < 4; ++nt) {
                const int ntp = nt >> 1;
                const int hb = (nt & 1) * 2;
                MMA_BF16(oacc[nt], pah[0], pah[1], pah[2], pah[3],
                         vh[ntp][hb], vh[ntp][hb + 1]);
                MMA_BF16(oacc[nt], pah[0], pah[1], pah[2], pah[3],
                         vl[ntp][hb], vl[ntp][hb + 1]);
                MMA_BF16(oacc[nt], pal[0], pal[1], pal[2], pal[3],
                         vh[ntp][hb], vh[ntp][hb + 1]);
            }
        }

        if (kt < 15) CP_WAIT0();
        __syncthreads();
    }

    // ---- one-time l reduction over the 4-lane row group ----
    l0 += __shfl_xor_sync(0xffffffffu, l0, 1);
    l0 += __shfl_xor_sync(0xffffffffu, l0, 2);
    l1 += __shfl_xor_sync(0xffffffffu, l1, 1);
    l1 += __shfl_xor_sync(0xffffffffu, l1, 2);

    // ---- epilogue (packed split) ----
    const float inv0 = 1.0f / l0;
    const float inv1 = 1.0f / l1;
    const int row0 = qrow0 + w * 16 + gid;
#pragma unroll
    for (int nt = 0; nt < 4; ++nt) {
        int col = h * HD_ + nt * 8 + 2 * tig;
        uint32_t hv, lv;
        split2p(oacc[nt][0] * inv0, oacc[nt][1] * inv0, hv, lv);
        *reinterpret_cast<uint32_t*>(outh + (size_t)row0 * C_ + col) = hv;
        *reinterpret_cast<uint32_t*>(outl + (size_t)row0 * C_ + col) = lv;
        split2p(oacc[nt][2] * inv1, oacc[nt][3] * inv1, hv, lv);
        *reinterpret_cast<uint32_t*>(outh + (size_t)(row0 + 8) * C_ + col) = hv;
        *reinterpret_cast<uint32_t*>(outl + (size_t)(row0 + 8) * C_ + col) = lv;
    }
}

// ---------------------------------------------------------------------------
// launch
// ---------------------------------------------------------------------------
extern "C" void kernel_launch(void* const* d_in, const int* in_sizes, int n_in,
                              void* d_out, int out_size) {
    const float* x     = (const float*)d_in[0];
    const float* elev  = (const float*)d_in[1];
    const float* uw    = (const float*)d_in[2];
    const float* vw    = (const float*)d_in[3];
    const float* wqkv  = (const float*)d_in[4];
    const float* wproj = (const float*)d_in[5];
    const float* bproj = (const float*)d_in[6];
    const float* alpha = (const float*)d_in[7];
    const float* beta  = (const float*)d_in[8];
    float* out = (float*)d_out;

    float *ws_p;
    float4* bias4_p;
    __nv_bfloat16 *xh, *xl, *wqkvh, *wqkvl, *wprojh, *wprojl;
    __nv_bfloat16 *qkvh, *qkvl, *attnh, *attnl;
    cudaGetSymbolAddress((void**)&ws_p, g_ws);
    cudaGetSymbolAddress((void**)&bias4_p, g_bias4);
    cudaGetSymbolAddress((void**)&xh, g_xh);
    cudaGetSymbolAddress((void**)&xl, g_xl);
    cudaGetSymbolAddress((void**)&wqkvh, g_wqkvh);
    cudaGetSymbolAddress((void**)&wqkvl, g_wqkvl);
    cudaGetSymbolAddress((void**)&wprojh, g_wprojh);
    cudaGetSymbolAddress((void**)&wprojl, g_wprojl);
    cudaGetSymbolAddress((void**)&qkvh, g_qkvh);
    cudaGetSymbolAddress((void**)&qkvl, g_qkvl);
    cudaGetSymbolAddress((void**)&attnh, g_attnh);
    cudaGetSymbolAddress((void**)&attnl, g_attnl);

    cudaFuncSetAttribute(gemm_qkv,
                         cudaFuncAttributeMaxDynamicSharedMemorySize,
                         GEMM_SMEM_BYTES);
    cudaFuncSetAttribute(gemm_proj,
                         cudaFuncAttributeMaxDynamicSharedMemorySize,
                         P64_SMEM_BYTES);
    cudaFuncSetAttribute(attn_mma,
                         cudaFuncAttributeMaxDynamicSharedMemorySize,
                         ATTN_SMEM_BYTES);

    // 1) merged converts + wind strength (fused)
    convert_all<<<(N4_TOTAL + B_ * N_ + 255) / 256, 256>>>(
        x, wqkv, wproj, uw, vw, xh, xl, wqkvh, wqkvl, wprojh, wprojl, ws_p);

    // 2) fragment-ordered bias
    bias_perm_kernel<<<B_ * N_ * N_ / 4 / 256, 256>>>(elev, ws_p, alpha, beta,
                                                      bias4_p);

    // 3) qkv = x @ w_qkv^T (split output)
    gemm_qkv<<<dim3(6, 64), 256, GEMM_SMEM_BYTES>>>(
        xh, xl, wqkvh, wqkvl, qkvh, qkvl);

    // 4) flash attention (split output, no online max)
    attn_mma<<<dim3(8, NH_, B_), 256, ATTN_SMEM_BYTES>>>(
        qkvh, qkvl, bias4_p, attnh, attnl);

    // 5) out = attn @ w_proj^T + b_proj (f32 output, 64-row tiles)
    gemm_proj<<<dim3(2, 128), 256, P64_SMEM_BYTES>>>(
        attnh, attnl, wprojh, wprojl, bproj, out);
}

// round 13
// speedup vs baseline: 1.1713x; 1.1261x over previous
#include <cuda_runtime.h>
#include <cuda_fp16.h>
#include <math.h>
#include <cstdint>

// ---------------------------------------------------------------------------
// PhysicsGuidedAttentionCorrected
// B=8, N=1024, C=256, NUM_HEADS=8, hd=32
// R13: fp16 (not bf16) hi/lo pipeline. GEMMs stay 3-term (err ~2^-22).
//      Attention: S = QhKh + QhKl (drop QloKh), P as single fp16,
//      O += PhVh + PhVl (drop PloVh). MMAs/warp/kt: 96 -> 64.
// ---------------------------------------------------------------------------

#define B_ 8
#define N_ 1024
#define C_ 256
#define NH_ 8
#define HD_ 32

// scratch (device globals; no allocations allowed)
__device__ float g_ws[B_ * N_];
__device__ float4 g_bias4[B_ * N_ * N_ / 4];       // fragment-ordered bias
__device__ __half g_xh[B_ * N_ * C_];
__device__ __half g_xl[B_ * N_ * C_];
__device__ __half g_wqkvh[3 * C_ * C_];
__device__ __half g_wqkvl[3 * C_ * C_];
__device__ __half g_wprojh[C_ * C_];
__device__ __half g_wprojl[C_ * C_];
__device__ __half g_qkvh[B_ * N_ * 3 * C_];
__device__ __half g_qkvl[B_ * N_ * 3 * C_];
__device__ __half g_attnh[B_ * N_ * C_];
__device__ __half g_attnl[B_ * N_ * C_];

// ---------------------------------------------------------------------------
// helpers
// ---------------------------------------------------------------------------
__device__ __forceinline__ uint32_t smem_u32(const void* p) {
    uint32_t a;
    asm("{ .reg .u64 t; cvta.to.shared.u64 t, %1; cvt.u32.u64 %0, t; }"
        : "=r"(a) : "l"(p));
    return a;
}

#define LDSM_X4(r0, r1, r2, r3, addr)                                        \
    asm volatile("ldmatrix.sync.aligned.m8n8.x4.shared.b16 {%0,%1,%2,%3}, [%4];" \
                 : "=r"(r0), "=r"(r1), "=r"(r2), "=r"(r3) : "r"(addr))

#define LDSM_X4T(r0, r1, r2, r3, addr)                                       \
    asm volatile("ldmatrix.sync.aligned.m8n8.x4.trans.shared.b16 {%0,%1,%2,%3}, [%4];" \
                 : "=r"(r0), "=r"(r1), "=r"(r2), "=r"(r3) : "r"(addr))

#define MMA_FP16(d, a0, a1, a2, a3, b0, b1)                                  \
    asm volatile("mma.sync.aligned.m16n8k16.row.col.f32.f16.f16.f32 "        \
                 "{%0,%1,%2,%3}, {%4,%5,%6,%7}, {%8,%9}, {%0,%1,%2,%3};"     \
                 : "+f"((d)[0]), "+f"((d)[1]), "+f"((d)[2]), "+f"((d)[3])    \
                 : "r"(a0), "r"(a1), "r"(a2), "r"(a3), "r"(b0), "r"(b1))

#define CP_ASYNC16(saddr, gptr)                                              \
    asm volatile("cp.async.cg.shared.global [%0], [%1], 16;"                 \
                 :: "r"(saddr), "l"(gptr))
#define CP_COMMIT() asm volatile("cp.async.commit_group;" ::: "memory")
#define CP_WAIT0()  asm volatile("cp.async.wait_group 0;" ::: "memory")

// fp16 hi/lo split: hi = f16x2{rn(x), rn(y)}; lo = f16x2 of residuals.
__device__ __forceinline__ void split2h(float x, float y,
                                        uint32_t& hi, uint32_t& lo) {
    uint32_t h;
    asm("cvt.rn.f16x2.f32 %0, %1, %2;" : "=r"(h) : "f"(y), "f"(x));
    float fx, fy;
    asm("{\n\t.reg .f16 a,b;\n\tmov.b32 {a,b}, %2;\n\t"
        "cvt.f32.f16 %0, a;\n\tcvt.f32.f16 %1, b;\n\t}"
        : "=f"(fx), "=f"(fy) : "r"(h));
    uint32_t l;
    asm("cvt.rn.f16x2.f32 %0, %1, %2;" : "=r"(l) : "f"(y - fy), "f"(x - fx));
    hi = h; lo = l;
}
// single fp16 pack (for P)
__device__ __forceinline__ uint32_t pack_h2(float x, float y) {
    uint32_t h;
    asm("cvt.rn.f16x2.f32 %0, %1, %2;" : "=r"(h) : "f"(y), "f"(x));
    return h;
}

// ---------------------------------------------------------------------------
// bias precompute in MMA-fragment order (R8/R10 layout).
// ---------------------------------------------------------------------------
__device__ __forceinline__ float bias_val(float ei, float wi, float ej,
                                          float wj, float alpha, float beta) {
    float ed = fmaxf((ej - ei) * 1e-3f, 0.0f);
    float z = (wi + wj) * 0.5f - 5.0f;
    float wf = 1.0f / (1.0f + __expf(-z));
    float bia = -alpha * ed * (1.0f - beta * wf);
    return fminf(fmaxf(bia, -10.0f), 0.0f);
}

__global__ __launch_bounds__(256)
void bias_perm_kernel(const float* __restrict__ elev, const float* __restrict__ ws,
                      const float* __restrict__ alpha_p,
                      const float* __restrict__ beta_p,
                      float4* __restrict__ bias4) {
    const int t = blockIdx.x * blockDim.x + threadIdx.x;
    const int lane = t & 31;
    const int nt = (t >> 5) & 7;
    const int w  = (t >> 8) & 7;
    const int kt = (t >> 11) & 15;
    const int qt = (t >> 15) & 7;
    const int b  = t >> 18;
    const float alpha = *alpha_p;
    const float beta = *beta_p;

    const int i0 = qt * 128 + w * 16 + (lane >> 2);
    const int j0 = kt * 64 + nt * 8 + 2 * (lane & 3);
    const float* e = elev + b * 1024;
    const float* wsb = ws + b * 1024;
    float ei0 = e[i0], ei1 = e[i0 + 8];
    float wi0 = wsb[i0], wi1 = wsb[i0 + 8];
    float ej0 = e[j0], ej1 = e[j0 + 1];
    float wj0 = wsb[j0], wj1 = wsb[j0 + 1];

    float4 o;
    o.x = bias_val(ei0, wi0, ej0, wj0, alpha, beta);
    o.y = bias_val(ei0, wi0, ej1, wj1, alpha, beta);
    o.z = bias_val(ei1, wi1, ej0, wj0, alpha, beta);
    o.w = bias_val(ei1, wi1, ej1, wj1, alpha, beta);
    bias4[t] = o;
}

// ---------------------------------------------------------------------------
// merged converter (x | wqkv | wproj) + fused wind strength
// ---------------------------------------------------------------------------
#define N4_X (B_ * N_ * C_ / 4)
#define N4_WQKV (3 * C_ * C_ / 4)
#define N4_WPROJ (C_ * C_ / 4)
#define N4_TOTAL (N4_X + N4_WQKV + N4_WPROJ)

__global__ void convert_all(const float* __restrict__ x,
                            const float* __restrict__ wqkv,
                            const float* __restrict__ wproj,
                            const float* __restrict__ uwind,
                            const float* __restrict__ vwind,
                            __half* __restrict__ xh, __half* __restrict__ xl,
                            __half* __restrict__ wqh, __half* __restrict__ wql,
                            __half* __restrict__ wph, __half* __restrict__ wpl,
                            float* __restrict__ ws) {
    int i = blockIdx.x * blockDim.x + threadIdx.x;
    if (i >= N4_TOTAL) {
        int t = i - N4_TOTAL;
        if (t >= B_ * N_) return;
        int b = t >> 10;
        int n = t & 1023;
        int r = n >> 5;
        int c = n & 31;
        const float* ub = uwind + b * 4096;
        const float* vb = vwind + b * 4096;
        float s = 0.0f;
#pragma unroll
        for (int dr = 0; dr < 2; ++dr)
#pragma unroll
            for (int dc = 0; dc < 2; ++dc) {
                int idx = (2 * r + dr) * 64 + (2 * c + dc);
                float uu = ub[idx], vv = vb[idx];
                s += sqrtf(uu * uu + vv * vv + 1e-8f);
            }
        ws[t] = s * 0.25f;
        return;
    }
    const float* in;
    __half *hi, *lo;
    int off;
    if (i < N4_X) { in = x; hi = xh; lo = xl; off = i; }
    else if (i < N4_X + N4_WQKV) { in = wqkv; hi = wqh; lo = wql; off = i - N4_X; }
    else { in = wproj; hi = wph; lo = wpl; off = i - N4_X - N4_WQKV; }
    float4 v = reinterpret_cast<const float4*>(in)[off];
    uint32_t h01, l01, h23, l23;
    split2h(v.x, v.y, h01, l01);
    split2h(v.z, v.w, h23, l23);
    *reinterpret_cast<uint2*>(hi + 4 * off) = make_uint2(h01, h23);
    *reinterpret_cast<uint2*>(lo + 4 * off) = make_uint2(l01, l23);
}

// ---------------------------------------------------------------------------
// fp16-split tensor-core GEMM 128x128 (QKV, split output), 3-term.
// ---------------------------------------------------------------------------
#define PITCH 40
#define GEMM_BUF_BYTES (4 * 128 * PITCH * 2)
#define GEMM_SMEM_BYTES (2 * GEMM_BUF_BYTES)

__global__ __launch_bounds__(256, 2)
void gemm_qkv(const __half* __restrict__ Ah, const __half* __restrict__ Al,
              const __half* __restrict__ Bh, const __half* __restrict__ Bl,
              __half* __restrict__ Ch, __half* __restrict__ Cl) {
    const int N = 768;
    extern __shared__ __align__(16) char smem_raw[];
    const uint32_t uS = smem_u32(smem_raw);

    const int tid = threadIdx.x;
    const int lane = tid & 31;
    const int wid = tid >> 5;
    const int wm = wid & 1;
    const int wn = wid >> 1;
    const int bx = blockIdx.x;
    const int by = blockIdx.y;

    const __half* Agh = Ah + (size_t)by * 128 * 256;
    const __half* Agl = Al + (size_t)by * 128 * 256;
    const __half* Bgh = Bh + (size_t)bx * 128 * 256;
    const __half* Bgl = Bl + (size_t)bx * 128 * 256;

    float acc[4][4][4];
#pragma unroll
    for (int mt = 0; mt < 4; ++mt)
#pragma unroll
        for (int nt = 0; nt < 4; ++nt)
#pragma unroll
            for (int i = 0; i < 4; ++i) acc[mt][nt][i] = 0.0f;

    const uint32_t aoff =
        (uint32_t)((wm * 64 + (lane & 15)) * PITCH + ((lane & 16) ? 8 : 0)) * 2;
    const uint32_t boff =
        (uint32_t)((wn * 32 + (lane & 7) + ((lane & 16) ? 8 : 0)) * PITCH +
                   ((lane & 8) ? 8 : 0)) * 2;

    const int row0 = tid >> 2;
    const int c8 = (tid & 3) * 8;

#pragma unroll
    for (int i = 0; i < 2; ++i) {
        int row = row0 + i * 64;
        size_t g = (size_t)row * 256 + c8;
        uint32_t so = (uint32_t)(row * PITCH + c8) * 2;
        CP_ASYNC16(uS + so, Agh + g);
        CP_ASYNC16(uS + 10240 + so, Agl + g);
        CP_ASYNC16(uS + 20480 + so, Bgh + g);
        CP_ASYNC16(uS + 30720 + so, Bgl + g);
    }
    CP_COMMIT();
    CP_WAIT0();
    __syncthreads();

#pragma unroll 1
    for (int kb = 0; kb < 8; ++kb) {
        const int p = kb & 1;
        const uint32_t bufb = uS + (uint32_t)p * GEMM_BUF_BYTES;

        if (kb < 7) {
            const uint32_t nb = uS + (uint32_t)(1 - p) * GEMM_BUF_BYTES;
#pragma unroll
            for (int i = 0; i < 2; ++i) {
                int row = row0 + i * 64;
                size_t g = (size_t)row * 256 + (kb + 1) * 32 + c8;
                uint32_t so = (uint32_t)(row * PITCH + c8) * 2;
                CP_ASYNC16(nb + so, Agh + g);
                CP_ASYNC16(nb + 10240 + so, Agl + g);
                CP_ASYNC16(nb + 20480 + so, Bgh + g);
                CP_ASYNC16(nb + 30720 + so, Bgl + g);
            }
            CP_COMMIT();
        }

        const uint32_t uAh = bufb, uAl = bufb + 10240;
        const uint32_t uBh = bufb + 20480, uBl = bufb + 30720;

#pragma unroll
        for (int kk = 0; kk < 2; ++kk) {
            const uint32_t kof = (uint32_t)(kk * 16) * 2;
            uint32_t bhf[2][4], blf[2][4];
#pragma unroll
            for (int ntp = 0; ntp < 2; ++ntp) {
                uint32_t ba = boff + (uint32_t)(ntp * 16 * PITCH) * 2 + kof;
                LDSM_X4(bhf[ntp][0], bhf[ntp][1], bhf[ntp][2], bhf[ntp][3], uBh + ba);
                LDSM_X4(blf[ntp][0], blf[ntp][1], blf[ntp][2], blf[ntp][3], uBl + ba);
            }
#pragma unroll
            for (int mt = 0; mt < 4; ++mt) {
                uint32_t aa = aoff + (uint32_t)(mt * 16 * PITCH) * 2 + kof;
                uint32_t ah0, ah1, ah2, ah3, al0, al1, al2, al3;
                LDSM_X4(ah0, ah1, ah2, ah3, uAh + aa);
                LDSM_X4(al0, al1, al2, al3, uAl + aa);
#pragma unroll
                for (int nt = 0; nt < 4; ++nt) {
                    const int ntp = nt >> 1;
                    const int hb = (nt & 1) * 2;
                    MMA_FP16(acc[mt][nt], ah0, ah1, ah2, ah3,
                             bhf[ntp][hb], bhf[ntp][hb + 1]);
                    MMA_FP16(acc[mt][nt], ah0, ah1, ah2, ah3,
                             blf[ntp][hb], blf[ntp][hb + 1]);
                    MMA_FP16(acc[mt][nt], al0, al1, al2, al3,
                             bhf[ntp][hb], bhf[ntp][hb + 1]);
                }
            }
        }

        if (kb < 7) CP_WAIT0();
        __syncthreads();
    }

    const int gid = lane >> 2;
    const int tig = lane & 3;
#pragma unroll
    for (int mt = 0; mt < 4; ++mt) {
        int row = by * 128 + wm * 64 + mt * 16 + gid;
#pragma unroll
        for (int nt = 0; nt < 4; ++nt) {
            int col = bx * 128 + wn * 32 + nt * 8 + 2 * tig;
            uint32_t hh, ll;
            split2h(acc[mt][nt][0], acc[mt][nt][1], hh, ll);
            *reinterpret_cast<uint32_t*>(Ch + (size_t)row * N + col) = hh;
            *reinterpret_cast<uint32_t*>(Cl + (size_t)row * N + col) = ll;
            split2h(acc[mt][nt][2], acc[mt][nt][3], hh, ll);
            *reinterpret_cast<uint32_t*>(Ch + (size_t)(row + 8) * N + col) = hh;
            *reinterpret_cast<uint32_t*>(Cl + (size_t)(row + 8) * N + col) = ll;
        }
    }
}

// ---------------------------------------------------------------------------
// proj GEMM: 64x128 tiles, fp16 3-term, f32 + bias output.
// ---------------------------------------------------------------------------
#define P64_BUF_BYTES (2 * 64 * PITCH * 2 + 2 * 128 * PITCH * 2)   // 30720
#define P64_SMEM_BYTES (2 * P64_BUF_BYTES)

__global__ __launch_bounds__(256, 2)
void gemm_proj(const __half* __restrict__ Ah, const __half* __restrict__ Al,
               const __half* __restrict__ Bh, const __half* __restrict__ Bl,
               const float* __restrict__ bias, float* __restrict__ C) {
    const int N = 256;
    extern __shared__ __align__(16) char smem_raw[];
    const uint32_t uS = smem_u32(smem_raw);

    const int tid = threadIdx.x;
    const int lane = tid & 31;
    const int wid = tid >> 5;
    const int wm = wid & 1;
    const int wn = wid >> 1;
    const int bx = blockIdx.x;
    const int by = blockIdx.y;

    const __half* Agh = Ah + (size_t)by * 64 * 256;
    const __half* Agl = Al + (size_t)by * 64 * 256;
    const __half* Bgh = Bh + (size_t)bx * 128 * 256;
    const __half* Bgl = Bl + (size_t)bx * 128 * 256;

    float acc[2][4][4];
#pragma unroll
    for (int mt = 0; mt < 2; ++mt)
#pragma unroll
        for (int nt = 0; nt < 4; ++nt)
#pragma unroll
            for (int i = 0; i < 4; ++i) acc[mt][nt][i] = 0.0f;

    const uint32_t aoff =
        (uint32_t)((wm * 32 + (lane & 15)) * PITCH + ((lane & 16) ? 8 : 0)) * 2;
    const uint32_t boff =
        (uint32_t)((wn * 32 + (lane & 7) + ((lane & 16) ? 8 : 0)) * PITCH +
                   ((lane & 8) ? 8 : 0)) * 2;

    const int arow = tid >> 2;
    const int ac8 = (tid & 3) * 8;
    const uint32_t aso = (uint32_t)(arow * PITCH + ac8) * 2;
    const int brow0 = tid >> 2;

#pragma unroll 1
    for (int kb = -1; kb < 8; ++kb) {
        if (kb < 7) {
            const uint32_t nb = uS + (uint32_t)((kb + 1) & 1) * P64_BUF_BYTES;
            int kof = (kb + 1) * 32;
            {
                size_t g = (size_t)arow * 256 + kof + ac8;
                CP_ASYNC16(nb + aso, Agh + g);
                CP_ASYNC16(nb + 5120 + aso, Agl + g);
            }
#pragma unroll
            for (int i = 0; i < 2; ++i) {
                int row = brow0 + i * 64;
                size_t g = (size_t)row * 256 + kof + ac8;
                uint32_t so = (uint32_t)(row * PITCH + ac8) * 2;
                CP_ASYNC16(nb + 10240 + so, Bgh + g);
                CP_ASYNC16(nb + 20480 + so, Bgl + g);
            }
            CP_COMMIT();
        }
        if (kb < 0) { CP_WAIT0(); __syncthreads(); continue; }

        const uint32_t bufb = uS + (uint32_t)(kb & 1) * P64_BUF_BYTES;
        const uint32_t uAh = bufb, uAl = bufb + 5120;
        const uint32_t uBh = bufb + 10240, uBl = bufb + 20480;

#pragma unroll
        for (int kk = 0; kk < 2; ++kk) {
            const uint32_t kof = (uint32_t)(kk * 16) * 2;
            uint32_t bhf[2][4], blf[2][4];
#pragma unroll
            for (int ntp = 0; ntp < 2; ++ntp) {
                uint32_t ba = boff + (uint32_t)(ntp * 16 * PITCH) * 2 + kof;
                LDSM_X4(bhf[ntp][0], bhf[ntp][1], bhf[ntp][2], bhf[ntp][3], uBh + ba);
                LDSM_X4(blf[ntp][0], blf[ntp][1], blf[ntp][2], blf[ntp][3], uBl + ba);
            }
#pragma unroll
            for (int mt = 0; mt < 2; ++mt) {
                uint32_t aa = aoff + (uint32_t)(mt * 16 * PITCH) * 2 + kof;
                uint32_t ah0, ah1, ah2, ah3, al0, al1, al2, al3;
                LDSM_X4(ah0, ah1, ah2, ah3, uAh + aa);
                LDSM_X4(al0, al1, al2, al3, uAl + aa);
#pragma unroll
                for (int nt = 0; nt < 4; ++nt) {
                    const int ntp = nt >> 1;
                    const int hb = (nt & 1) * 2;
                    MMA_FP16(acc[mt][nt], ah0, ah1, ah2, ah3,
                             bhf[ntp][hb], bhf[ntp][hb + 1]);
                    MMA_FP16(acc[mt][nt], ah0, ah1, ah2, ah3,
                             blf[ntp][hb], blf[ntp][hb + 1]);
                    MMA_FP16(acc[mt][nt], al0, al1, al2, al3,
                             bhf[ntp][hb], bhf[ntp][hb + 1]);
                }
            }
        }

        if (kb < 7) CP_WAIT0();
        __syncthreads();
    }

    const int gid = lane >> 2;
    const int tig = lane & 3;
#pragma unroll
    for (int mt = 0; mt < 2; ++mt) {
        int row = by * 64 + wm * 32 + mt * 16 + gid;
#pragma unroll
        for (int nt = 0; nt < 4; ++nt) {
            int col = bx * 128 + wn * 32 + nt * 8 + 2 * tig;
            float2 bb = *reinterpret_cast<const float2*>(bias + col);
            float2 v0 = make_float2(acc[mt][nt][0] + bb.x, acc[mt][nt][1] + bb.y);
            float2 v1 = make_float2(acc[mt][nt][2] + bb.x, acc[mt][nt][3] + bb.y);
            *reinterpret_cast<float2*>(C + (size_t)row * N + col) = v0;
            *reinterpret_cast<float2*>(C + (size_t)(row + 8) * N + col) = v1;
        }
    }
}

// ---------------------------------------------------------------------------
// fp16 flash attention: S = QhKh + QhKl (no Q_lo), P single fp16,
// O += PhVh + PhVl. No online max. 64 MMAs/warp/kt.
// ---------------------------------------------------------------------------
#define ATTN_Q_BYTES (128 * PITCH * 2)            // 10240 (Qh only)
#define ATTN_BUF_BYTES (4 * 64 * PITCH * 2)       // 20480 per buffer
#define ATTN_SMEM_BYTES (ATTN_Q_BYTES + 2 * ATTN_BUF_BYTES)   // 51200

__global__ __launch_bounds__(256, 2)
void attn_mma(const __half* __restrict__ qkvh,
              const __half* __restrict__ qkvl,
              const float4* __restrict__ bias4,
              __half* __restrict__ outh,
              __half* __restrict__ outl) {
    extern __shared__ __align__(16) char smem_raw[];
    __half* Qh = reinterpret_cast<__half*>(smem_raw);
    const uint32_t uQh = smem_u32(Qh);
    const uint32_t uKV = uQh + ATTN_Q_BYTES;

    const int tid = threadIdx.x;
    const int lane = tid & 31;
    const int w = tid >> 5;
    const int gid = lane >> 2;
    const int tig = lane & 3;
    const int qc = blockIdx.x;
    const int h  = blockIdx.y;
    const int b  = blockIdx.z;

    const float scale = 0.17677669529663687f;   // 1/sqrt(32)
    const int qrow0 = b * N_ + qc * 128;

    const int krow = tid >> 2;
    const int kc8 = (tid & 3) * 8;
    const uint32_t kso = (uint32_t)(krow * PITCH + kc8) * 2;

    // prologue: stage kt=0 into buffer 0
    {
        size_t g = (size_t)(b * N_ + krow) * 768 + 256 + h * HD_ + kc8;
        CP_ASYNC16(uKV + kso, qkvh + g);
        CP_ASYNC16(uKV + 5120 + kso, qkvl + g);
        CP_ASYNC16(uKV + 10240 + kso, qkvh + g + 256);
        CP_ASYNC16(uKV + 15360 + kso, qkvl + g + 256);
        CP_COMMIT();
    }

    // stage Qh only (Q_lo unused: its cross term is dropped)
    {
        int row = tid >> 1;                 // 0..127
        int c8 = (tid & 1) * 16;
        size_t g = (size_t)(qrow0 + row) * 768 + h * HD_ + c8;
        int so = row * PITCH + c8;
        *reinterpret_cast<uint4*>(&Qh[so]) =
            *reinterpret_cast<const uint4*>(qkvh + g);
        *reinterpret_cast<uint4*>(&Qh[so + 8]) =
            *reinterpret_cast<const uint4*>(qkvh + g + 8);
    }
    CP_WAIT0();
    __syncthreads();

    const uint32_t aoff =
        (uint32_t)((w * 16 + (lane & 15)) * PITCH + ((lane & 16) ? 8 : 0)) * 2;
    const uint32_t koff =
        (uint32_t)(((lane & 7) + ((lane & 16) ? 8 : 0)) * PITCH +
                   ((lane & 8) ? 8 : 0)) * 2;
    const uint32_t voff =
        (uint32_t)((lane & 15) * PITCH + ((lane & 16) ? 8 : 0)) * 2;

    // hoisted Qh fragments
    uint32_t qh[2][4];
#pragma unroll
    for (int kk = 0; kk < 2; ++kk) {
        const uint32_t kof = (uint32_t)(kk * 16) * 2;
        LDSM_X4(qh[kk][0], qh[kk][1], qh[kk][2], qh[kk][3], uQh + aoff + kof);
    }

    float l0 = 0.0f, l1 = 0.0f;
    float oacc[4][4];
#pragma unroll
    for (int nt = 0; nt < 4; ++nt)
#pragma unroll
        for (int i = 0; i < 4; ++i) oacc[nt][i] = 0.0f;

    const float4* bias_tb =
        bias4 + ((size_t)((b * 8 + qc) * 16)) * 2048 + (w * 8) * 32 + lane;

#pragma unroll 1
    for (int kt = 0; kt < 16; ++kt) {
        const int p = kt & 1;
        const uint32_t bufb = uKV + (uint32_t)p * ATTN_BUF_BYTES;

        if (kt < 15) {
            const uint32_t nb = uKV + (uint32_t)(1 - p) * ATTN_BUF_BYTES;
            size_t g = (size_t)(b * N_ + (kt + 1) * 64 + krow) * 768 + 256 +
                       h * HD_ + kc8;
            CP_ASYNC16(nb + kso, qkvh + g);
            CP_ASYNC16(nb + 5120 + kso, qkvl + g);
            CP_ASYNC16(nb + 10240 + kso, qkvh + g + 256);
            CP_ASYNC16(nb + 15360 + kso, qkvl + g + 256);
            CP_COMMIT();
        }

        const uint32_t uKh = bufb, uKl = bufb + 5120;
        const uint32_t uVh = bufb + 10240, uVl = bufb + 15360;

        // ---- S = Qh*Kh + Qh*Kl ----
        float sacc[8][4];
#pragma unroll
        for (int nt = 0; nt < 8; ++nt)
#pragma unroll
            for (int i = 0; i < 4; ++i) sacc[nt][i] = 0.0f;

#pragma unroll
        for (int kk = 0; kk < 2; ++kk) {
            const uint32_t kof = (uint32_t)(kk * 16) * 2;
            uint32_t bh[4][4], bl[4][4];
#pragma unroll
            for (int ntp = 0; ntp < 4; ++ntp) {
                uint32_t ba = koff + (uint32_t)(ntp * 16 * PITCH) * 2 + kof;
                LDSM_X4(bh[ntp][0], bh[ntp][1], bh[ntp][2], bh[ntp][3], uKh + ba);
                LDSM_X4(bl[ntp][0], bl[ntp][1], bl[ntp][2], bl[ntp][3], uKl + ba);
            }
#pragma unroll
            for (int nt = 0; nt < 8; ++nt) {
                const int ntp = nt >> 1;
                const int hb = (nt & 1) * 2;
                MMA_FP16(sacc[nt], qh[kk][0], qh[kk][1], qh[kk][2], qh[kk][3],
                         bh[ntp][hb], bh[ntp][hb + 1]);
                MMA_FP16(sacc[nt], qh[kk][0], qh[kk][1], qh[kk][2], qh[kk][3],
                         bl[ntp][hb], bl[ntp][hb + 1]);
            }
        }

        // ---- scale + bias + exp ----
        const float4* bt = bias_tb + kt * 2048;
#pragma unroll
        for (int nt = 0; nt < 8; ++nt) {
            float4 bb = bt[nt * 32];
            float p0 = __expf(fmaf(sacc[nt][0], scale, bb.x));
            float p1 = __expf(fmaf(sacc[nt][1], scale, bb.y));
            float p2 = __expf(fmaf(sacc[nt][2], scale, bb.z));
            float p3 = __expf(fmaf(sacc[nt][3], scale, bb.w));
            sacc[nt][0] = p0; sacc[nt][1] = p1;
            sacc[nt][2] = p2; sacc[nt][3] = p3;
            l0 += p0 + p1;
            l1 += p2 + p3;
        }

        // ---- O += Ph*Vh + Ph*Vl (P single fp16) ----
#pragma unroll
        for (int ks = 0; ks < 4; ++ks) {
            uint32_t pah[4];
            pah[0] = pack_h2(sacc[2 * ks][0],     sacc[2 * ks][1]);
            pah[1] = pack_h2(sacc[2 * ks][2],     sacc[2 * ks][3]);
            pah[2] = pack_h2(sacc[2 * ks + 1][0], sacc[2 * ks + 1][1]);
            pah[3] = pack_h2(sacc[2 * ks + 1][2], sacc[2 * ks + 1][3]);

            uint32_t vh[2][4], vl[2][4];
#pragma unroll
            for (int ntp = 0; ntp < 2; ++ntp) {
                uint32_t va = voff + (uint32_t)(ks * 16 * PITCH + ntp * 16) * 2;
                LDSM_X4T(vh[ntp][0], vh[ntp][1], vh[ntp][2], vh[ntp][3], uVh + va);
                LDSM_X4T(vl[ntp][0], vl[ntp][1], vl[ntp][2], vl[ntp][3], uVl + va);
            }
#pragma unroll
            for (int nt = 0; nt < 4; ++nt) {
                const int ntp = nt >> 1;
                const int hb = (nt & 1) * 2;
                MMA_FP16(oacc[nt], pah[0], pah[1], pah[2], pah[3],
                         vh[ntp][hb], vh[ntp][hb + 1]);
                MMA_FP16(oacc[nt], pah[0], pah[1], pah[2], pah[3],
                         vl[ntp][hb], vl[ntp][hb + 1]);
            }
        }

        if (kt < 15) CP_WAIT0();
        __syncthreads();
    }

    // ---- one-time l reduction over the 4-lane row group ----
    l0 += __shfl_xor_sync(0xffffffffu, l0, 1);
    l0 += __shfl_xor_sync(0xffffffffu, l0, 2);
    l1 += __shfl_xor_sync(0xffffffffu, l1, 1);
    l1 += __shfl_xor_sync(0xffffffffu, l1, 2);

    // ---- epilogue ----
    const float inv0 = 1.0f / l0;
    const float inv1 = 1.0f / l1;
    const int row0 = qrow0 + w * 16 + gid;
#pragma unroll
    for (int nt = 0; nt < 4; ++nt) {
        int col = h * HD_ + nt * 8 + 2 * tig;
        uint32_t hv, lv;
        split2h(oacc[nt][0] * inv0, oacc[nt][1] * inv0, hv, lv);
        *reinterpret_cast<uint32_t*>(outh + (size_t)row0 * C_ + col) = hv;
        *reinterpret_cast<uint32_t*>(outl + (size_t)row0 * C_ + col) = lv;
        split2h(oacc[nt][2] * inv1, oacc[nt][3] * inv1, hv, lv);
        *reinterpret_cast<uint32_t*>(outh + (size_t)(row0 + 8) * C_ + col) = hv;
        *reinterpret_cast<uint32_t*>(outl + (size_t)(row0 + 8) * C_ + col) = lv;
    }
}

// ---------------------------------------------------------------------------
// launch
// ---------------------------------------------------------------------------
extern "C" void kernel_launch(void* const* d_in, const int* in_sizes, int n_in,
                              void* d_out, int out_size) {
    const float* x     = (const float*)d_in[0];
    const float* elev  = (const float*)d_in[1];
    const float* uw    = (const float*)d_in[2];
    const float* vw    = (const float*)d_in[3];
    const float* wqkv  = (const float*)d_in[4];
    const float* wproj = (const float*)d_in[5];
    const float* bproj = (const float*)d_in[6];
    const float* alpha = (const float*)d_in[7];
    const float* beta  = (const float*)d_in[8];
    float* out = (float*)d_out;

    float *ws_p;
    float4* bias4_p;
    __half *xh, *xl, *wqkvh, *wqkvl, *wprojh, *wprojl;
    __half *qkvh, *qkvl, *attnh, *attnl;
    cudaGetSymbolAddress((void**)&ws_p, g_ws);
    cudaGetSymbolAddress((void**)&bias4_p, g_bias4);
    cudaGetSymbolAddress((void**)&xh, g_xh);
    cudaGetSymbolAddress((void**)&xl, g_xl);
    cudaGetSymbolAddress((void**)&wqkvh, g_wqkvh);
    cudaGetSymbolAddress((void**)&wqkvl, g_wqkvl);
    cudaGetSymbolAddress((void**)&wprojh, g_wprojh);
    cudaGetSymbolAddress((void**)&wprojl, g_wprojl);
    cudaGetSymbolAddress((void**)&qkvh, g_qkvh);
    cudaGetSymbolAddress((void**)&qkvl, g_qkvl);
    cudaGetSymbolAddress((void**)&attnh, g_attnh);
    cudaGetSymbolAddress((void**)&attnl, g_attnl);

    cudaFuncSetAttribute(gemm_qkv,
                         cudaFuncAttributeMaxDynamicSharedMemorySize,
                         GEMM_SMEM_BYTES);
    cudaFuncSetAttribute(gemm_proj,
                         cudaFuncAttributeMaxDynamicSharedMemorySize,
                         P64_SMEM_BYTES);
    cudaFuncSetAttribute(attn_mma,
                         cudaFuncAttributeMaxDynamicSharedMemorySize,
                         ATTN_SMEM_BYTES);

    // 1) merged converts + wind strength (fused)
    convert_all<<<(N4_TOTAL + B_ * N_ + 255) / 256, 256>>>(
        x, wqkv, wproj, uw, vw, xh, xl, wqkvh, wqkvl, wprojh, wprojl, ws_p);

    // 2) fragment-ordered bias
    bias_perm_kernel<<<B_ * N_ * N_ / 4 / 256, 256>>>(elev, ws_p, alpha, beta,
                                                      bias4_p);

    // 3) qkv = x @ w_qkv^T (split output)
    gemm_qkv<<<dim3(6, 64), 256, GEMM_SMEM_BYTES>>>(
        xh, xl, wqkvh, wqkvl, qkvh, qkvl);

    // 4) flash attention (fp16, reduced-term)
    attn_mma<<<dim3(8, NH_, B_), 256, ATTN_SMEM_BYTES>>>(
        qkvh, qkvl, bias4_p, attnh, attnl);

    // 5) out = attn @ w_proj^T + b_proj
    gemm_proj<<<dim3(2, 128), 256, P64_SMEM_BYTES>>>(
        attnh, attnl, wprojh, wprojl, bproj, out);
}

// round 14
// speedup vs baseline: 1.4376x; 1.2274x over previous
#include <cuda_runtime.h>
#include <cuda_fp16.h>
#include <math.h>
#include <cstdint>

// ---------------------------------------------------------------------------
// PhysicsGuidedAttentionCorrected
// B=8, N=1024, C=256, NUM_HEADS=8, hd=32
// R14: pure-fp16 attention (S=QhKh, P fp16, O=PhVh; 32 MMAs/warp/kt,
//      K/V lo never loaded -> staging & smem halved). QKV GEMM computes
//      3-term f32 then stores single fp16. proj stays 3-term from split attn.
// ---------------------------------------------------------------------------

#define B_ 8
#define N_ 1024
#define C_ 256
#define NH_ 8
#define HD_ 32

// scratch (device globals; no allocations allowed)
__device__ float g_ws[B_ * N_];
__device__ float4 g_bias4[B_ * N_ * N_ / 4];       // fragment-ordered bias
__device__ __half g_xh[B_ * N_ * C_];
__device__ __half g_xl[B_ * N_ * C_];
__device__ __half g_wqkvh[3 * C_ * C_];
__device__ __half g_wqkvl[3 * C_ * C_];
__device__ __half g_wprojh[C_ * C_];
__device__ __half g_wprojl[C_ * C_];
__device__ __half g_qkvh[B_ * N_ * 3 * C_];
__device__ __half g_attnh[B_ * N_ * C_];
__device__ __half g_attnl[B_ * N_ * C_];

// ---------------------------------------------------------------------------
// helpers
// ---------------------------------------------------------------------------
__device__ __forceinline__ uint32_t smem_u32(const void* p) {
    uint32_t a;
    asm("{ .reg .u64 t; cvta.to.shared.u64 t, %1; cvt.u32.u64 %0, t; }"
        : "=r"(a) : "l"(p));
    return a;
}

#define LDSM_X4(r0, r1, r2, r3, addr)                                        \
    asm volatile("ldmatrix.sync.aligned.m8n8.x4.shared.b16 {%0,%1,%2,%3}, [%4];" \
                 : "=r"(r0), "=r"(r1), "=r"(r2), "=r"(r3) : "r"(addr))

#define LDSM_X4T(r0, r1, r2, r3, addr)                                       \
    asm volatile("ldmatrix.sync.aligned.m8n8.x4.trans.shared.b16 {%0,%1,%2,%3}, [%4];" \
                 : "=r"(r0), "=r"(r1), "=r"(r2), "=r"(r3) : "r"(addr))

#define MMA_FP16(d, a0, a1, a2, a3, b0, b1)                                  \
    asm volatile("mma.sync.aligned.m16n8k16.row.col.f32.f16.f16.f32 "        \
                 "{%0,%1,%2,%3}, {%4,%5,%6,%7}, {%8,%9}, {%0,%1,%2,%3};"     \
                 : "+f"((d)[0]), "+f"((d)[1]), "+f"((d)[2]), "+f"((d)[3])    \
                 : "r"(a0), "r"(a1), "r"(a2), "r"(a3), "r"(b0), "r"(b1))

#define CP_ASYNC16(saddr, gptr)                                              \
    asm volatile("cp.async.cg.shared.global [%0], [%1], 16;"                 \
                 :: "r"(saddr), "l"(gptr))
#define CP_COMMIT() asm volatile("cp.async.commit_group;" ::: "memory")
#define CP_WAIT0()  asm volatile("cp.async.wait_group 0;" ::: "memory")

// fp16 hi/lo split
__device__ __forceinline__ void split2h(float x, float y,
                                        uint32_t& hi, uint32_t& lo) {
    uint32_t h;
    asm("cvt.rn.f16x2.f32 %0, %1, %2;" : "=r"(h) : "f"(y), "f"(x));
    float fx, fy;
    asm("{\n\t.reg .f16 a,b;\n\tmov.b32 {a,b}, %2;\n\t"
        "cvt.f32.f16 %0, a;\n\tcvt.f32.f16 %1, b;\n\t}"
        : "=f"(fx), "=f"(fy) : "r"(h));
    uint32_t l;
    asm("cvt.rn.f16x2.f32 %0, %1, %2;" : "=r"(l) : "f"(y - fy), "f"(x - fx));
    hi = h; lo = l;
}
__device__ __forceinline__ uint32_t pack_h2(float x, float y) {
    uint32_t h;
    asm("cvt.rn.f16x2.f32 %0, %1, %2;" : "=r"(h) : "f"(y), "f"(x));
    return h;
}

// ---------------------------------------------------------------------------
// bias precompute in MMA-fragment order (R8/R10 layout).
// ---------------------------------------------------------------------------
__device__ __forceinline__ float bias_val(float ei, float wi, float ej,
                                          float wj, float alpha, float beta) {
    float ed = fmaxf((ej - ei) * 1e-3f, 0.0f);
    float z = (wi + wj) * 0.5f - 5.0f;
    float wf = 1.0f / (1.0f + __expf(-z));
    float bia = -alpha * ed * (1.0f - beta * wf);
    return fminf(fmaxf(bia, -10.0f), 0.0f);
}

__global__ __launch_bounds__(256)
void bias_perm_kernel(const float* __restrict__ elev, const float* __restrict__ ws,
                      const float* __restrict__ alpha_p,
                      const float* __restrict__ beta_p,
                      float4* __restrict__ bias4) {
    const int t = blockIdx.x * blockDim.x + threadIdx.x;
    const int lane = t & 31;
    const int nt = (t >> 5) & 7;
    const int w  = (t >> 8) & 7;
    const int kt = (t >> 11) & 15;
    const int qt = (t >> 15) & 7;
    const int b  = t >> 18;
    const float alpha = *alpha_p;
    const float beta = *beta_p;

    const int i0 = qt * 128 + w * 16 + (lane >> 2);
    const int j0 = kt * 64 + nt * 8 + 2 * (lane & 3);
    const float* e = elev + b * 1024;
    const float* wsb = ws + b * 1024;
    float ei0 = e[i0], ei1 = e[i0 + 8];
    float wi0 = wsb[i0], wi1 = wsb[i0 + 8];
    float ej0 = e[j0], ej1 = e[j0 + 1];
    float wj0 = wsb[j0], wj1 = wsb[j0 + 1];

    float4 o;
    o.x = bias_val(ei0, wi0, ej0, wj0, alpha, beta);
    o.y = bias_val(ei0, wi0, ej1, wj1, alpha, beta);
    o.z = bias_val(ei1, wi1, ej0, wj0, alpha, beta);
    o.w = bias_val(ei1, wi1, ej1, wj1, alpha, beta);
    bias4[t] = o;
}

// ---------------------------------------------------------------------------
// merged converter (x | wqkv | wproj) + fused wind strength
// ---------------------------------------------------------------------------
#define N4_X (B_ * N_ * C_ / 4)
#define N4_WQKV (3 * C_ * C_ / 4)
#define N4_WPROJ (C_ * C_ / 4)
#define N4_TOTAL (N4_X + N4_WQKV + N4_WPROJ)

__global__ void convert_all(const float* __restrict__ x,
                            const float* __restrict__ wqkv,
                            const float* __restrict__ wproj,
                            const float* __restrict__ uwind,
                            const float* __restrict__ vwind,
                            __half* __restrict__ xh, __half* __restrict__ xl,
                            __half* __restrict__ wqh, __half* __restrict__ wql,
                            __half* __restrict__ wph, __half* __restrict__ wpl,
                            float* __restrict__ ws) {
    int i = blockIdx.x * blockDim.x + threadIdx.x;
    if (i >= N4_TOTAL) {
        int t = i - N4_TOTAL;
        if (t >= B_ * N_) return;
        int b = t >> 10;
        int n = t & 1023;
        int r = n >> 5;
        int c = n & 31;
        const float* ub = uwind + b * 4096;
        const float* vb = vwind + b * 4096;
        float s = 0.0f;
#pragma unroll
        for (int dr = 0; dr < 2; ++dr)
#pragma unroll
            for (int dc = 0; dc < 2; ++dc) {
                int idx = (2 * r + dr) * 64 + (2 * c + dc);
                float uu = ub[idx], vv = vb[idx];
                s += sqrtf(uu * uu + vv * vv + 1e-8f);
            }
        ws[t] = s * 0.25f;
        return;
    }
    const float* in;
    __half *hi, *lo;
    int off;
    if (i < N4_X) { in = x; hi = xh; lo = xl; off = i; }
    else if (i < N4_X + N4_WQKV) { in = wqkv; hi = wqh; lo = wql; off = i - N4_X; }
    else { in = wproj; hi = wph; lo = wpl; off = i - N4_X - N4_WQKV; }
    float4 v = reinterpret_cast<const float4*>(in)[off];
    uint32_t h01, l01, h23, l23;
    split2h(v.x, v.y, h01, l01);
    split2h(v.z, v.w, h23, l23);
    *reinterpret_cast<uint2*>(hi + 4 * off) = make_uint2(h01, h23);
    *reinterpret_cast<uint2*>(lo + 4 * off) = make_uint2(l01, l23);
}

// ---------------------------------------------------------------------------
// fp16-split GEMM 128x128 (QKV): 3-term f32 accumulate, SINGLE fp16 output.
// ---------------------------------------------------------------------------
#define PITCH 40
#define GEMM_BUF_BYTES (4 * 128 * PITCH * 2)
#define GEMM_SMEM_BYTES (2 * GEMM_BUF_BYTES)

__global__ __launch_bounds__(256, 2)
void gemm_qkv(const __half* __restrict__ Ah, const __half* __restrict__ Al,
              const __half* __restrict__ Bh, const __half* __restrict__ Bl,
              __half* __restrict__ Ch) {
    const int N = 768;
    extern __shared__ __align__(16) char smem_raw[];
    const uint32_t uS = smem_u32(smem_raw);

    const int tid = threadIdx.x;
    const int lane = tid & 31;
    const int wid = tid >> 5;
    const int wm = wid & 1;
    const int wn = wid >> 1;
    const int bx = blockIdx.x;
    const int by = blockIdx.y;

    const __half* Agh = Ah + (size_t)by * 128 * 256;
    const __half* Agl = Al + (size_t)by * 128 * 256;
    const __half* Bgh = Bh + (size_t)bx * 128 * 256;
    const __half* Bgl = Bl + (size_t)bx * 128 * 256;

    float acc[4][4][4];
#pragma unroll
    for (int mt = 0; mt < 4; ++mt)
#pragma unroll
        for (int nt = 0; nt < 4; ++nt)
#pragma unroll
            for (int i = 0; i < 4; ++i) acc[mt][nt][i] = 0.0f;

    const uint32_t aoff =
        (uint32_t)((wm * 64 + (lane & 15)) * PITCH + ((lane & 16) ? 8 : 0)) * 2;
    const uint32_t boff =
        (uint32_t)((wn * 32 + (lane & 7) + ((lane & 16) ? 8 : 0)) * PITCH +
                   ((lane & 8) ? 8 : 0)) * 2;

    const int row0 = tid >> 2;
    const int c8 = (tid & 3) * 8;

#pragma unroll
    for (int i = 0; i < 2; ++i) {
        int row = row0 + i * 64;
        size_t g = (size_t)row * 256 + c8;
        uint32_t so = (uint32_t)(row * PITCH + c8) * 2;
        CP_ASYNC16(uS + so, Agh + g);
        CP_ASYNC16(uS + 10240 + so, Agl + g);
        CP_ASYNC16(uS + 20480 + so, Bgh + g);
        CP_ASYNC16(uS + 30720 + so, Bgl + g);
    }
    CP_COMMIT();
    CP_WAIT0();
    __syncthreads();

#pragma unroll 1
    for (int kb = 0; kb < 8; ++kb) {
        const int p = kb & 1;
        const uint32_t bufb = uS + (uint32_t)p * GEMM_BUF_BYTES;

        if (kb < 7) {
            const uint32_t nb = uS + (uint32_t)(1 - p) * GEMM_BUF_BYTES;
#pragma unroll
            for (int i = 0; i < 2; ++i) {
                int row = row0 + i * 64;
                size_t g = (size_t)row * 256 + (kb + 1) * 32 + c8;
                uint32_t so = (uint32_t)(row * PITCH + c8) * 2;
                CP_ASYNC16(nb + so, Agh + g);
                CP_ASYNC16(nb + 10240 + so, Agl + g);
                CP_ASYNC16(nb + 20480 + so, Bgh + g);
                CP_ASYNC16(nb + 30720 + so, Bgl + g);
            }
            CP_COMMIT();
        }

        const uint32_t uAh = bufb, uAl = bufb + 10240;
        const uint32_t uBh = bufb + 20480, uBl = bufb + 30720;

#pragma unroll
        for (int kk = 0; kk < 2; ++kk) {
            const uint32_t kof = (uint32_t)(kk * 16) * 2;
            uint32_t bhf[2][4], blf[2][4];
#pragma unroll
            for (int ntp = 0; ntp < 2; ++ntp) {
                uint32_t ba = boff + (uint32_t)(ntp * 16 * PITCH) * 2 + kof;
                LDSM_X4(bhf[ntp][0], bhf[ntp][1], bhf[ntp][2], bhf[ntp][3], uBh + ba);
                LDSM_X4(blf[ntp][0], blf[ntp][1], blf[ntp][2], blf[ntp][3], uBl + ba);
            }
#pragma unroll
            for (int mt = 0; mt < 4; ++mt) {
                uint32_t aa = aoff + (uint32_t)(mt * 16 * PITCH) * 2 + kof;
                uint32_t ah0, ah1, ah2, ah3, al0, al1, al2, al3;
                LDSM_X4(ah0, ah1, ah2, ah3, uAh + aa);
                LDSM_X4(al0, al1, al2, al3, uAl + aa);
#pragma unroll
                for (int nt = 0; nt < 4; ++nt) {
                    const int ntp = nt >> 1;
                    const int hb = (nt & 1) * 2;
                    MMA_FP16(acc[mt][nt], ah0, ah1, ah2, ah3,
                             bhf[ntp][hb], bhf[ntp][hb + 1]);
                    MMA_FP16(acc[mt][nt], ah0, ah1, ah2, ah3,
                             blf[ntp][hb], blf[ntp][hb + 1]);
                    MMA_FP16(acc[mt][nt], al0, al1, al2, al3,
                             bhf[ntp][hb], bhf[ntp][hb + 1]);
                }
            }
        }

        if (kb < 7) CP_WAIT0();
        __syncthreads();
    }

    const int gid = lane >> 2;
    const int tig = lane & 3;
#pragma unroll
    for (int mt = 0; mt < 4; ++mt) {
        int row = by * 128 + wm * 64 + mt * 16 + gid;
#pragma unroll
        for (int nt = 0; nt < 4; ++nt) {
            int col = bx * 128 + wn * 32 + nt * 8 + 2 * tig;
            *reinterpret_cast<uint32_t*>(Ch + (size_t)row * N + col) =
                pack_h2(acc[mt][nt][0], acc[mt][nt][1]);
            *reinterpret_cast<uint32_t*>(Ch + (size_t)(row + 8) * N + col) =
                pack_h2(acc[mt][nt][2], acc[mt][nt][3]);
        }
    }
}

// ---------------------------------------------------------------------------
// proj GEMM: 64x128 tiles, fp16 3-term, f32 + bias output.
// ---------------------------------------------------------------------------
#define P64_BUF_BYTES (2 * 64 * PITCH * 2 + 2 * 128 * PITCH * 2)   // 30720
#define P64_SMEM_BYTES (2 * P64_BUF_BYTES)

__global__ __launch_bounds__(256, 2)
void gemm_proj(const __half* __restrict__ Ah, const __half* __restrict__ Al,
               const __half* __restrict__ Bh, const __half* __restrict__ Bl,
               const float* __restrict__ bias, float* __restrict__ C) {
    const int N = 256;
    extern __shared__ __align__(16) char smem_raw[];
    const uint32_t uS = smem_u32(smem_raw);

    const int tid = threadIdx.x;
    const int lane = tid & 31;
    const int wid = tid >> 5;
    const int wm = wid & 1;
    const int wn = wid >> 1;
    const int bx = blockIdx.x;
    const int by = blockIdx.y;

    const __half* Agh = Ah + (size_t)by * 64 * 256;
    const __half* Agl = Al + (size_t)by * 64 * 256;
    const __half* Bgh = Bh + (size_t)bx * 128 * 256;
    const __half* Bgl = Bl + (size_t)bx * 128 * 256;

    float acc[2][4][4];
#pragma unroll
    for (int mt = 0; mt < 2; ++mt)
#pragma unroll
        for (int nt = 0; nt < 4; ++nt)
#pragma unroll
            for (int i = 0; i < 4; ++i) acc[mt][nt][i] = 0.0f;

    const uint32_t aoff =
        (uint32_t)((wm * 32 + (lane & 15)) * PITCH + ((lane & 16) ? 8 : 0)) * 2;
    const uint32_t boff =
        (uint32_t)((wn * 32 + (lane & 7) + ((lane & 16) ? 8 : 0)) * PITCH +
                   ((lane & 8) ? 8 : 0)) * 2;

    const int arow = tid >> 2;
    const int ac8 = (tid & 3) * 8;
    const uint32_t aso = (uint32_t)(arow * PITCH + ac8) * 2;
    const int brow0 = tid >> 2;

#pragma unroll 1
    for (int kb = -1; kb < 8; ++kb) {
        if (kb < 7) {
            const uint32_t nb = uS + (uint32_t)((kb + 1) & 1) * P64_BUF_BYTES;
            int kof = (kb + 1) * 32;
            {
                size_t g = (size_t)arow * 256 + kof + ac8;
                CP_ASYNC16(nb + aso, Agh + g);
                CP_ASYNC16(nb + 5120 + aso, Agl + g);
            }
#pragma unroll
            for (int i = 0; i < 2; ++i) {
                int row = brow0 + i * 64;
                size_t g = (size_t)row * 256 + kof + ac8;
                uint32_t so = (uint32_t)(row * PITCH + ac8) * 2;
                CP_ASYNC16(nb + 10240 + so, Bgh + g);
                CP_ASYNC16(nb + 20480 + so, Bgl + g);
            }
            CP_COMMIT();
        }
        if (kb < 0) { CP_WAIT0(); __syncthreads(); continue; }

        const uint32_t bufb = uS + (uint32_t)(kb & 1) * P64_BUF_BYTES;
        const uint32_t uAh = bufb, uAl = bufb + 5120;
        const uint32_t uBh = bufb + 10240, uBl = bufb + 20480;

#pragma unroll
        for (int kk = 0; kk < 2; ++kk) {
            const uint32_t kof = (uint32_t)(kk * 16) * 2;
            uint32_t bhf[2][4], blf[2][4];
#pragma unroll
            for (int ntp = 0; ntp < 2; ++ntp) {
                uint32_t ba = boff + (uint32_t)(ntp * 16 * PITCH) * 2 + kof;
                LDSM_X4(bhf[ntp][0], bhf[ntp][1], bhf[ntp][2], bhf[ntp][3], uBh + ba);
                LDSM_X4(blf[ntp][0], blf[ntp][1], blf[ntp][2], blf[ntp][3], uBl + ba);
            }
#pragma unroll
            for (int mt = 0; mt < 2; ++mt) {
                uint32_t aa = aoff + (uint32_t)(mt * 16 * PITCH) * 2 + kof;
                uint32_t ah0, ah1, ah2, ah3, al0, al1, al2, al3;
                LDSM_X4(ah0, ah1, ah2, ah3, uAh + aa);
                LDSM_X4(al0, al1, al2, al3, uAl + aa);
#pragma unroll
                for (int nt = 0; nt < 4; ++nt) {
                    const int ntp = nt >> 1;
                    const int hb = (nt & 1) * 2;
                    MMA_FP16(acc[mt][nt], ah0, ah1, ah2, ah3,
                             bhf[ntp][hb], bhf[ntp][hb + 1]);
                    MMA_FP16(acc[mt][nt], ah0, ah1, ah2, ah3,
                             blf[ntp][hb], blf[ntp][hb + 1]);
                    MMA_FP16(acc[mt][nt], al0, al1, al2, al3,
                             bhf[ntp][hb], bhf[ntp][hb + 1]);
                }
            }
        }

        if (kb < 7) CP_WAIT0();
        __syncthreads();
    }

    const int gid = lane >> 2;
    const int tig = lane & 3;
#pragma unroll
    for (int mt = 0; mt < 2; ++mt) {
        int row = by * 64 + wm * 32 + mt * 16 + gid;
#pragma unroll
        for (int nt = 0; nt < 4; ++nt) {
            int col = bx * 128 + wn * 32 + nt * 8 + 2 * tig;
            float2 bb = *reinterpret_cast<const float2*>(bias + col);
            float2 v0 = make_float2(acc[mt][nt][0] + bb.x, acc[mt][nt][1] + bb.y);
            float2 v1 = make_float2(acc[mt][nt][2] + bb.x, acc[mt][nt][3] + bb.y);
            *reinterpret_cast<float2*>(C + (size_t)row * N + col) = v0;
            *reinterpret_cast<float2*>(C + (size_t)(row + 8) * N + col) = v1;
        }
    }
}

// ---------------------------------------------------------------------------
// pure-fp16 flash attention: S = QhKh, P single fp16, O = PhVh.
// 32 MMAs/warp/kt; only qkv_hi staged (K/V traffic halved).
// ---------------------------------------------------------------------------
#define ATTN_Q_BYTES (128 * PITCH * 2)            // 10240
#define ATTN_BUF_BYTES (2 * 64 * PITCH * 2)       // 10240 per buffer (Kh|Vh)
#define ATTN_SMEM_BYTES (ATTN_Q_BYTES + 2 * ATTN_BUF_BYTES)   // 30720

__global__ __launch_bounds__(256, 2)
void attn_mma(const __half* __restrict__ qkvh,
              const float4* __restrict__ bias4,
              __half* __restrict__ outh,
              __half* __restrict__ outl) {
    extern __shared__ __align__(16) char smem_raw[];
    __half* Qh = reinterpret_cast<__half*>(smem_raw);
    const uint32_t uQh = smem_u32(Qh);
    const uint32_t uKV = uQh + ATTN_Q_BYTES;

    const int tid = threadIdx.x;
    const int lane = tid & 31;
    const int w = tid >> 5;
    const int gid = lane >> 2;
    const int tig = lane & 3;
    const int qc = blockIdx.x;
    const int h  = blockIdx.y;
    const int b  = blockIdx.z;

    const float scale = 0.17677669529663687f;   // 1/sqrt(32)
    const int qrow0 = b * N_ + qc * 128;

    const int krow = tid >> 2;
    const int kc8 = (tid & 3) * 8;
    const uint32_t kso = (uint32_t)(krow * PITCH + kc8) * 2;

    // prologue: stage kt=0 (Kh|Vh) into buffer 0
    {
        size_t g = (size_t)(b * N_ + krow) * 768 + 256 + h * HD_ + kc8;
        CP_ASYNC16(uKV + kso, qkvh + g);
        CP_ASYNC16(uKV + 5120 + kso, qkvh + g + 256);
        CP_COMMIT();
    }

    // stage Qh
    {
        int row = tid >> 1;
        int c8 = (tid & 1) * 16;
        size_t g = (size_t)(qrow0 + row) * 768 + h * HD_ + c8;
        int so = row * PITCH + c8;
        *reinterpret_cast<uint4*>(&Qh[so]) =
            *reinterpret_cast<const uint4*>(qkvh + g);
        *reinterpret_cast<uint4*>(&Qh[so + 8]) =
            *reinterpret_cast<const uint4*>(qkvh + g + 8);
    }
    CP_WAIT0();
    __syncthreads();

    const uint32_t aoff =
        (uint32_t)((w * 16 + (lane & 15)) * PITCH + ((lane & 16) ? 8 : 0)) * 2;
    const uint32_t koff =
        (uint32_t)(((lane & 7) + ((lane & 16) ? 8 : 0)) * PITCH +
                   ((lane & 8) ? 8 : 0)) * 2;
    const uint32_t voff =
        (uint32_t)((lane & 15) * PITCH + ((lane & 16) ? 8 : 0)) * 2;

    // hoisted Qh fragments
    uint32_t qh[2][4];
#pragma unroll
    for (int kk = 0; kk < 2; ++kk) {
        const uint32_t kof = (uint32_t)(kk * 16) * 2;
        LDSM_X4(qh[kk][0], qh[kk][1], qh[kk][2], qh[kk][3], uQh + aoff + kof);
    }

    float l0 = 0.0f, l1 = 0.0f;
    float oacc[4][4];
#pragma unroll
    for (int nt = 0; nt < 4; ++nt)
#pragma unroll
        for (int i = 0; i < 4; ++i) oacc[nt][i] = 0.0f;

    const float4* bias_tb =
        bias4 + ((size_t)((b * 8 + qc) * 16)) * 2048 + (w * 8) * 32 + lane;

#pragma unroll 1
    for (int kt = 0; kt < 16; ++kt) {
        const int p = kt & 1;
        const uint32_t bufb = uKV + (uint32_t)p * ATTN_BUF_BYTES;

        if (kt < 15) {
            const uint32_t nb = uKV + (uint32_t)(1 - p) * ATTN_BUF_BYTES;
            size_t g = (size_t)(b * N_ + (kt + 1) * 64 + krow) * 768 + 256 +
                       h * HD_ + kc8;
            CP_ASYNC16(nb + kso, qkvh + g);
            CP_ASYNC16(nb + 5120 + kso, qkvh + g + 256);
            CP_COMMIT();
        }

        const uint32_t uKh = bufb;
        const uint32_t uVh = bufb + 5120;

        // ---- S = Qh*Kh ----
        float sacc[8][4];
#pragma unroll
        for (int nt = 0; nt < 8; ++nt)
#pragma unroll
            for (int i = 0; i < 4; ++i) sacc[nt][i] = 0.0f;

#pragma unroll
        for (int kk = 0; kk < 2; ++kk) {
            const uint32_t kof = (uint32_t)(kk * 16) * 2;
            uint32_t bh[4][4];
#pragma unroll
            for (int ntp = 0; ntp < 4; ++ntp) {
                uint32_t ba = koff + (uint32_t)(ntp * 16 * PITCH) * 2 + kof;
                LDSM_X4(bh[ntp][0], bh[ntp][1], bh[ntp][2], bh[ntp][3], uKh + ba);
            }
#pragma unroll
            for (int nt = 0; nt < 8; ++nt) {
                const int ntp = nt >> 1;
                const int hb = (nt & 1) * 2;
                MMA_FP16(sacc[nt], qh[kk][0], qh[kk][1], qh[kk][2], qh[kk][3],
                         bh[ntp][hb], bh[ntp][hb + 1]);
            }
        }

        // ---- scale + bias + exp ----
        const float4* bt = bias_tb + kt * 2048;
#pragma unroll
        for (int nt = 0; nt < 8; ++nt) {
            float4 bb = bt[nt * 32];
            float p0 = __expf(fmaf(sacc[nt][0], scale, bb.x));
            float p1 = __expf(fmaf(sacc[nt][1], scale, bb.y));
            float p2 = __expf(fmaf(sacc[nt][2], scale, bb.z));
            float p3 = __expf(fmaf(sacc[nt][3], scale, bb.w));
            sacc[nt][0] = p0; sacc[nt][1] = p1;
            sacc[nt][2] = p2; sacc[nt][3] = p3;
            l0 += p0 + p1;
            l1 += p2 + p3;
        }

        // ---- O += Ph*Vh ----
#pragma unroll
        for (int ks = 0; ks < 4; ++ks) {
            uint32_t pah[4];
            pah[0] = pack_h2(sacc[2 * ks][0],     sacc[2 * ks][1]);
            pah[1] = pack_h2(sacc[2 * ks][2],     sacc[2 * ks][3]);
            pah[2] = pack_h2(sacc[2 * ks + 1][0], sacc[2 * ks + 1][1]);
            pah[3] = pack_h2(sacc[2 * ks + 1][2], sacc[2 * ks + 1][3]);

            uint32_t vh[2][4];
#pragma unroll
            for (int ntp = 0; ntp < 2; ++ntp) {
                uint32_t va = voff + (uint32_t)(ks * 16 * PITCH + ntp * 16) * 2;
                LDSM_X4T(vh[ntp][0], vh[ntp][1], vh[ntp][2], vh[ntp][3], uVh + va);
            }
#pragma unroll
            for (int nt = 0; nt < 4; ++nt) {
                const int ntp = nt >> 1;
                const int hb = (nt & 1) * 2;
                MMA_FP16(oacc[nt], pah[0], pah[1], pah[2], pah[3],
                         vh[ntp][hb], vh[ntp][hb + 1]);
            }
        }

        if (kt < 15) CP_WAIT0();
        __syncthreads();
    }

    // ---- one-time l reduction over the 4-lane row group ----
    l0 += __shfl_xor_sync(0xffffffffu, l0, 1);
    l0 += __shfl_xor_sync(0xffffffffu, l0, 2);
    l1 += __shfl_xor_sync(0xffffffffu, l1, 1);
    l1 += __shfl_xor_sync(0xffffffffu, l1, 2);

    // ---- epilogue (split output for proj 3-term) ----
    const float inv0 = 1.0f / l0;
    const float inv1 = 1.0f / l1;
    const int row0 = qrow0 + w * 16 + gid;
#pragma unroll
    for (int nt = 0; nt < 4; ++nt) {
        int col = h * HD_ + nt * 8 + 2 * tig;
        uint32_t hv, lv;
        split2h(oacc[nt][0] * inv0, oacc[nt][1] * inv0, hv, lv);
        *reinterpret_cast<uint32_t*>(outh + (size_t)row0 * C_ + col) = hv;
        *reinterpret_cast<uint32_t*>(outl + (size_t)row0 * C_ + col) = lv;
        split2h(oacc[nt][2] * inv1, oacc[nt][3] * inv1, hv, lv);
        *reinterpret_cast<uint32_t*>(outh + (size_t)(row0 + 8) * C_ + col) = hv;
        *reinterpret_cast<uint32_t*>(outl + (size_t)(row0 + 8) * C_ + col) = lv;
    }
}

// ---------------------------------------------------------------------------
// launch
// ---------------------------------------------------------------------------
extern "C" void kernel_launch(void* const* d_in, const int* in_sizes, int n_in,
                              void* d_out, int out_size) {
    const float* x     = (const float*)d_in[0];
    const float* elev  = (const float*)d_in[1];
    const float* uw    = (const float*)d_in[2];
    const float* vw    = (const float*)d_in[3];
    const float* wqkv  = (const float*)d_in[4];
    const float* wproj = (const float*)d_in[5];
    const float* bproj = (const float*)d_in[6];
    const float* alpha = (const float*)d_in[7];
    const float* beta  = (const float*)d_in[8];
    float* out = (float*)d_out;

    float *ws_p;
    float4* bias4_p;
    __half *xh, *xl, *wqkvh, *wqkvl, *wprojh, *wprojl;
    __half *qkvh, *attnh, *attnl;
    cudaGetSymbolAddress((void**)&ws_p, g_ws);
    cudaGetSymbolAddress((void**)&bias4_p, g_bias4);
    cudaGetSymbolAddress((void**)&xh, g_xh);
    cudaGetSymbolAddress((void**)&xl, g_xl);
    cudaGetSymbolAddress((void**)&wqkvh, g_wqkvh);
    cudaGetSymbolAddress((void**)&wqkvl, g_wqkvl);
    cudaGetSymbolAddress((void**)&wprojh, g_wprojh);
    cudaGetSymbolAddress((void**)&wprojl, g_wprojl);
    cudaGetSymbolAddress((void**)&qkvh, g_qkvh);
    cudaGetSymbolAddress((void**)&attnh, g_attnh);
    cudaGetSymbolAddress((void**)&attnl, g_attnl);

    cudaFuncSetAttribute(gemm_qkv,
                         cudaFuncAttributeMaxDynamicSharedMemorySize,
                         GEMM_SMEM_BYTES);
    cudaFuncSetAttribute(gemm_proj,
                         cudaFuncAttributeMaxDynamicSharedMemorySize,
                         P64_SMEM_BYTES);
    cudaFuncSetAttribute(attn_mma,
                         cudaFuncAttributeMaxDynamicSharedMemorySize,
                         ATTN_SMEM_BYTES);

    // 1) merged converts + wind strength (fused)
    convert_all<<<(N4_TOTAL + B_ * N_ + 255) / 256, 256>>>(
        x, wqkv, wproj, uw, vw, xh, xl, wqkvh, wqkvl, wprojh, wprojl, ws_p);

    // 2) fragment-ordered bias
    bias_perm_kernel<<<B_ * N_ * N_ / 4 / 256, 256>>>(elev, ws_p, alpha, beta,
                                                      bias4_p);

    // 3) qkv = x @ w_qkv^T (3-term compute, single fp16 output)
    gemm_qkv<<<dim3(6, 64), 256, GEMM_SMEM_BYTES>>>(
        xh, xl, wqkvh, wqkvl, qkvh);

    // 4) pure-fp16 flash attention (split output)
    attn_mma<<<dim3(8, NH_, B_), 256, ATTN_SMEM_BYTES>>>(
        qkvh, bias4_p, attnh, attnl);

    // 5) out = attn @ w_proj^T + b_proj
    gemm_proj<<<dim3(2, 128), 256, P64_SMEM_BYTES>>>(
        attnh, attnl, wprojh, wprojl, bproj, out);
}

// round 15
// speedup vs baseline: 1.6675x; 1.1599x over previous
#include <cuda_runtime.h>
#include <cuda_fp16.h>
#include <math.h>
#include <cstdint>

// ---------------------------------------------------------------------------
// PhysicsGuidedAttentionCorrected
// B=8, N=1024, C=256, NUM_HEADS=8, hd=32
// R15: QKV GEMM single-term fp16 (output is fp16 anyway; 32 MMAs/tile,
//      staging halved, x_lo/wqkv_lo eliminated). Attention pure-fp16 (R14).
//      proj stays 3-term fp16-split -> f32.
// ---------------------------------------------------------------------------

#define B_ 8
#define N_ 1024
#define C_ 256
#define NH_ 8
#define HD_ 32

// scratch (device globals; no allocations allowed)
__device__ float g_ws[B_ * N_];
__device__ float4 g_bias4[B_ * N_ * N_ / 4];       // fragment-ordered bias
__device__ __half g_xh[B_ * N_ * C_];
__device__ __half g_wqkvh[3 * C_ * C_];
__device__ __half g_wprojh[C_ * C_];
__device__ __half g_wprojl[C_ * C_];
__device__ __half g_qkvh[B_ * N_ * 3 * C_];
__device__ __half g_attnh[B_ * N_ * C_];
__device__ __half g_attnl[B_ * N_ * C_];

// ---------------------------------------------------------------------------
// helpers
// ---------------------------------------------------------------------------
__device__ __forceinline__ uint32_t smem_u32(const void* p) {
    uint32_t a;
    asm("{ .reg .u64 t; cvta.to.shared.u64 t, %1; cvt.u32.u64 %0, t; }"
        : "=r"(a) : "l"(p));
    return a;
}

#define LDSM_X4(r0, r1, r2, r3, addr)                                        \
    asm volatile("ldmatrix.sync.aligned.m8n8.x4.shared.b16 {%0,%1,%2,%3}, [%4];" \
                 : "=r"(r0), "=r"(r1), "=r"(r2), "=r"(r3) : "r"(addr))

#define LDSM_X4T(r0, r1, r2, r3, addr)                                       \
    asm volatile("ldmatrix.sync.aligned.m8n8.x4.trans.shared.b16 {%0,%1,%2,%3}, [%4];" \
                 : "=r"(r0), "=r"(r1), "=r"(r2), "=r"(r3) : "r"(addr))

#define MMA_FP16(d, a0, a1, a2, a3, b0, b1)                                  \
    asm volatile("mma.sync.aligned.m16n8k16.row.col.f32.f16.f16.f32 "        \
                 "{%0,%1,%2,%3}, {%4,%5,%6,%7}, {%8,%9}, {%0,%1,%2,%3};"     \
                 : "+f"((d)[0]), "+f"((d)[1]), "+f"((d)[2]), "+f"((d)[3])    \
                 : "r"(a0), "r"(a1), "r"(a2), "r"(a3), "r"(b0), "r"(b1))

#define CP_ASYNC16(saddr, gptr)                                              \
    asm volatile("cp.async.cg.shared.global [%0], [%1], 16;"                 \
                 :: "r"(saddr), "l"(gptr))
#define CP_COMMIT() asm volatile("cp.async.commit_group;" ::: "memory")
#define CP_WAIT0()  asm volatile("cp.async.wait_group 0;" ::: "memory")

// fp16 hi/lo split
__device__ __forceinline__ void split2h(float x, float y,
                                        uint32_t& hi, uint32_t& lo) {
    uint32_t h;
    asm("cvt.rn.f16x2.f32 %0, %1, %2;" : "=r"(h) : "f"(y), "f"(x));
    float fx, fy;
    asm("{\n\t.reg .f16 a,b;\n\tmov.b32 {a,b}, %2;\n\t"
        "cvt.f32.f16 %0, a;\n\tcvt.f32.f16 %1, b;\n\t}"
        : "=f"(fx), "=f"(fy) : "r"(h));
    uint32_t l;
    asm("cvt.rn.f16x2.f32 %0, %1, %2;" : "=r"(l) : "f"(y - fy), "f"(x - fx));
    hi = h; lo = l;
}
__device__ __forceinline__ uint32_t pack_h2(float x, float y) {
    uint32_t h;
    asm("cvt.rn.f16x2.f32 %0, %1, %2;" : "=r"(h) : "f"(y), "f"(x));
    return h;
}

// ---------------------------------------------------------------------------
// bias precompute in MMA-fragment order (R8/R10 layout).
// ---------------------------------------------------------------------------
__device__ __forceinline__ float bias_val(float ei, float wi, float ej,
                                          float wj, float alpha, float beta) {
    float ed = fmaxf((ej - ei) * 1e-3f, 0.0f);
    float z = (wi + wj) * 0.5f - 5.0f;
    float wf = 1.0f / (1.0f + __expf(-z));
    float bia = -alpha * ed * (1.0f - beta * wf);
    return fminf(fmaxf(bia, -10.0f), 0.0f);
}

__global__ __launch_bounds__(256)
void bias_perm_kernel(const float* __restrict__ elev, const float* __restrict__ ws,
                      const float* __restrict__ alpha_p,
                      const float* __restrict__ beta_p,
                      float4* __restrict__ bias4) {
    const int t = blockIdx.x * blockDim.x + threadIdx.x;
    const int lane = t & 31;
    const int nt = (t >> 5) & 7;
    const int w  = (t >> 8) & 7;
    const int kt = (t >> 11) & 15;
    const int qt = (t >> 15) & 7;
    const int b  = t >> 18;
    const float alpha = *alpha_p;
    const float beta = *beta_p;

    const int i0 = qt * 128 + w * 16 + (lane >> 2);
    const int j0 = kt * 64 + nt * 8 + 2 * (lane & 3);
    const float* e = elev + b * 1024;
    const float* wsb = ws + b * 1024;
    float ei0 = e[i0], ei1 = e[i0 + 8];
    float wi0 = wsb[i0], wi1 = wsb[i0 + 8];
    float ej0 = e[j0], ej1 = e[j0 + 1];
    float wj0 = wsb[j0], wj1 = wsb[j0 + 1];

    float4 o;
    o.x = bias_val(ei0, wi0, ej0, wj0, alpha, beta);
    o.y = bias_val(ei0, wi0, ej1, wj1, alpha, beta);
    o.z = bias_val(ei1, wi1, ej0, wj0, alpha, beta);
    o.w = bias_val(ei1, wi1, ej1, wj1, alpha, beta);
    bias4[t] = o;
}

// ---------------------------------------------------------------------------
// merged converter: x -> fp16 hi only; wqkv -> fp16 hi only;
// wproj -> fp16 hi/lo; + fused wind strength.
// ---------------------------------------------------------------------------
#define N4_X (B_ * N_ * C_ / 4)
#define N4_WQKV (3 * C_ * C_ / 4)
#define N4_WPROJ (C_ * C_ / 4)
#define N4_TOTAL (N4_X + N4_WQKV + N4_WPROJ)

__global__ void convert_all(const float* __restrict__ x,
                            const float* __restrict__ wqkv,
                            const float* __restrict__ wproj,
                            const float* __restrict__ uwind,
                            const float* __restrict__ vwind,
                            __half* __restrict__ xh,
                            __half* __restrict__ wqh,
                            __half* __restrict__ wph, __half* __restrict__ wpl,
                            float* __restrict__ ws) {
    int i = blockIdx.x * blockDim.x + threadIdx.x;
    if (i >= N4_TOTAL) {
        int t = i - N4_TOTAL;
        if (t >= B_ * N_) return;
        int b = t >> 10;
        int n = t & 1023;
        int r = n >> 5;
        int c = n & 31;
        const float* ub = uwind + b * 4096;
        const float* vb = vwind + b * 4096;
        float s = 0.0f;
#pragma unroll
        for (int dr = 0; dr < 2; ++dr)
#pragma unroll
            for (int dc = 0; dc < 2; ++dc) {
                int idx = (2 * r + dr) * 64 + (2 * c + dc);
                float uu = ub[idx], vv = vb[idx];
                s += sqrtf(uu * uu + vv * vv + 1e-8f);
            }
        ws[t] = s * 0.25f;
        return;
    }
    if (i < N4_X + N4_WQKV) {
        const float* in = (i < N4_X) ? x : wqkv;
        __half* hi = (i < N4_X) ? xh : wqh;
        int off = (i < N4_X) ? i : (i - N4_X);
        float4 v = reinterpret_cast<const float4*>(in)[off];
        *reinterpret_cast<uint2*>(hi + 4 * off) =
            make_uint2(pack_h2(v.x, v.y), pack_h2(v.z, v.w));
    } else {
        int off = i - N4_X - N4_WQKV;
        float4 v = reinterpret_cast<const float4*>(wproj)[off];
        uint32_t h01, l01, h23, l23;
        split2h(v.x, v.y, h01, l01);
        split2h(v.z, v.w, h23, l23);
        *reinterpret_cast<uint2*>(wph + 4 * off) = make_uint2(h01, h23);
        *reinterpret_cast<uint2*>(wpl + 4 * off) = make_uint2(l01, l23);
    }
}

// ---------------------------------------------------------------------------
// single-term fp16 GEMM 128x128 (QKV): C = Ah*Bh^T, fp16 output.
// ---------------------------------------------------------------------------
#define PITCH 40
#define QG_BUF_BYTES (2 * 128 * PITCH * 2)   // 20480 per buffer (Ah|Bh)
#define QG_SMEM_BYTES (2 * QG_BUF_BYTES)     // 40960

__global__ __launch_bounds__(256, 2)
void gemm_qkv(const __half* __restrict__ Ah, const __half* __restrict__ Bh,
              __half* __restrict__ Ch) {
    const int N = 768;
    extern __shared__ __align__(16) char smem_raw[];
    const uint32_t uS = smem_u32(smem_raw);

    const int tid = threadIdx.x;
    const int lane = tid & 31;
    const int wid = tid >> 5;
    const int wm = wid & 1;
    const int wn = wid >> 1;
    const int bx = blockIdx.x;
    const int by = blockIdx.y;

    const __half* Agh = Ah + (size_t)by * 128 * 256;
    const __half* Bgh = Bh + (size_t)bx * 128 * 256;

    float acc[4][4][4];
#pragma unroll
    for (int mt = 0; mt < 4; ++mt)
#pragma unroll
        for (int nt = 0; nt < 4; ++nt)
#pragma unroll
            for (int i = 0; i < 4; ++i) acc[mt][nt][i] = 0.0f;

    const uint32_t aoff =
        (uint32_t)((wm * 64 + (lane & 15)) * PITCH + ((lane & 16) ? 8 : 0)) * 2;
    const uint32_t boff =
        (uint32_t)((wn * 32 + (lane & 7) + ((lane & 16) ? 8 : 0)) * PITCH +
                   ((lane & 8) ? 8 : 0)) * 2;

    const int row0 = tid >> 2;
    const int c8 = (tid & 3) * 8;

#pragma unroll
    for (int i = 0; i < 2; ++i) {
        int row = row0 + i * 64;
        size_t g = (size_t)row * 256 + c8;
        uint32_t so = (uint32_t)(row * PITCH + c8) * 2;
        CP_ASYNC16(uS + so, Agh + g);
        CP_ASYNC16(uS + 10240 + so, Bgh + g);
    }
    CP_COMMIT();
    CP_WAIT0();
    __syncthreads();

#pragma unroll 1
    for (int kb = 0; kb < 8; ++kb) {
        const int p = kb & 1;
        const uint32_t bufb = uS + (uint32_t)p * QG_BUF_BYTES;

        if (kb < 7) {
            const uint32_t nb = uS + (uint32_t)(1 - p) * QG_BUF_BYTES;
#pragma unroll
            for (int i = 0; i < 2; ++i) {
                int row = row0 + i * 64;
                size_t g = (size_t)row * 256 + (kb + 1) * 32 + c8;
                uint32_t so = (uint32_t)(row * PITCH + c8) * 2;
                CP_ASYNC16(nb + so, Agh + g);
                CP_ASYNC16(nb + 10240 + so, Bgh + g);
            }
            CP_COMMIT();
        }

        const uint32_t uAh = bufb, uBh = bufb + 10240;

#pragma unroll
        for (int kk = 0; kk < 2; ++kk) {
            const uint32_t kof = (uint32_t)(kk * 16) * 2;
            uint32_t bhf[2][4];
#pragma unroll
            for (int ntp = 0; ntp < 2; ++ntp) {
                uint32_t ba = boff + (uint32_t)(ntp * 16 * PITCH) * 2 + kof;
                LDSM_X4(bhf[ntp][0], bhf[ntp][1], bhf[ntp][2], bhf[ntp][3], uBh + ba);
            }
#pragma unroll
            for (int mt = 0; mt < 4; ++mt) {
                uint32_t aa = aoff + (uint32_t)(mt * 16 * PITCH) * 2 + kof;
                uint32_t ah0, ah1, ah2, ah3;
                LDSM_X4(ah0, ah1, ah2, ah3, uAh + aa);
#pragma unroll
                for (int nt = 0; nt < 4; ++nt) {
                    const int ntp = nt >> 1;
                    const int hb = (nt & 1) * 2;
                    MMA_FP16(acc[mt][nt], ah0, ah1, ah2, ah3,
                             bhf[ntp][hb], bhf[ntp][hb + 1]);
                }
            }
        }

        if (kb < 7) CP_WAIT0();
        __syncthreads();
    }

    const int gid = lane >> 2;
    const int tig = lane & 3;
#pragma unroll
    for (int mt = 0; mt < 4; ++mt) {
        int row = by * 128 + wm * 64 + mt * 16 + gid;
#pragma unroll
        for (int nt = 0; nt < 4; ++nt) {
            int col = bx * 128 + wn * 32 + nt * 8 + 2 * tig;
            *reinterpret_cast<uint32_t*>(Ch + (size_t)row * N + col) =
                pack_h2(acc[mt][nt][0], acc[mt][nt][1]);
            *reinterpret_cast<uint32_t*>(Ch + (size_t)(row + 8) * N + col) =
                pack_h2(acc[mt][nt][2], acc[mt][nt][3]);
        }
    }
}

// ---------------------------------------------------------------------------
// proj GEMM: 64x128 tiles, fp16 3-term, f32 + bias output.
// ---------------------------------------------------------------------------
#define P64_BUF_BYTES (2 * 64 * PITCH * 2 + 2 * 128 * PITCH * 2)   // 30720
#define P64_SMEM_BYTES (2 * P64_BUF_BYTES)

__global__ __launch_bounds__(256, 2)
void gemm_proj(const __half* __restrict__ Ah, const __half* __restrict__ Al,
               const __half* __restrict__ Bh, const __half* __restrict__ Bl,
               const float* __restrict__ bias, float* __restrict__ C) {
    const int N = 256;
    extern __shared__ __align__(16) char smem_raw[];
    const uint32_t uS = smem_u32(smem_raw);

    const int tid = threadIdx.x;
    const int lane = tid & 31;
    const int wid = tid >> 5;
    const int wm = wid & 1;
    const int wn = wid >> 1;
    const int bx = blockIdx.x;
    const int by = blockIdx.y;

    const __half* Agh = Ah + (size_t)by * 64 * 256;
    const __half* Agl = Al + (size_t)by * 64 * 256;
    const __half* Bgh = Bh + (size_t)bx * 128 * 256;
    const __half* Bgl = Bl + (size_t)bx * 128 * 256;

    float acc[2][4][4];
#pragma unroll
    for (int mt = 0; mt < 2; ++mt)
#pragma unroll
        for (int nt = 0; nt < 4; ++nt)
#pragma unroll
            for (int i = 0; i < 4; ++i) acc[mt][nt][i] = 0.0f;

    const uint32_t aoff =
        (uint32_t)((wm * 32 + (lane & 15)) * PITCH + ((lane & 16) ? 8 : 0)) * 2;
    const uint32_t boff =
        (uint32_t)((wn * 32 + (lane & 7) + ((lane & 16) ? 8 : 0)) * PITCH +
                   ((lane & 8) ? 8 : 0)) * 2;

    const int arow = tid >> 2;
    const int ac8 = (tid & 3) * 8;
    const uint32_t aso = (uint32_t)(arow * PITCH + ac8) * 2;
    const int brow0 = tid >> 2;

#pragma unroll 1
    for (int kb = -1; kb < 8; ++kb) {
        if (kb < 7) {
            const uint32_t nb = uS + (uint32_t)((kb + 1) & 1) * P64_BUF_BYTES;
            int kof = (kb + 1) * 32;
            {
                size_t g = (size_t)arow * 256 + kof + ac8;
                CP_ASYNC16(nb + aso, Agh + g);
                CP_ASYNC16(nb + 5120 + aso, Agl + g);
            }
#pragma unroll
            for (int i = 0; i < 2; ++i) {
                int row = brow0 + i * 64;
                size_t g = (size_t)row * 256 + kof + ac8;
                uint32_t so = (uint32_t)(row * PITCH + ac8) * 2;
                CP_ASYNC16(nb + 10240 + so, Bgh + g);
                CP_ASYNC16(nb + 20480 + so, Bgl + g);
            }
            CP_COMMIT();
        }
        if (kb < 0) { CP_WAIT0(); __syncthreads(); continue; }

        const uint32_t bufb = uS + (uint32_t)(kb & 1) * P64_BUF_BYTES;
        const uint32_t uAh = bufb, uAl = bufb + 5120;
        const uint32_t uBh = bufb + 10240, uBl = bufb + 20480;

#pragma unroll
        for (int kk = 0; kk < 2; ++kk) {
            const uint32_t kof = (uint32_t)(kk * 16) * 2;
            uint32_t bhf[2][4], blf[2][4];
#pragma unroll
            for (int ntp = 0; ntp < 2; ++ntp) {
                uint32_t ba = boff + (uint32_t)(ntp * 16 * PITCH) * 2 + kof;
                LDSM_X4(bhf[ntp][0], bhf[ntp][1], bhf[ntp][2], bhf[ntp][3], uBh + ba);
                LDSM_X4(blf[ntp][0], blf[ntp][1], blf[ntp][2], blf[ntp][3], uBl + ba);
            }
#pragma unroll
            for (int mt = 0; mt < 2; ++mt) {
                uint32_t aa = aoff + (uint32_t)(mt * 16 * PITCH) * 2 + kof;
                uint32_t ah0, ah1, ah2, ah3, al0, al1, al2, al3;
                LDSM_X4(ah0, ah1, ah2, ah3, uAh + aa);
                LDSM_X4(al0, al1, al2, al3, uAl + aa);
#pragma unroll
                for (int nt = 0; nt < 4; ++nt) {
                    const int ntp = nt >> 1;
                    const int hb = (nt & 1) * 2;
                    MMA_FP16(acc[mt][nt], ah0, ah1, ah2, ah3,
                             bhf[ntp][hb], bhf[ntp][hb + 1]);
                    MMA_FP16(acc[mt][nt], ah0, ah1, ah2, ah3,
                             blf[ntp][hb], blf[ntp][hb + 1]);
                    MMA_FP16(acc[mt][nt], al0, al1, al2, al3,
                             bhf[ntp][hb], bhf[ntp][hb + 1]);
                }
            }
        }

        if (kb < 7) CP_WAIT0();
        __syncthreads();
    }

    const int gid = lane >> 2;
    const int tig = lane & 3;
#pragma unroll
    for (int mt = 0; mt < 2; ++mt) {
        int row = by * 64 + wm * 32 + mt * 16 + gid;
#pragma unroll
        for (int nt = 0; nt < 4; ++nt) {
            int col = bx * 128 + wn * 32 + nt * 8 + 2 * tig;
            float2 bb = *reinterpret_cast<const float2*>(bias + col);
            float2 v0 = make_float2(acc[mt][nt][0] + bb.x, acc[mt][nt][1] + bb.y);
            float2 v1 = make_float2(acc[mt][nt][2] + bb.x, acc[mt][nt][3] + bb.y);
            *reinterpret_cast<float2*>(C + (size_t)row * N + col) = v0;
            *reinterpret_cast<float2*>(C + (size_t)(row + 8) * N + col) = v1;
        }
    }
}

// ---------------------------------------------------------------------------
// pure-fp16 flash attention: S = QhKh, P single fp16, O = PhVh. (R14, proven)
// ---------------------------------------------------------------------------
#define ATTN_Q_BYTES (128 * PITCH * 2)            // 10240
#define ATTN_BUF_BYTES (2 * 64 * PITCH * 2)       // 10240 per buffer (Kh|Vh)
#define ATTN_SMEM_BYTES (ATTN_Q_BYTES + 2 * ATTN_BUF_BYTES)   // 30720

__global__ __launch_bounds__(256, 2)
void attn_mma(const __half* __restrict__ qkvh,
              const float4* __restrict__ bias4,
              __half* __restrict__ outh,
              __half* __restrict__ outl) {
    extern __shared__ __align__(16) char smem_raw[];
    __half* Qh = reinterpret_cast<__half*>(smem_raw);
    const uint32_t uQh = smem_u32(Qh);
    const uint32_t uKV = uQh + ATTN_Q_BYTES;

    const int tid = threadIdx.x;
    const int lane = tid & 31;
    const int w = tid >> 5;
    const int gid = lane >> 2;
    const int tig = lane & 3;
    const int qc = blockIdx.x;
    const int h  = blockIdx.y;
    const int b  = blockIdx.z;

    const float scale = 0.17677669529663687f;   // 1/sqrt(32)
    const int qrow0 = b * N_ + qc * 128;

    const int krow = tid >> 2;
    const int kc8 = (tid & 3) * 8;
    const uint32_t kso = (uint32_t)(krow * PITCH + kc8) * 2;

    // prologue: stage kt=0 (Kh|Vh) into buffer 0
    {
        size_t g = (size_t)(b * N_ + krow) * 768 + 256 + h * HD_ + kc8;
        CP_ASYNC16(uKV + kso, qkvh + g);
        CP_ASYNC16(uKV + 5120 + kso, qkvh + g + 256);
        CP_COMMIT();
    }

    // stage Qh
    {
        int row = tid >> 1;
        int c8 = (tid & 1) * 16;
        size_t g = (size_t)(qrow0 + row) * 768 + h * HD_ + c8;
        int so = row * PITCH + c8;
        *reinterpret_cast<uint4*>(&Qh[so]) =
            *reinterpret_cast<const uint4*>(qkvh + g);
        *reinterpret_cast<uint4*>(&Qh[so + 8]) =
            *reinterpret_cast<const uint4*>(qkvh + g + 8);
    }
    CP_WAIT0();
    __syncthreads();

    const uint32_t aoff =
        (uint32_t)((w * 16 + (lane & 15)) * PITCH + ((lane & 16) ? 8 : 0)) * 2;
    const uint32_t koff =
        (uint32_t)(((lane & 7) + ((lane & 16) ? 8 : 0)) * PITCH +
                   ((lane & 8) ? 8 : 0)) * 2;
    const uint32_t voff =
        (uint32_t)((lane & 15) * PITCH + ((lane & 16) ? 8 : 0)) * 2;

    // hoisted Qh fragments
    uint32_t qh[2][4];
#pragma unroll
    for (int kk = 0; kk < 2; ++kk) {
        const uint32_t kof = (uint32_t)(kk * 16) * 2;
        LDSM_X4(qh[kk][0], qh[kk][1], qh[kk][2], qh[kk][3], uQh + aoff + kof);
    }

    float l0 = 0.0f, l1 = 0.0f;
    float oacc[4][4];
#pragma unroll
    for (int nt = 0; nt < 4; ++nt)
#pragma unroll
        for (int i = 0; i < 4; ++i) oacc[nt][i] = 0.0f;

    const float4* bias_tb =
        bias4 + ((size_t)((b * 8 + qc) * 16)) * 2048 + (w * 8) * 32 + lane;

#pragma unroll 1
    for (int kt = 0; kt < 16; ++kt) {
        const int p = kt & 1;
        const uint32_t bufb = uKV + (uint32_t)p * ATTN_BUF_BYTES;

        if (kt < 15) {
            const uint32_t nb = uKV + (uint32_t)(1 - p) * ATTN_BUF_BYTES;
            size_t g = (size_t)(b * N_ + (kt + 1) * 64 + krow) * 768 + 256 +
                       h * HD_ + kc8;
            CP_ASYNC16(nb + kso, qkvh + g);
            CP_ASYNC16(nb + 5120 + kso, qkvh + g + 256);
            CP_COMMIT();
        }

        const uint32_t uKh = bufb;
        const uint32_t uVh = bufb + 5120;

        // ---- S = Qh*Kh ----
        float sacc[8][4];
#pragma unroll
        for (int nt = 0; nt < 8; ++nt)
#pragma unroll
            for (int i = 0; i < 4; ++i) sacc[nt][i] = 0.0f;

#pragma unroll
        for (int kk = 0; kk < 2; ++kk) {
            const uint32_t kof = (uint32_t)(kk * 16) * 2;
            uint32_t bh[4][4];
#pragma unroll
            for (int ntp = 0; ntp < 4; ++ntp) {
                uint32_t ba = koff + (uint32_t)(ntp * 16 * PITCH) * 2 + kof;
                LDSM_X4(bh[ntp][0], bh[ntp][1], bh[ntp][2], bh[ntp][3], uKh + ba);
            }
#pragma unroll
            for (int nt = 0; nt < 8; ++nt) {
                const int ntp = nt >> 1;
                const int hb = (nt & 1) * 2;
                MMA_FP16(sacc[nt], qh[kk][0], qh[kk][1], qh[kk][2], qh[kk][3],
                         bh[ntp][hb], bh[ntp][hb + 1]);
            }
        }

        // ---- scale + bias + exp ----
        const float4* bt = bias_tb + kt * 2048;
#pragma unroll
        for (int nt = 0; nt < 8; ++nt) {
            float4 bb = bt[nt * 32];
            float p0 = __expf(fmaf(sacc[nt][0], scale, bb.x));
            float p1 = __expf(fmaf(sacc[nt][1], scale, bb.y));
            float p2 = __expf(fmaf(sacc[nt][2], scale, bb.z));
            float p3 = __expf(fmaf(sacc[nt][3], scale, bb.w));
            sacc[nt][0] = p0; sacc[nt][1] = p1;
            sacc[nt][2] = p2; sacc[nt][3] = p3;
            l0 += p0 + p1;
            l1 += p2 + p3;
        }

        // ---- O += Ph*Vh ----
#pragma unroll
        for (int ks = 0; ks < 4; ++ks) {
            uint32_t pah[4];
            pah[0] = pack_h2(sacc[2 * ks][0],     sacc[2 * ks][1]);
            pah[1] = pack_h2(sacc[2 * ks][2],     sacc[2 * ks][3]);
            pah[2] = pack_h2(sacc[2 * ks + 1][0], sacc[2 * ks + 1][1]);
            pah[3] = pack_h2(sacc[2 * ks + 1][2], sacc[2 * ks + 1][3]);

            uint32_t vh[2][4];
#pragma unroll
            for (int ntp = 0; ntp < 2; ++ntp) {
                uint32_t va = voff + (uint32_t)(ks * 16 * PITCH + ntp * 16) * 2;
                LDSM_X4T(vh[ntp][0], vh[ntp][1], vh[ntp][2], vh[ntp][3], uVh + va);
            }
#pragma unroll
            for (int nt = 0; nt < 4; ++nt) {
                const int ntp = nt >> 1;
                const int hb = (nt & 1) * 2;
                MMA_FP16(oacc[nt], pah[0], pah[1], pah[2], pah[3],
                         vh[ntp][hb], vh[ntp][hb + 1]);
            }
        }

        if (kt < 15) CP_WAIT0();
        __syncthreads();
    }

    // ---- one-time l reduction over the 4-lane row group ----
    l0 += __shfl_xor_sync(0xffffffffu, l0, 1);
    l0 += __shfl_xor_sync(0xffffffffu, l0, 2);
    l1 += __shfl_xor_sync(0xffffffffu, l1, 1);
    l1 += __shfl_xor_sync(0xffffffffu, l1, 2);

    // ---- epilogue (split output for proj 3-term) ----
    const float inv0 = 1.0f / l0;
    const float inv1 = 1.0f / l1;
    const int row0 = qrow0 + w * 16 + gid;
#pragma unroll
    for (int nt = 0; nt < 4; ++nt) {
        int col = h * HD_ + nt * 8 + 2 * tig;
        uint32_t hv, lv;
        split2h(oacc[nt][0] * inv0, oacc[nt][1] * inv0, hv, lv);
        *reinterpret_cast<uint32_t*>(outh + (size_t)row0 * C_ + col) = hv;
        *reinterpret_cast<uint32_t*>(outl + (size_t)row0 * C_ + col) = lv;
        split2h(oacc[nt][2] * inv1, oacc[nt][3] * inv1, hv, lv);
        *reinterpret_cast<uint32_t*>(outh + (size_t)(row0 + 8) * C_ + col) = hv;
        *reinterpret_cast<uint32_t*>(outl + (size_t)(row0 + 8) * C_ + col) = lv;
    }
}

// ---------------------------------------------------------------------------
// launch
// ---------------------------------------------------------------------------
extern "C" void kernel_launch(void* const* d_in, const int* in_sizes, int n_in,
                              void* d_out, int out_size) {
    const float* x     = (const float*)d_in[0];
    const float* elev  = (const float*)d_in[1];
    const float* uw    = (const float*)d_in[2];
    const float* vw    = (const float*)d_in[3];
    const float* wqkv  = (const float*)d_in[4];
    const float* wproj = (const float*)d_in[5];
    const float* bproj = (const float*)d_in[6];
    const float* alpha = (const float*)d_in[7];
    const float* beta  = (const float*)d_in[8];
    float* out = (float*)d_out;

    float *ws_p;
    float4* bias4_p;
    __half *xh, *wqkvh, *wprojh, *wprojl;
    __half *qkvh, *attnh, *attnl;
    cudaGetSymbolAddress((void**)&ws_p, g_ws);
    cudaGetSymbolAddress((void**)&bias4_p, g_bias4);
    cudaGetSymbolAddress((void**)&xh, g_xh);
    cudaGetSymbolAddress((void**)&wqkvh, g_wqkvh);
    cudaGetSymbolAddress((void**)&wprojh, g_wprojh);
    cudaGetSymbolAddress((void**)&wprojl, g_wprojl);
    cudaGetSymbolAddress((void**)&qkvh, g_qkvh);
    cudaGetSymbolAddress((void**)&attnh, g_attnh);
    cudaGetSymbolAddress((void**)&attnl, g_attnl);

    cudaFuncSetAttribute(gemm_qkv,
                         cudaFuncAttributeMaxDynamicSharedMemorySize,
                         QG_SMEM_BYTES);
    cudaFuncSetAttribute(gemm_proj,
                         cudaFuncAttributeMaxDynamicSharedMemorySize,
                         P64_SMEM_BYTES);
    cudaFuncSetAttribute(attn_mma,
                         cudaFuncAttributeMaxDynamicSharedMemorySize,
                         ATTN_SMEM_BYTES);

    // 1) merged converts + wind strength (fused)
    convert_all<<<(N4_TOTAL + B_ * N_ + 255) / 256, 256>>>(
        x, wqkv, wproj, uw, vw, xh, wqkvh, wprojh, wprojl, ws_p);

    // 2) fragment-ordered bias
    bias_perm_kernel<<<B_ * N_ * N_ / 4 / 256, 256>>>(elev, ws_p, alpha, beta,
                                                      bias4_p);

    // 3) qkv = x @ w_qkv^T (single-term fp16)
    gemm_qkv<<<dim3(6, 64), 256, QG_SMEM_BYTES>>>(xh, wqkvh, qkvh);

    // 4) pure-fp16 flash attention (split output)
    attn_mma<<<dim3(8, NH_, B_), 256, ATTN_SMEM_BYTES>>>(
        qkvh, bias4_p, attnh, attnl);

    // 5) out = attn @ w_proj^T + b_proj (3-term)
    gemm_proj<<<dim3(2, 128), 256, P64_SMEM_BYTES>>>(
        attnh, attnl, wprojh, wprojl, bproj, out);
}

// round 16
// speedup vs baseline: 1.7791x; 1.0669x over previous
#include <cuda_runtime.h>
#include <cuda_fp16.h>
#include <math.h>
#include <cstdint>

// ---------------------------------------------------------------------------
// PhysicsGuidedAttentionCorrected
// B=8, N=1024, C=256, NUM_HEADS=8, hd=32
// R16: R15 + bias stored as fp16 in fragment order (|bias| <= 1e-3, fp16
//      abs err ~5e-7): attn bias traffic and bias_perm stores halved.
// ---------------------------------------------------------------------------

#define B_ 8
#define N_ 1024
#define C_ 256
#define NH_ 8
#define HD_ 32

// scratch (device globals; no allocations allowed)
__device__ float g_ws[B_ * N_];
__device__ uint4 g_bias8[B_ * N_ * N_ / 8];        // fragment-ordered fp16 bias
__device__ __half g_xh[B_ * N_ * C_];
__device__ __half g_wqkvh[3 * C_ * C_];
__device__ __half g_wprojh[C_ * C_];
__device__ __half g_wprojl[C_ * C_];
__device__ __half g_qkvh[B_ * N_ * 3 * C_];
__device__ __half g_attnh[B_ * N_ * C_];
__device__ __half g_attnl[B_ * N_ * C_];

// ---------------------------------------------------------------------------
// helpers
// ---------------------------------------------------------------------------
__device__ __forceinline__ uint32_t smem_u32(const void* p) {
    uint32_t a;
    asm("{ .reg .u64 t; cvta.to.shared.u64 t, %1; cvt.u32.u64 %0, t; }"
        : "=r"(a) : "l"(p));
    return a;
}

#define LDSM_X4(r0, r1, r2, r3, addr)                                        \
    asm volatile("ldmatrix.sync.aligned.m8n8.x4.shared.b16 {%0,%1,%2,%3}, [%4];" \
                 : "=r"(r0), "=r"(r1), "=r"(r2), "=r"(r3) : "r"(addr))

#define LDSM_X4T(r0, r1, r2, r3, addr)                                       \
    asm volatile("ldmatrix.sync.aligned.m8n8.x4.trans.shared.b16 {%0,%1,%2,%3}, [%4];" \
                 : "=r"(r0), "=r"(r1), "=r"(r2), "=r"(r3) : "r"(addr))

#define MMA_FP16(d, a0, a1, a2, a3, b0, b1)                                  \
    asm volatile("mma.sync.aligned.m16n8k16.row.col.f32.f16.f16.f32 "        \
                 "{%0,%1,%2,%3}, {%4,%5,%6,%7}, {%8,%9}, {%0,%1,%2,%3};"     \
                 : "+f"((d)[0]), "+f"((d)[1]), "+f"((d)[2]), "+f"((d)[3])    \
                 : "r"(a0), "r"(a1), "r"(a2), "r"(a3), "r"(b0), "r"(b1))

#define CP_ASYNC16(saddr, gptr)                                              \
    asm volatile("cp.async.cg.shared.global [%0], [%1], 16;"                 \
                 :: "r"(saddr), "l"(gptr))
#define CP_COMMIT() asm volatile("cp.async.commit_group;" ::: "memory")
#define CP_WAIT0()  asm volatile("cp.async.wait_group 0;" ::: "memory")

// fp16 hi/lo split
__device__ __forceinline__ void split2h(float x, float y,
                                        uint32_t& hi, uint32_t& lo) {
    uint32_t h;
    asm("cvt.rn.f16x2.f32 %0, %1, %2;" : "=r"(h) : "f"(y), "f"(x));
    float fx, fy;
    asm("{\n\t.reg .f16 a,b;\n\tmov.b32 {a,b}, %2;\n\t"
        "cvt.f32.f16 %0, a;\n\tcvt.f32.f16 %1, b;\n\t}"
        : "=f"(fx), "=f"(fy) : "r"(h));
    uint32_t l;
    asm("cvt.rn.f16x2.f32 %0, %1, %2;" : "=r"(l) : "f"(y - fy), "f"(x - fx));
    hi = h; lo = l;
}
__device__ __forceinline__ uint32_t pack_h2(float x, float y) {
    uint32_t h;
    asm("cvt.rn.f16x2.f32 %0, %1, %2;" : "=r"(h) : "f"(y), "f"(x));
    return h;
}
__device__ __forceinline__ float2 unpack_h2(uint32_t u) {
    float x, y;
    asm("{\n\t.reg .f16 a,b;\n\tmov.b32 {a,b}, %2;\n\t"
        "cvt.f32.f16 %0, a;\n\tcvt.f32.f16 %1, b;\n\t}"
        : "=f"(x), "=f"(y) : "r"(u));
    return make_float2(x, y);
}

// ---------------------------------------------------------------------------
// bias precompute, fp16 fragment order.
// uint4 index t: lane(0..4) | ntp(5..6) | w(7..9) | kt(10..13) | qt(14..16) | b(17..19)
// i0 = qt*128 + w*16 + (lane>>2); j0 = kt*64 + ntp*16 + 2*(lane&3)
// u = { h2(b(i0,j0),b(i0,j0+1)), h2(b(i0+8,j0),b(i0+8,j0+1)),
//       h2(b(i0,j0+8),b(i0,j0+9)), h2(b(i0+8,j0+8),b(i0+8,j0+9)) }
// ---------------------------------------------------------------------------
__device__ __forceinline__ float bias_val(float ei, float wi, float ej,
                                          float wj, float alpha, float beta) {
    float ed = fmaxf((ej - ei) * 1e-3f, 0.0f);
    float z = (wi + wj) * 0.5f - 5.0f;
    float wf = 1.0f / (1.0f + __expf(-z));
    float bia = -alpha * ed * (1.0f - beta * wf);
    return fminf(fmaxf(bia, -10.0f), 0.0f);
}

__global__ __launch_bounds__(256)
void bias_perm_kernel(const float* __restrict__ elev, const float* __restrict__ ws,
                      const float* __restrict__ alpha_p,
                      const float* __restrict__ beta_p,
                      uint4* __restrict__ bias8) {
    const int t = blockIdx.x * blockDim.x + threadIdx.x;   // 1,048,576
    const int lane = t & 31;
    const int ntp = (t >> 5) & 3;
    const int w  = (t >> 7) & 7;
    const int kt = (t >> 10) & 15;
    const int qt = (t >> 14) & 7;
    const int b  = t >> 17;
    const float alpha = *alpha_p;
    const float beta = *beta_p;

    const int i0 = qt * 128 + w * 16 + (lane >> 2);
    const int j0 = kt * 64 + ntp * 16 + 2 * (lane & 3);
    const float* e = elev + b * 1024;
    const float* wsb = ws + b * 1024;
    float ei0 = e[i0], ei1 = e[i0 + 8];
    float wi0 = wsb[i0], wi1 = wsb[i0 + 8];
    float ej0 = e[j0], ej1 = e[j0 + 1], ej2 = e[j0 + 8], ej3 = e[j0 + 9];
    float wj0 = wsb[j0], wj1 = wsb[j0 + 1], wj2 = wsb[j0 + 8], wj3 = wsb[j0 + 9];

    uint4 u;
    u.x = pack_h2(bias_val(ei0, wi0, ej0, wj0, alpha, beta),
                  bias_val(ei0, wi0, ej1, wj1, alpha, beta));
    u.y = pack_h2(bias_val(ei1, wi1, ej0, wj0, alpha, beta),
                  bias_val(ei1, wi1, ej1, wj1, alpha, beta));
    u.z = pack_h2(bias_val(ei0, wi0, ej2, wj2, alpha, beta),
                  bias_val(ei0, wi0, ej3, wj3, alpha, beta));
    u.w = pack_h2(bias_val(ei1, wi1, ej2, wj2, alpha, beta),
                  bias_val(ei1, wi1, ej3, wj3, alpha, beta));
    bias8[t] = u;
}

// ---------------------------------------------------------------------------
// merged converter: x,wqkv -> fp16 hi; wproj -> fp16 hi/lo; + wind strength
// ---------------------------------------------------------------------------
#define N4_X (B_ * N_ * C_ / 4)
#define N4_WQKV (3 * C_ * C_ / 4)
#define N4_WPROJ (C_ * C_ / 4)
#define N4_TOTAL (N4_X + N4_WQKV + N4_WPROJ)

__global__ void convert_all(const float* __restrict__ x,
                            const float* __restrict__ wqkv,
                            const float* __restrict__ wproj,
                            const float* __restrict__ uwind,
                            const float* __restrict__ vwind,
                            __half* __restrict__ xh,
                            __half* __restrict__ wqh,
                            __half* __restrict__ wph, __half* __restrict__ wpl,
                            float* __restrict__ ws) {
    int i = blockIdx.x * blockDim.x + threadIdx.x;
    if (i >= N4_TOTAL) {
        int t = i - N4_TOTAL;
        if (t >= B_ * N_) return;
        int b = t >> 10;
        int n = t & 1023;
        int r = n >> 5;
        int c = n & 31;
        const float* ub = uwind + b * 4096;
        const float* vb = vwind + b * 4096;
        float s = 0.0f;
#pragma unroll
        for (int dr = 0; dr < 2; ++dr)
#pragma unroll
            for (int dc = 0; dc < 2; ++dc) {
                int idx = (2 * r + dr) * 64 + (2 * c + dc);
                float uu = ub[idx], vv = vb[idx];
                s += sqrtf(uu * uu + vv * vv + 1e-8f);
            }
        ws[t] = s * 0.25f;
        return;
    }
    if (i < N4_X + N4_WQKV) {
        const float* in = (i < N4_X) ? x : wqkv;
        __half* hi = (i < N4_X) ? xh : wqh;
        int off = (i < N4_X) ? i : (i - N4_X);
        float4 v = reinterpret_cast<const float4*>(in)[off];
        *reinterpret_cast<uint2*>(hi + 4 * off) =
            make_uint2(pack_h2(v.x, v.y), pack_h2(v.z, v.w));
    } else {
        int off = i - N4_X - N4_WQKV;
        float4 v = reinterpret_cast<const float4*>(wproj)[off];
        uint32_t h01, l01, h23, l23;
        split2h(v.x, v.y, h01, l01);
        split2h(v.z, v.w, h23, l23);
        *reinterpret_cast<uint2*>(wph + 4 * off) = make_uint2(h01, h23);
        *reinterpret_cast<uint2*>(wpl + 4 * off) = make_uint2(l01, l23);
    }
}

// ---------------------------------------------------------------------------
// single-term fp16 GEMM 128x128 (QKV): C = Ah*Bh^T, fp16 output. (R15 proven)
// ---------------------------------------------------------------------------
#define PITCH 40
#define QG_BUF_BYTES (2 * 128 * PITCH * 2)
#define QG_SMEM_BYTES (2 * QG_BUF_BYTES)

__global__ __launch_bounds__(256, 2)
void gemm_qkv(const __half* __restrict__ Ah, const __half* __restrict__ Bh,
              __half* __restrict__ Ch) {
    const int N = 768;
    extern __shared__ __align__(16) char smem_raw[];
    const uint32_t uS = smem_u32(smem_raw);

    const int tid = threadIdx.x;
    const int lane = tid & 31;
    const int wid = tid >> 5;
    const int wm = wid & 1;
    const int wn = wid >> 1;
    const int bx = blockIdx.x;
    const int by = blockIdx.y;

    const __half* Agh = Ah + (size_t)by * 128 * 256;
    const __half* Bgh = Bh + (size_t)bx * 128 * 256;

    float acc[4][4][4];
#pragma unroll
    for (int mt = 0; mt < 4; ++mt)
#pragma unroll
        for (int nt = 0; nt < 4; ++nt)
#pragma unroll
            for (int i = 0; i < 4; ++i) acc[mt][nt][i] = 0.0f;

    const uint32_t aoff =
        (uint32_t)((wm * 64 + (lane & 15)) * PITCH + ((lane & 16) ? 8 : 0)) * 2;
    const uint32_t boff =
        (uint32_t)((wn * 32 + (lane & 7) + ((lane & 16) ? 8 : 0)) * PITCH +
                   ((lane & 8) ? 8 : 0)) * 2;

    const int row0 = tid >> 2;
    const int c8 = (tid & 3) * 8;

#pragma unroll
    for (int i = 0; i < 2; ++i) {
        int row = row0 + i * 64;
        size_t g = (size_t)row * 256 + c8;
        uint32_t so = (uint32_t)(row * PITCH + c8) * 2;
        CP_ASYNC16(uS + so, Agh + g);
        CP_ASYNC16(uS + 10240 + so, Bgh + g);
    }
    CP_COMMIT();
    CP_WAIT0();
    __syncthreads();

#pragma unroll 1
    for (int kb = 0; kb < 8; ++kb) {
        const int p = kb & 1;
        const uint32_t bufb = uS + (uint32_t)p * QG_BUF_BYTES;

        if (kb < 7) {
            const uint32_t nb = uS + (uint32_t)(1 - p) * QG_BUF_BYTES;
#pragma unroll
            for (int i = 0; i < 2; ++i) {
                int row = row0 + i * 64;
                size_t g = (size_t)row * 256 + (kb + 1) * 32 + c8;
                uint32_t so = (uint32_t)(row * PITCH + c8) * 2;
                CP_ASYNC16(nb + so, Agh + g);
                CP_ASYNC16(nb + 10240 + so, Bgh + g);
            }
            CP_COMMIT();
        }

        const uint32_t uAh = bufb, uBh = bufb + 10240;

#pragma unroll
        for (int kk = 0; kk < 2; ++kk) {
            const uint32_t kof = (uint32_t)(kk * 16) * 2;
            uint32_t bhf[2][4];
#pragma unroll
            for (int ntp = 0; ntp < 2; ++ntp) {
                uint32_t ba = boff + (uint32_t)(ntp * 16 * PITCH) * 2 + kof;
                LDSM_X4(bhf[ntp][0], bhf[ntp][1], bhf[ntp][2], bhf[ntp][3], uBh + ba);
            }
#pragma unroll
            for (int mt = 0; mt < 4; ++mt) {
                uint32_t aa = aoff + (uint32_t)(mt * 16 * PITCH) * 2 + kof;
                uint32_t ah0, ah1, ah2, ah3;
                LDSM_X4(ah0, ah1, ah2, ah3, uAh + aa);
#pragma unroll
                for (int nt = 0; nt < 4; ++nt) {
                    const int ntp = nt >> 1;
                    const int hb = (nt & 1) * 2;
                    MMA_FP16(acc[mt][nt], ah0, ah1, ah2, ah3,
                             bhf[ntp][hb], bhf[ntp][hb + 1]);
                }
            }
        }

        if (kb < 7) CP_WAIT0();
        __syncthreads();
    }

    const int gid = lane >> 2;
    const int tig = lane & 3;
#pragma unroll
    for (int mt = 0; mt < 4; ++mt) {
        int row = by * 128 + wm * 64 + mt * 16 + gid;
#pragma unroll
        for (int nt = 0; nt < 4; ++nt) {
            int col = bx * 128 + wn * 32 + nt * 8 + 2 * tig;
            *reinterpret_cast<uint32_t*>(Ch + (size_t)row * N + col) =
                pack_h2(acc[mt][nt][0], acc[mt][nt][1]);
            *reinterpret_cast<uint32_t*>(Ch + (size_t)(row + 8) * N + col) =
                pack_h2(acc[mt][nt][2], acc[mt][nt][3]);
        }
    }
}

// ---------------------------------------------------------------------------
// proj GEMM: 64x128 tiles, fp16 3-term, f32 + bias output. (proven)
// ---------------------------------------------------------------------------
#define P64_BUF_BYTES (2 * 64 * PITCH * 2 + 2 * 128 * PITCH * 2)
#define P64_SMEM_BYTES (2 * P64_BUF_BYTES)

__global__ __launch_bounds__(256, 2)
void gemm_proj(const __half* __restrict__ Ah, const __half* __restrict__ Al,
               const __half* __restrict__ Bh, const __half* __restrict__ Bl,
               const float* __restrict__ bias, float* __restrict__ C) {
    const int N = 256;
    extern __shared__ __align__(16) char smem_raw[];
    const uint32_t uS = smem_u32(smem_raw);

    const int tid = threadIdx.x;
    const int lane = tid & 31;
    const int wid = tid >> 5;
    const int wm = wid & 1;
    const int wn = wid >> 1;
    const int bx = blockIdx.x;
    const int by = blockIdx.y;

    const __half* Agh = Ah + (size_t)by * 64 * 256;
    const __half* Agl = Al + (size_t)by * 64 * 256;
    const __half* Bgh = Bh + (size_t)bx * 128 * 256;
    const __half* Bgl = Bl + (size_t)bx * 128 * 256;

    float acc[2][4][4];
#pragma unroll
    for (int mt = 0; mt < 2; ++mt)
#pragma unroll
        for (int nt = 0; nt < 4; ++nt)
#pragma unroll
            for (int i = 0; i < 4; ++i) acc[mt][nt][i] = 0.0f;

    const uint32_t aoff =
        (uint32_t)((wm * 32 + (lane & 15)) * PITCH + ((lane & 16) ? 8 : 0)) * 2;
    const uint32_t boff =
        (uint32_t)((wn * 32 + (lane & 7) + ((lane & 16) ? 8 : 0)) * PITCH +
                   ((lane & 8) ? 8 : 0)) * 2;

    const int arow = tid >> 2;
    const int ac8 = (tid & 3) * 8;
    const uint32_t aso = (uint32_t)(arow * PITCH + ac8) * 2;
    const int brow0 = tid >> 2;

#pragma unroll 1
    for (int kb = -1; kb < 8; ++kb) {
        if (kb < 7) {
            const uint32_t nb = uS + (uint32_t)((kb + 1) & 1) * P64_BUF_BYTES;
            int kof = (kb + 1) * 32;
            {
                size_t g = (size_t)arow * 256 + kof + ac8;
                CP_ASYNC16(nb + aso, Agh + g);
                CP_ASYNC16(nb + 5120 + aso, Agl + g);
            }
#pragma unroll
            for (int i = 0; i < 2; ++i) {
                int row = brow0 + i * 64;
                size_t g = (size_t)row * 256 + kof + ac8;
                uint32_t so = (uint32_t)(row * PITCH + ac8) * 2;
                CP_ASYNC16(nb + 10240 + so, Bgh + g);
                CP_ASYNC16(nb + 20480 + so, Bgl + g);
            }
            CP_COMMIT();
        }
        if (kb < 0) { CP_WAIT0(); __syncthreads(); continue; }

        const uint32_t bufb = uS + (uint32_t)(kb & 1) * P64_BUF_BYTES;
        const uint32_t uAh = bufb, uAl = bufb + 5120;
        const uint32_t uBh = bufb + 10240, uBl = bufb + 20480;

#pragma unroll
        for (int kk = 0; kk < 2; ++kk) {
            const uint32_t kof = (uint32_t)(kk * 16) * 2;
            uint32_t bhf[2][4], blf[2][4];
#pragma unroll
            for (int ntp = 0; ntp < 2; ++ntp) {
                uint32_t ba = boff + (uint32_t)(ntp * 16 * PITCH) * 2 + kof;
                LDSM_X4(bhf[ntp][0], bhf[ntp][1], bhf[ntp][2], bhf[ntp][3], uBh + ba);
                LDSM_X4(blf[ntp][0], blf[ntp][1], blf[ntp][2], blf[ntp][3], uBl + ba);
            }
#pragma unroll
            for (int mt = 0; mt < 2; ++mt) {
                uint32_t aa = aoff + (uint32_t)(mt * 16 * PITCH) * 2 + kof;
                uint32_t ah0, ah1, ah2, ah3, al0, al1, al2, al3;
                LDSM_X4(ah0, ah1, ah2, ah3, uAh + aa);
                LDSM_X4(al0, al1, al2, al3, uAl + aa);
#pragma unroll
                for (int nt = 0; nt < 4; ++nt) {
                    const int ntp = nt >> 1;
                    const int hb = (nt & 1) * 2;
                    MMA_FP16(acc[mt][nt], ah0, ah1, ah2, ah3,
                             bhf[ntp][hb], bhf[ntp][hb + 1]);
                    MMA_FP16(acc[mt][nt], ah0, ah1, ah2, ah3,
                             blf[ntp][hb], blf[ntp][hb + 1]);
                    MMA_FP16(acc[mt][nt], al0, al1, al2, al3,
                             bhf[ntp][hb], bhf[ntp][hb + 1]);
                }
            }
        }

        if (kb < 7) CP_WAIT0();
        __syncthreads();
    }

    const int gid = lane >> 2;
    const int tig = lane & 3;
#pragma unroll
    for (int mt = 0; mt < 2; ++mt) {
        int row = by * 64 + wm * 32 + mt * 16 + gid;
#pragma unroll
        for (int nt = 0; nt < 4; ++nt) {
            int col = bx * 128 + wn * 32 + nt * 8 + 2 * tig;
            float2 bb = *reinterpret_cast<const float2*>(bias + col);
            float2 v0 = make_float2(acc[mt][nt][0] + bb.x, acc[mt][nt][1] + bb.y);
            float2 v1 = make_float2(acc[mt][nt][2] + bb.x, acc[mt][nt][3] + bb.y);
            *reinterpret_cast<float2*>(C + (size_t)row * N + col) = v0;
            *reinterpret_cast<float2*>(C + (size_t)(row + 8) * N + col) = v1;
        }
    }
}

// ---------------------------------------------------------------------------
// pure-fp16 flash attention with fp16 bias (halved bias traffic).
// ---------------------------------------------------------------------------
#define ATTN_Q_BYTES (128 * PITCH * 2)
#define ATTN_BUF_BYTES (2 * 64 * PITCH * 2)
#define ATTN_SMEM_BYTES (ATTN_Q_BYTES + 2 * ATTN_BUF_BYTES)

__global__ __launch_bounds__(256, 2)
void attn_mma(const __half* __restrict__ qkvh,
              const uint4* __restrict__ bias8,
              __half* __restrict__ outh,
              __half* __restrict__ outl) {
    extern __shared__ __align__(16) char smem_raw[];
    __half* Qh = reinterpret_cast<__half*>(smem_raw);
    const uint32_t uQh = smem_u32(Qh);
    const uint32_t uKV = uQh + ATTN_Q_BYTES;

    const int tid = threadIdx.x;
    const int lane = tid & 31;
    const int w = tid >> 5;
    const int gid = lane >> 2;
    const int tig = lane & 3;
    const int qc = blockIdx.x;
    const int h  = blockIdx.y;
    const int b  = blockIdx.z;

    const float scale = 0.17677669529663687f;   // 1/sqrt(32)
    const int qrow0 = b * N_ + qc * 128;

    const int krow = tid >> 2;
    const int kc8 = (tid & 3) * 8;
    const uint32_t kso = (uint32_t)(krow * PITCH + kc8) * 2;

    // prologue: stage kt=0 (Kh|Vh)
    {
        size_t g = (size_t)(b * N_ + krow) * 768 + 256 + h * HD_ + kc8;
        CP_ASYNC16(uKV + kso, qkvh + g);
        CP_ASYNC16(uKV + 5120 + kso, qkvh + g + 256);
        CP_COMMIT();
    }

    // stage Qh
    {
        int row = tid >> 1;
        int c8 = (tid & 1) * 16;
        size_t g = (size_t)(qrow0 + row) * 768 + h * HD_ + c8;
        int so = row * PITCH + c8;
        *reinterpret_cast<uint4*>(&Qh[so]) =
            *reinterpret_cast<const uint4*>(qkvh + g);
        *reinterpret_cast<uint4*>(&Qh[so + 8]) =
            *reinterpret_cast<const uint4*>(qkvh + g + 8);
    }
    CP_WAIT0();
    __syncthreads();

    const uint32_t aoff =
        (uint32_t)((w * 16 + (lane & 15)) * PITCH + ((lane & 16) ? 8 : 0)) * 2;
    const uint32_t koff =
        (uint32_t)(((lane & 7) + ((lane & 16) ? 8 : 0)) * PITCH +
                   ((lane & 8) ? 8 : 0)) * 2;
    const uint32_t voff =
        (uint32_t)((lane & 15) * PITCH + ((lane & 16) ? 8 : 0)) * 2;

    // hoisted Qh fragments
    uint32_t qh[2][4];
#pragma unroll
    for (int kk = 0; kk < 2; ++kk) {
        const uint32_t kof = (uint32_t)(kk * 16) * 2;
        LDSM_X4(qh[kk][0], qh[kk][1], qh[kk][2], qh[kk][3], uQh + aoff + kof);
    }

    float l0 = 0.0f, l1 = 0.0f;
    float oacc[4][4];
#pragma unroll
    for (int nt = 0; nt < 4; ++nt)
#pragma unroll
        for (int i = 0; i < 4; ++i) oacc[nt][i] = 0.0f;

    // fp16 bias tile base: per (b,qc) 16 kt x 1024 uint4; per warp: w*128
    const uint4* bias_tb =
        bias8 + ((size_t)((b * 8 + qc) * 16)) * 1024 + w * 128 + lane;

#pragma unroll 1
    for (int kt = 0; kt < 16; ++kt) {
        const int p = kt & 1;
        const uint32_t bufb = uKV + (uint32_t)p * ATTN_BUF_BYTES;

        if (kt < 15) {
            const uint32_t nb = uKV + (uint32_t)(1 - p) * ATTN_BUF_BYTES;
            size_t g = (size_t)(b * N_ + (kt + 1) * 64 + krow) * 768 + 256 +
                       h * HD_ + kc8;
            CP_ASYNC16(nb + kso, qkvh + g);
            CP_ASYNC16(nb + 5120 + kso, qkvh + g + 256);
            CP_COMMIT();
        }

        const uint32_t uKh = bufb;
        const uint32_t uVh = bufb + 5120;

        // ---- S = Qh*Kh ----
        float sacc[8][4];
#pragma unroll
        for (int nt = 0; nt < 8; ++nt)
#pragma unroll
            for (int i = 0; i < 4; ++i) sacc[nt][i] = 0.0f;

#pragma unroll
        for (int kk = 0; kk < 2; ++kk) {
            const uint32_t kof = (uint32_t)(kk * 16) * 2;
            uint32_t bh[4][4];
#pragma unroll
            for (int ntp = 0; ntp < 4; ++ntp) {
                uint32_t ba = koff + (uint32_t)(ntp * 16 * PITCH) * 2 + kof;
                LDSM_X4(bh[ntp][0], bh[ntp][1], bh[ntp][2], bh[ntp][3], uKh + ba);
            }
#pragma unroll
            for (int nt = 0; nt < 8; ++nt) {
                const int ntp = nt >> 1;
                const int hb = (nt & 1) * 2;
                MMA_FP16(sacc[nt], qh[kk][0], qh[kk][1], qh[kk][2], qh[kk][3],
                         bh[ntp][hb], bh[ntp][hb + 1]);
            }
        }

        // ---- scale + fp16 bias + exp ----
        const uint4* bt = bias_tb + kt * 1024;
#pragma unroll
        for (int ntp = 0; ntp < 4; ++ntp) {
            uint4 u = bt[ntp * 32];
            float2 f0 = unpack_h2(u.x);   // (i0,j0),(i0,j0+1)
            float2 f1 = unpack_h2(u.y);   // (i0+8,j0),(i0+8,j0+1)
            float2 f2 = unpack_h2(u.z);   // nt+1
            float2 f3 = unpack_h2(u.w);
            const int nt0 = 2 * ntp;
            float p0 = __expf(fmaf(sacc[nt0][0], scale, f0.x));
            float p1 = __expf(fmaf(sacc[nt0][1], scale, f0.y));
            float p2 = __expf(fmaf(sacc[nt0][2], scale, f1.x));
            float p3 = __expf(fmaf(sacc[nt0][3], scale, f1.y));
            sacc[nt0][0] = p0; sacc[nt0][1] = p1;
            sacc[nt0][2] = p2; sacc[nt0][3] = p3;
            l0 += p0 + p1;
            l1 += p2 + p3;
            float p4 = __expf(fmaf(sacc[nt0 + 1][0], scale, f2.x));
            float p5 = __expf(fmaf(sacc[nt0 + 1][1], scale, f2.y));
            float p6 = __expf(fmaf(sacc[nt0 + 1][2], scale, f3.x));
            float p7 = __expf(fmaf(sacc[nt0 + 1][3], scale, f3.y));
            sacc[nt0 + 1][0] = p4; sacc[nt0 + 1][1] = p5;
            sacc[nt0 + 1][2] = p6; sacc[nt0 + 1][3] = p7;
            l0 += p4 + p5;
            l1 += p6 + p7;
        }

        // ---- O += Ph*Vh ----
#pragma unroll
        for (int ks = 0; ks < 4; ++ks) {
            uint32_t pah[4];
            pah[0] = pack_h2(sacc[2 * ks][0],     sacc[2 * ks][1]);
            pah[1] = pack_h2(sacc[2 * ks][2],     sacc[2 * ks][3]);
            pah[2] = pack_h2(sacc[2 * ks + 1][0], sacc[2 * ks + 1][1]);
            pah[3] = pack_h2(sacc[2 * ks + 1][2], sacc[2 * ks + 1][3]);

            uint32_t vh[2][4];
#pragma unroll
            for (int ntp = 0; ntp < 2; ++ntp) {
                uint32_t va = voff + (uint32_t)(ks * 16 * PITCH + ntp * 16) * 2;
                LDSM_X4T(vh[ntp][0], vh[ntp][1], vh[ntp][2], vh[ntp][3], uVh + va);
            }
#pragma unroll
            for (int nt = 0; nt < 4; ++nt) {
                const int ntp = nt >> 1;
                const int hb = (nt & 1) * 2;
                MMA_FP16(oacc[nt], pah[0], pah[1], pah[2], pah[3],
                         vh[ntp][hb], vh[ntp][hb + 1]);
            }
        }

        if (kt < 15) CP_WAIT0();
        __syncthreads();
    }

    // ---- one-time l reduction over the 4-lane row group ----
    l0 += __shfl_xor_sync(0xffffffffu, l0, 1);
    l0 += __shfl_xor_sync(0xffffffffu, l0, 2);
    l1 += __shfl_xor_sync(0xffffffffu, l1, 1);
    l1 += __shfl_xor_sync(0xffffffffu, l1, 2);

    // ---- epilogue (split output for proj 3-term) ----
    const float inv0 = 1.0f / l0;
    const float inv1 = 1.0f / l1;
    const int row0 = qrow0 + w * 16 + gid;
#pragma unroll
    for (int nt = 0; nt < 4; ++nt) {
        int col = h * HD_ + nt * 8 + 2 * tig;
        uint32_t hv, lv;
        split2h(oacc[nt][0] * inv0, oacc[nt][1] * inv0, hv, lv);
        *reinterpret_cast<uint32_t*>(outh + (size_t)row0 * C_ + col) = hv;
        *reinterpret_cast<uint32_t*>(outl + (size_t)row0 * C_ + col) = lv;
        split2h(oacc[nt][2] * inv1, oacc[nt][3] * inv1, hv, lv);
        *reinterpret_cast<uint32_t*>(outh + (size_t)(row0 + 8) * C_ + col) = hv;
        *reinterpret_cast<uint32_t*>(outl + (size_t)(row0 + 8) * C_ + col) = lv;
    }
}

// ---------------------------------------------------------------------------
// launch
// ---------------------------------------------------------------------------
extern "C" void kernel_launch(void* const* d_in, const int* in_sizes, int n_in,
                              void* d_out, int out_size) {
    const float* x     = (const float*)d_in[0];
    const float* elev  = (const float*)d_in[1];
    const float* uw    = (const float*)d_in[2];
    const float* vw    = (const float*)d_in[3];
    const float* wqkv  = (const float*)d_in[4];
    const float* wproj = (const float*)d_in[5];
    const float* bproj = (const float*)d_in[6];
    const float* alpha = (const float*)d_in[7];
    const float* beta  = (const float*)d_in[8];
    float* out = (float*)d_out;

    float *ws_p;
    uint4* bias8_p;
    __half *xh, *wqkvh, *wprojh, *wprojl;
    __half *qkvh, *attnh, *attnl;
    cudaGetSymbolAddress((void**)&ws_p, g_ws);
    cudaGetSymbolAddress((void**)&bias8_p, g_bias8);
    cudaGetSymbolAddress((void**)&xh, g_xh);
    cudaGetSymbolAddress((void**)&wqkvh, g_wqkvh);
    cudaGetSymbolAddress((void**)&wprojh, g_wprojh);
    cudaGetSymbolAddress((void**)&wprojl, g_wprojl);
    cudaGetSymbolAddress((void**)&qkvh, g_qkvh);
    cudaGetSymbolAddress((void**)&attnh, g_attnh);
    cudaGetSymbolAddress((void**)&attnl, g_attnl);

    cudaFuncSetAttribute(gemm_qkv,
                         cudaFuncAttributeMaxDynamicSharedMemorySize,
                         QG_SMEM_BYTES);
    cudaFuncSetAttribute(gemm_proj,
                         cudaFuncAttributeMaxDynamicSharedMemorySize,
                         P64_SMEM_BYTES);
    cudaFuncSetAttribute(attn_mma,
                         cudaFuncAttributeMaxDynamicSharedMemorySize,
                         ATTN_SMEM_BYTES);

    // 1) merged converts + wind strength (fused)
    convert_all<<<(N4_TOTAL + B_ * N_ + 255) / 256, 256>>>(
        x, wqkv, wproj, uw, vw, xh, wqkvh, wprojh, wprojl, ws_p);

    // 2) fragment-ordered fp16 bias
    bias_perm_kernel<<<B_ * N_ * N_ / 8 / 256, 256>>>(elev, ws_p, alpha, beta,
                                                      bias8_p);

    // 3) qkv = x @ w_qkv^T (single-term fp16)
    gemm_qkv<<<dim3(6, 64), 256, QG_SMEM_BYTES>>>(xh, wqkvh, qkvh);

    // 4) pure-fp16 flash attention (fp16 bias, split output)
    attn_mma<<<dim3(8, NH_, B_), 256, ATTN_SMEM_BYTES>>>(
        qkvh, bias8_p, attnh, attnl);

    // 5) out = attn @ w_proj^T + b_proj (3-term)
    gemm_proj<<<dim3(2, 128), 256, P64_SMEM_BYTES>>>(
        attnh, attnl, wprojh, wprojl, bproj, out);
}

// round 17
// speedup vs baseline: 1.9894x; 1.1182x over previous
#include <cuda_runtime.h>
#include <cuda_fp16.h>
#include <math.h>
#include <cstdint>

// ---------------------------------------------------------------------------
// PhysicsGuidedAttentionCorrected
// B=8, N=1024, C=256, NUM_HEADS=8, hd=32
// R17: log2-domain softmax with zero overhead: q pre-scaled by scale*log2e,
//      bias pre-scaled by log2e and used as the S accumulator init, exp is a
//      bare ex2.approx. Attn output single fp16; proj 2-term (A single, B split).
// ---------------------------------------------------------------------------

#define B_ 8
#define N_ 1024
#define C_ 256
#define NH_ 8
#define HD_ 32

// scratch (device globals; no allocations allowed)
__device__ float g_ws[B_ * N_];
__device__ uint4 g_bias8[B_ * N_ * N_ / 8];        // fragment-ordered fp16 bias*log2e
__device__ __half g_xh[B_ * N_ * C_];
__device__ __half g_wqkvh[3 * C_ * C_];
__device__ __half g_wprojh[C_ * C_];
__device__ __half g_wprojl[C_ * C_];
__device__ __half g_qkvh[B_ * N_ * 3 * C_];        // q pre-scaled by scale*log2e
__device__ __half g_attnh[B_ * N_ * C_];

// ---------------------------------------------------------------------------
// helpers
// ---------------------------------------------------------------------------
__device__ __forceinline__ uint32_t smem_u32(const void* p) {
    uint32_t a;
    asm("{ .reg .u64 t; cvta.to.shared.u64 t, %1; cvt.u32.u64 %0, t; }"
        : "=r"(a) : "l"(p));
    return a;
}

#define LDSM_X4(r0, r1, r2, r3, addr)                                        \
    asm volatile("ldmatrix.sync.aligned.m8n8.x4.shared.b16 {%0,%1,%2,%3}, [%4];" \
                 : "=r"(r0), "=r"(r1), "=r"(r2), "=r"(r3) : "r"(addr))

#define LDSM_X4T(r0, r1, r2, r3, addr)                                       \
    asm volatile("ldmatrix.sync.aligned.m8n8.x4.trans.shared.b16 {%0,%1,%2,%3}, [%4];" \
                 : "=r"(r0), "=r"(r1), "=r"(r2), "=r"(r3) : "r"(addr))

#define MMA_FP16(d, a0, a1, a2, a3, b0, b1)                                  \
    asm volatile("mma.sync.aligned.m16n8k16.row.col.f32.f16.f16.f32 "        \
                 "{%0,%1,%2,%3}, {%4,%5,%6,%7}, {%8,%9}, {%0,%1,%2,%3};"     \
                 : "+f"((d)[0]), "+f"((d)[1]), "+f"((d)[2]), "+f"((d)[3])    \
                 : "r"(a0), "r"(a1), "r"(a2), "r"(a3), "r"(b0), "r"(b1))

#define CP_ASYNC16(saddr, gptr)                                              \
    asm volatile("cp.async.cg.shared.global [%0], [%1], 16;"                 \
                 :: "r"(saddr), "l"(gptr))
#define CP_COMMIT() asm volatile("cp.async.commit_group;" ::: "memory")
#define CP_WAIT0()  asm volatile("cp.async.wait_group 0;" ::: "memory")

// fp16 hi/lo split (cold paths: wproj)
__device__ __forceinline__ void split2h(float x, float y,
                                        uint32_t& hi, uint32_t& lo) {
    uint32_t h;
    asm("cvt.rn.f16x2.f32 %0, %1, %2;" : "=r"(h) : "f"(y), "f"(x));
    float fx, fy;
    asm("{\n\t.reg .f16 a,b;\n\tmov.b32 {a,b}, %2;\n\t"
        "cvt.f32.f16 %0, a;\n\tcvt.f32.f16 %1, b;\n\t}"
        : "=f"(fx), "=f"(fy) : "r"(h));
    uint32_t l;
    asm("cvt.rn.f16x2.f32 %0, %1, %2;" : "=r"(l) : "f"(y - fy), "f"(x - fx));
    hi = h; lo = l;
}
__device__ __forceinline__ uint32_t pack_h2(float x, float y) {
    uint32_t h;
    asm("cvt.rn.f16x2.f32 %0, %1, %2;" : "=r"(h) : "f"(y), "f"(x));
    return h;
}
__device__ __forceinline__ float2 unpack_h2(uint32_t u) {
    float x, y;
    asm("{\n\t.reg .f16 a,b;\n\tmov.b32 {a,b}, %2;\n\t"
        "cvt.f32.f16 %0, a;\n\tcvt.f32.f16 %1, b;\n\t}"
        : "=f"(x), "=f"(y) : "r"(u));
    return make_float2(x, y);
}
__device__ __forceinline__ float ex2(float x) {
    float r;
    asm("ex2.approx.f32 %0, %1;" : "=f"(r) : "f"(x));
    return r;
}

#define QSCALE_LG2 0.25505653570120927f   // (1/sqrt(32)) * log2(e)
#define LOG2E 1.4426950408889634f

// ---------------------------------------------------------------------------
// bias precompute, fp16 fragment order, pre-multiplied by log2e.
// ---------------------------------------------------------------------------
__device__ __forceinline__ float bias_val(float ei, float wi, float ej,
                                          float wj, float alpha, float beta) {
    float ed = fmaxf((ej - ei) * 1e-3f, 0.0f);
    float z = (wi + wj) * 0.5f - 5.0f;
    float wf = 1.0f / (1.0f + __expf(-z));
    float bia = -alpha * ed * (1.0f - beta * wf);
    return fminf(fmaxf(bia, -10.0f), 0.0f) * LOG2E;
}

__global__ __launch_bounds__(256)
void bias_perm_kernel(const float* __restrict__ elev, const float* __restrict__ ws,
                      const float* __restrict__ alpha_p,
                      const float* __restrict__ beta_p,
                      uint4* __restrict__ bias8) {
    const int t = blockIdx.x * blockDim.x + threadIdx.x;   // 1,048,576
    const int lane = t & 31;
    const int ntp = (t >> 5) & 3;
    const int w  = (t >> 7) & 7;
    const int kt = (t >> 10) & 15;
    const int qt = (t >> 14) & 7;
    const int b  = t >> 17;
    const float alpha = *alpha_p;
    const float beta = *beta_p;

    const int i0 = qt * 128 + w * 16 + (lane >> 2);
    const int j0 = kt * 64 + ntp * 16 + 2 * (lane & 3);
    const float* e = elev + b * 1024;
    const float* wsb = ws + b * 1024;
    float ei0 = e[i0], ei1 = e[i0 + 8];
    float wi0 = wsb[i0], wi1 = wsb[i0 + 8];
    float ej0 = e[j0], ej1 = e[j0 + 1], ej2 = e[j0 + 8], ej3 = e[j0 + 9];
    float wj0 = wsb[j0], wj1 = wsb[j0 + 1], wj2 = wsb[j0 + 8], wj3 = wsb[j0 + 9];

    uint4 u;
    u.x = pack_h2(bias_val(ei0, wi0, ej0, wj0, alpha, beta),
                  bias_val(ei0, wi0, ej1, wj1, alpha, beta));
    u.y = pack_h2(bias_val(ei1, wi1, ej0, wj0, alpha, beta),
                  bias_val(ei1, wi1, ej1, wj1, alpha, beta));
    u.z = pack_h2(bias_val(ei0, wi0, ej2, wj2, alpha, beta),
                  bias_val(ei0, wi0, ej3, wj3, alpha, beta));
    u.w = pack_h2(bias_val(ei1, wi1, ej2, wj2, alpha, beta),
                  bias_val(ei1, wi1, ej3, wj3, alpha, beta));
    bias8[t] = u;
}

// ---------------------------------------------------------------------------
// merged converter: x,wqkv -> fp16 hi; wproj -> fp16 hi/lo; + wind strength
// ---------------------------------------------------------------------------
#define N4_X (B_ * N_ * C_ / 4)
#define N4_WQKV (3 * C_ * C_ / 4)
#define N4_WPROJ (C_ * C_ / 4)
#define N4_TOTAL (N4_X + N4_WQKV + N4_WPROJ)

__global__ void convert_all(const float* __restrict__ x,
                            const float* __restrict__ wqkv,
                            const float* __restrict__ wproj,
                            const float* __restrict__ uwind,
                            const float* __restrict__ vwind,
                            __half* __restrict__ xh,
                            __half* __restrict__ wqh,
                            __half* __restrict__ wph, __half* __restrict__ wpl,
                            float* __restrict__ ws) {
    int i = blockIdx.x * blockDim.x + threadIdx.x;
    if (i >= N4_TOTAL) {
        int t = i - N4_TOTAL;
        if (t >= B_ * N_) return;
        int b = t >> 10;
        int n = t & 1023;
        int r = n >> 5;
        int c = n & 31;
        const float* ub = uwind + b * 4096;
        const float* vb = vwind + b * 4096;
        float s = 0.0f;
#pragma unroll
        for (int dr = 0; dr < 2; ++dr)
#pragma unroll
            for (int dc = 0; dc < 2; ++dc) {
                int idx = (2 * r + dr) * 64 + (2 * c + dc);
                float uu = ub[idx], vv = vb[idx];
                s += sqrtf(uu * uu + vv * vv + 1e-8f);
            }
        ws[t] = s * 0.25f;
        return;
    }
    if (i < N4_X + N4_WQKV) {
        const float* in = (i < N4_X) ? x : wqkv;
        __half* hi = (i < N4_X) ? xh : wqh;
        int off = (i < N4_X) ? i : (i - N4_X);
        float4 v = reinterpret_cast<const float4*>(in)[off];
        *reinterpret_cast<uint2*>(hi + 4 * off) =
            make_uint2(pack_h2(v.x, v.y), pack_h2(v.z, v.w));
    } else {
        int off = i - N4_X - N4_WQKV;
        float4 v = reinterpret_cast<const float4*>(wproj)[off];
        uint32_t h01, l01, h23, l23;
        split2h(v.x, v.y, h01, l01);
        split2h(v.z, v.w, h23, l23);
        *reinterpret_cast<uint2*>(wph + 4 * off) = make_uint2(h01, h23);
        *reinterpret_cast<uint2*>(wpl + 4 * off) = make_uint2(l01, l23);
    }
}

// ---------------------------------------------------------------------------
// single-term fp16 GEMM 128x128 (QKV): C = Ah*Bh^T, fp16 output.
// q tiles (bx<2) are pre-scaled by scale*log2e.
// ---------------------------------------------------------------------------
#define PITCH 40
#define QG_BUF_BYTES (2 * 128 * PITCH * 2)
#define QG_SMEM_BYTES (2 * QG_BUF_BYTES)

__global__ __launch_bounds__(256, 2)
void gemm_qkv(const __half* __restrict__ Ah, const __half* __restrict__ Bh,
              __half* __restrict__ Ch) {
    const int N = 768;
    extern __shared__ __align__(16) char smem_raw[];
    const uint32_t uS = smem_u32(smem_raw);

    const int tid = threadIdx.x;
    const int lane = tid & 31;
    const int wid = tid >> 5;
    const int wm = wid & 1;
    const int wn = wid >> 1;
    const int bx = blockIdx.x;
    const int by = blockIdx.y;

    const __half* Agh = Ah + (size_t)by * 128 * 256;
    const __half* Bgh = Bh + (size_t)bx * 128 * 256;

    float acc[4][4][4];
#pragma unroll
    for (int mt = 0; mt < 4; ++mt)
#pragma unroll
        for (int nt = 0; nt < 4; ++nt)
#pragma unroll
            for (int i = 0; i < 4; ++i) acc[mt][nt][i] = 0.0f;

    const uint32_t aoff =
        (uint32_t)((wm * 64 + (lane & 15)) * PITCH + ((lane & 16) ? 8 : 0)) * 2;
    const uint32_t boff =
        (uint32_t)((wn * 32 + (lane & 7) + ((lane & 16) ? 8 : 0)) * PITCH +
                   ((lane & 8) ? 8 : 0)) * 2;

    const int row0 = tid >> 2;
    const int c8 = (tid & 3) * 8;

#pragma unroll
    for (int i = 0; i < 2; ++i) {
        int row = row0 + i * 64;
        size_t g = (size_t)row * 256 + c8;
        uint32_t so = (uint32_t)(row * PITCH + c8) * 2;
        CP_ASYNC16(uS + so, Agh + g);
        CP_ASYNC16(uS + 10240 + so, Bgh + g);
    }
    CP_COMMIT();
    CP_WAIT0();
    __syncthreads();

#pragma unroll 1
    for (int kb = 0; kb < 8; ++kb) {
        const int p = kb & 1;
        const uint32_t bufb = uS + (uint32_t)p * QG_BUF_BYTES;

        if (kb < 7) {
            const uint32_t nb = uS + (uint32_t)(1 - p) * QG_BUF_BYTES;
#pragma unroll
            for (int i = 0; i < 2; ++i) {
                int row = row0 + i * 64;
                size_t g = (size_t)row * 256 + (kb + 1) * 32 + c8;
                uint32_t so = (uint32_t)(row * PITCH + c8) * 2;
                CP_ASYNC16(nb + so, Agh + g);
                CP_ASYNC16(nb + 10240 + so, Bgh + g);
            }
            CP_COMMIT();
        }

        const uint32_t uAh = bufb, uBh = bufb + 10240;

#pragma unroll
        for (int kk = 0; kk < 2; ++kk) {
            const uint32_t kof = (uint32_t)(kk * 16) * 2;
            uint32_t bhf[2][4];
#pragma unroll
            for (int ntp = 0; ntp < 2; ++ntp) {
                uint32_t ba = boff + (uint32_t)(ntp * 16 * PITCH) * 2 + kof;
                LDSM_X4(bhf[ntp][0], bhf[ntp][1], bhf[ntp][2], bhf[ntp][3], uBh + ba);
            }
#pragma unroll
            for (int mt = 0; mt < 4; ++mt) {
                uint32_t aa = aoff + (uint32_t)(mt * 16 * PITCH) * 2 + kof;
                uint32_t ah0, ah1, ah2, ah3;
                LDSM_X4(ah0, ah1, ah2, ah3, uAh + aa);
#pragma unroll
                for (int nt = 0; nt < 4; ++nt) {
                    const int ntp = nt >> 1;
                    const int hb = (nt & 1) * 2;
                    MMA_FP16(acc[mt][nt], ah0, ah1, ah2, ah3,
                             bhf[ntp][hb], bhf[ntp][hb + 1]);
                }
            }
        }

        if (kb < 7) CP_WAIT0();
        __syncthreads();
    }

    // q columns (bx<2) get scale*log2e folded in
    const float qs = (bx < 2) ? QSCALE_LG2 : 1.0f;
    const int gid = lane >> 2;
    const int tig = lane & 3;
#pragma unroll
    for (int mt = 0; mt < 4; ++mt) {
        int row = by * 128 + wm * 64 + mt * 16 + gid;
#pragma unroll
        for (int nt = 0; nt < 4; ++nt) {
            int col = bx * 128 + wn * 32 + nt * 8 + 2 * tig;
            *reinterpret_cast<uint32_t*>(Ch + (size_t)row * N + col) =
                pack_h2(acc[mt][nt][0] * qs, acc[mt][nt][1] * qs);
            *reinterpret_cast<uint32_t*>(Ch + (size_t)(row + 8) * N + col) =
                pack_h2(acc[mt][nt][2] * qs, acc[mt][nt][3] * qs);
        }
    }
}

// ---------------------------------------------------------------------------
// proj GEMM: 64x128 tiles, 2-term (A single fp16, B split), f32 + bias out.
// ---------------------------------------------------------------------------
#define P64_BUF_BYTES (64 * PITCH * 2 + 2 * 128 * PITCH * 2)   // 25600
#define P64_SMEM_BYTES (2 * P64_BUF_BYTES)                      // 51200

__global__ __launch_bounds__(256, 2)
void gemm_proj(const __half* __restrict__ Ah,
               const __half* __restrict__ Bh, const __half* __restrict__ Bl,
               const float* __restrict__ bias, float* __restrict__ C) {
    const int N = 256;
    extern __shared__ __align__(16) char smem_raw[];
    const uint32_t uS = smem_u32(smem_raw);

    const int tid = threadIdx.x;
    const int lane = tid & 31;
    const int wid = tid >> 5;
    const int wm = wid & 1;
    const int wn = wid >> 1;
    const int bx = blockIdx.x;
    const int by = blockIdx.y;

    const __half* Agh = Ah + (size_t)by * 64 * 256;
    const __half* Bgh = Bh + (size_t)bx * 128 * 256;
    const __half* Bgl = Bl + (size_t)bx * 128 * 256;

    float acc[2][4][4];
#pragma unroll
    for (int mt = 0; mt < 2; ++mt)
#pragma unroll
        for (int nt = 0; nt < 4; ++nt)
#pragma unroll
            for (int i = 0; i < 4; ++i) acc[mt][nt][i] = 0.0f;

    const uint32_t aoff =
        (uint32_t)((wm * 32 + (lane & 15)) * PITCH + ((lane & 16) ? 8 : 0)) * 2;
    const uint32_t boff =
        (uint32_t)((wn * 32 + (lane & 7) + ((lane & 16) ? 8 : 0)) * PITCH +
                   ((lane & 8) ? 8 : 0)) * 2;

    const int arow = tid >> 2;
    const int ac8 = (tid & 3) * 8;
    const uint32_t aso = (uint32_t)(arow * PITCH + ac8) * 2;
    const int brow0 = tid >> 2;

#pragma unroll 1
    for (int kb = -1; kb < 8; ++kb) {
        if (kb < 7) {
            const uint32_t nb = uS + (uint32_t)((kb + 1) & 1) * P64_BUF_BYTES;
            int kof = (kb + 1) * 32;
            {
                size_t g = (size_t)arow * 256 + kof + ac8;
                CP_ASYNC16(nb + aso, Agh + g);
            }
#pragma unroll
            for (int i = 0; i < 2; ++i) {
                int row = brow0 + i * 64;
                size_t g = (size_t)row * 256 + kof + ac8;
                uint32_t so = (uint32_t)(row * PITCH + ac8) * 2;
                CP_ASYNC16(nb + 5120 + so, Bgh + g);
                CP_ASYNC16(nb + 15360 + so, Bgl + g);
            }
            CP_COMMIT();
        }
        if (kb < 0) { CP_WAIT0(); __syncthreads(); continue; }

        const uint32_t bufb = uS + (uint32_t)(kb & 1) * P64_BUF_BYTES;
        const uint32_t uAh = bufb;
        const uint32_t uBh = bufb + 5120, uBl = bufb + 15360;

#pragma unroll
        for (int kk = 0; kk < 2; ++kk) {
            const uint32_t kof = (uint32_t)(kk * 16) * 2;
            uint32_t bhf[2][4], blf[2][4];
#pragma unroll
            for (int ntp = 0; ntp < 2; ++ntp) {
                uint32_t ba = boff + (uint32_t)(ntp * 16 * PITCH) * 2 + kof;
                LDSM_X4(bhf[ntp][0], bhf[ntp][1], bhf[ntp][2], bhf[ntp][3], uBh + ba);
                LDSM_X4(blf[ntp][0], blf[ntp][1], blf[ntp][2], blf[ntp][3], uBl + ba);
            }
#pragma unroll
            for (int mt = 0; mt < 2; ++mt) {
                uint32_t aa = aoff + (uint32_t)(mt * 16 * PITCH) * 2 + kof;
                uint32_t ah0, ah1, ah2, ah3;
                LDSM_X4(ah0, ah1, ah2, ah3, uAh + aa);
#pragma unroll
                for (int nt = 0; nt < 4; ++nt) {
                    const int ntp = nt >> 1;
                    const int hb = (nt & 1) * 2;
                    MMA_FP16(acc[mt][nt], ah0, ah1, ah2, ah3,
                             bhf[ntp][hb], bhf[ntp][hb + 1]);
                    MMA_FP16(acc[mt][nt], ah0, ah1, ah2, ah3,
                             blf[ntp][hb], blf[ntp][hb + 1]);
                }
            }
        }

        if (kb < 7) CP_WAIT0();
        __syncthreads();
    }

    const int gid = lane >> 2;
    const int tig = lane & 3;
#pragma unroll
    for (int mt = 0; mt < 2; ++mt) {
        int row = by * 64 + wm * 32 + mt * 16 + gid;
#pragma unroll
        for (int nt = 0; nt < 4; ++nt) {
            int col = bx * 128 + wn * 32 + nt * 8 + 2 * tig;
            float2 bb = *reinterpret_cast<const float2*>(bias + col);
            float2 v0 = make_float2(acc[mt][nt][0] + bb.x, acc[mt][nt][1] + bb.y);
            float2 v1 = make_float2(acc[mt][nt][2] + bb.x, acc[mt][nt][3] + bb.y);
            *reinterpret_cast<float2*>(C + (size_t)row * N + col) = v0;
            *reinterpret_cast<float2*>(C + (size_t)(row + 8) * N + col) = v1;
        }
    }
}

// ---------------------------------------------------------------------------
// pure-fp16 flash attention, log2-domain softmax:
// S accumulators initialized with bias*log2e; q pre-scaled; exp = ex2.approx.
// Single fp16 output.
// ---------------------------------------------------------------------------
#define ATTN_Q_BYTES (128 * PITCH * 2)
#define ATTN_BUF_BYTES (2 * 64 * PITCH * 2)
#define ATTN_SMEM_BYTES (ATTN_Q_BYTES + 2 * ATTN_BUF_BYTES)

__global__ __launch_bounds__(256, 2)
void attn_mma(const __half* __restrict__ qkvh,
              const uint4* __restrict__ bias8,
              __half* __restrict__ outh) {
    extern __shared__ __align__(16) char smem_raw[];
    __half* Qh = reinterpret_cast<__half*>(smem_raw);
    const uint32_t uQh = smem_u32(Qh);
    const uint32_t uKV = uQh + ATTN_Q_BYTES;

    const int tid = threadIdx.x;
    const int lane = tid & 31;
    const int w = tid >> 5;
    const int gid = lane >> 2;
    const int tig = lane & 3;
    const int qc = blockIdx.x;
    const int h  = blockIdx.y;
    const int b  = blockIdx.z;

    const int qrow0 = b * N_ + qc * 128;

    const int krow = tid >> 2;
    const int kc8 = (tid & 3) * 8;
    const uint32_t kso = (uint32_t)(krow * PITCH + kc8) * 2;

    // prologue: stage kt=0 (Kh|Vh)
    {
        size_t g = (size_t)(b * N_ + krow) * 768 + 256 + h * HD_ + kc8;
        CP_ASYNC16(uKV + kso, qkvh + g);
        CP_ASYNC16(uKV + 5120 + kso, qkvh + g + 256);
        CP_COMMIT();
    }

    // stage Qh (pre-scaled by scale*log2e)
    {
        int row = tid >> 1;
        int c8 = (tid & 1) * 16;
        size_t g = (size_t)(qrow0 + row) * 768 + h * HD_ + c8;
        int so = row * PITCH + c8;
        *reinterpret_cast<uint4*>(&Qh[so]) =
            *reinterpret_cast<const uint4*>(qkvh + g);
        *reinterpret_cast<uint4*>(&Qh[so + 8]) =
            *reinterpret_cast<const uint4*>(qkvh + g + 8);
    }
    CP_WAIT0();
    __syncthreads();

    const uint32_t aoff =
        (uint32_t)((w * 16 + (lane & 15)) * PITCH + ((lane & 16) ? 8 : 0)) * 2;
    const uint32_t koff =
        (uint32_t)(((lane & 7) + ((lane & 16) ? 8 : 0)) * PITCH +
                   ((lane & 8) ? 8 : 0)) * 2;
    const uint32_t voff =
        (uint32_t)((lane & 15) * PITCH + ((lane & 16) ? 8 : 0)) * 2;

    // hoisted Qh fragments
    uint32_t qh[2][4];
#pragma unroll
    for (int kk = 0; kk < 2; ++kk) {
        const uint32_t kof = (uint32_t)(kk * 16) * 2;
        LDSM_X4(qh[kk][0], qh[kk][1], qh[kk][2], qh[kk][3], uQh + aoff + kof);
    }

    float l0 = 0.0f, l1 = 0.0f;
    float oacc[4][4];
#pragma unroll
    for (int nt = 0; nt < 4; ++nt)
#pragma unroll
        for (int i = 0; i < 4; ++i) oacc[nt][i] = 0.0f;

    const uint4* bias_tb =
        bias8 + ((size_t)((b * 8 + qc) * 16)) * 1024 + w * 128 + lane;

#pragma unroll 1
    for (int kt = 0; kt < 16; ++kt) {
        const int p = kt & 1;
        const uint32_t bufb = uKV + (uint32_t)p * ATTN_BUF_BYTES;

        if (kt < 15) {
            const uint32_t nb = uKV + (uint32_t)(1 - p) * ATTN_BUF_BYTES;
            size_t g = (size_t)(b * N_ + (kt + 1) * 64 + krow) * 768 + 256 +
                       h * HD_ + kc8;
            CP_ASYNC16(nb + kso, qkvh + g);
            CP_ASYNC16(nb + 5120 + kso, qkvh + g + 256);
            CP_COMMIT();
        }

        const uint32_t uKh = bufb;
        const uint32_t uVh = bufb + 5120;

        // ---- init S accumulators with bias*log2e (fp16 -> f32) ----
        float sacc[8][4];
        {
            const uint4* bt = bias_tb + kt * 1024;
#pragma unroll
            for (int ntp = 0; ntp < 4; ++ntp) {
                uint4 u = bt[ntp * 32];
                float2 f0 = unpack_h2(u.x);
                float2 f1 = unpack_h2(u.y);
                float2 f2 = unpack_h2(u.z);
                float2 f3 = unpack_h2(u.w);
                const int nt0 = 2 * ntp;
                sacc[nt0][0] = f0.x; sacc[nt0][1] = f0.y;
                sacc[nt0][2] = f1.x; sacc[nt0][3] = f1.y;
                sacc[nt0 + 1][0] = f2.x; sacc[nt0 + 1][1] = f2.y;
                sacc[nt0 + 1][2] = f3.x; sacc[nt0 + 1][3] = f3.y;
            }
        }

        // ---- S += Qh*Kh (log2-scaled q; result = s*scale*lg2e + bias*lg2e) ----
#pragma unroll
        for (int kk = 0; kk < 2; ++kk) {
            const uint32_t kof = (uint32_t)(kk * 16) * 2;
            uint32_t bh[4][4];
#pragma unroll
            for (int ntp = 0; ntp < 4; ++ntp) {
                uint32_t ba = koff + (uint32_t)(ntp * 16 * PITCH) * 2 + kof;
                LDSM_X4(bh[ntp][0], bh[ntp][1], bh[ntp][2], bh[ntp][3], uKh + ba);
            }
#pragma unroll
            for (int nt = 0; nt < 8; ++nt) {
                const int ntp = nt >> 1;
                const int hb = (nt & 1) * 2;
                MMA_FP16(sacc[nt], qh[kk][0], qh[kk][1], qh[kk][2], qh[kk][3],
                         bh[ntp][hb], bh[ntp][hb + 1]);
            }
        }

        // ---- exp = bare ex2 ----
#pragma unroll
        for (int nt = 0; nt < 8; ++nt) {
            float p0 = ex2(sacc[nt][0]);
            float p1 = ex2(sacc[nt][1]);
            float p2 = ex2(sacc[nt][2]);
            float p3 = ex2(sacc[nt][3]);
            sacc[nt][0] = p0; sacc[nt][1] = p1;
            sacc[nt][2] = p2; sacc[nt][3] = p3;
            l0 += p0 + p1;
            l1 += p2 + p3;
        }

        // ---- O += Ph*Vh ----
#pragma unroll
        for (int ks = 0; ks < 4; ++ks) {
            uint32_t pah[4];
            pah[0] = pack_h2(sacc[2 * ks][0],     sacc[2 * ks][1]);
            pah[1] = pack_h2(sacc[2 * ks][2],     sacc[2 * ks][3]);
            pah[2] = pack_h2(sacc[2 * ks + 1][0], sacc[2 * ks + 1][1]);
            pah[3] = pack_h2(sacc[2 * ks + 1][2], sacc[2 * ks + 1][3]);

            uint32_t vh[2][4];
#pragma unroll
            for (int ntp = 0; ntp < 2; ++ntp) {
                uint32_t va = voff + (uint32_t)(ks * 16 * PITCH + ntp * 16) * 2;
                LDSM_X4T(vh[ntp][0], vh[ntp][1], vh[ntp][2], vh[ntp][3], uVh + va);
            }
#pragma unroll
            for (int nt = 0; nt < 4; ++nt) {
                const int ntp = nt >> 1;
                const int hb = (nt & 1) * 2;
                MMA_FP16(oacc[nt], pah[0], pah[1], pah[2], pah[3],
                         vh[ntp][hb], vh[ntp][hb + 1]);
            }
        }

        if (kt < 15) CP_WAIT0();
        __syncthreads();
    }

    // ---- one-time l reduction over the 4-lane row group ----
    l0 += __shfl_xor_sync(0xffffffffu, l0, 1);
    l0 += __shfl_xor_sync(0xffffffffu, l0, 2);
    l1 += __shfl_xor_sync(0xffffffffu, l1, 1);
    l1 += __shfl_xor_sync(0xffffffffu, l1, 2);

    // ---- epilogue: single fp16 output ----
    const float inv0 = 1.0f / l0;
    const float inv1 = 1.0f / l1;
    const int row0 = qrow0 + w * 16 + gid;
#pragma unroll
    for (int nt = 0; nt < 4; ++nt) {
        int col = h * HD_ + nt * 8 + 2 * tig;
        *reinterpret_cast<uint32_t*>(outh + (size_t)row0 * C_ + col) =
            pack_h2(oacc[nt][0] * inv0, oacc[nt][1] * inv0);
        *reinterpret_cast<uint32_t*>(outh + (size_t)(row0 + 8) * C_ + col) =
            pack_h2(oacc[nt][2] * inv1, oacc[nt][3] * inv1);
    }
}

// ---------------------------------------------------------------------------
// launch
// ---------------------------------------------------------------------------
extern "C" void kernel_launch(void* const* d_in, const int* in_sizes, int n_in,
                              void* d_out, int out_size) {
    const float* x     = (const float*)d_in[0];
    const float* elev  = (const float*)d_in[1];
    const float* uw    = (const float*)d_in[2];
    const float* vw    = (const float*)d_in[3];
    const float* wqkv  = (const float*)d_in[4];
    const float* wproj = (const float*)d_in[5];
    const float* bproj = (const float*)d_in[6];
    const float* alpha = (const float*)d_in[7];
    const float* beta  = (const float*)d_in[8];
    float* out = (float*)d_out;

    float *ws_p;
    uint4* bias8_p;
    __half *xh, *wqkvh, *wprojh, *wprojl;
    __half *qkvh, *attnh;
    cudaGetSymbolAddress((void**)&ws_p, g_ws);
    cudaGetSymbolAddress((void**)&bias8_p, g_bias8);
    cudaGetSymbolAddress((void**)&xh, g_xh);
    cudaGetSymbolAddress((void**)&wqkvh, g_wqkvh);
    cudaGetSymbolAddress((void**)&wprojh, g_wprojh);
    cudaGetSymbolAddress((void**)&wprojl, g_wprojl);
    cudaGetSymbolAddress((void**)&qkvh, g_qkvh);
    cudaGetSymbolAddress((void**)&attnh, g_attnh);

    cudaFuncSetAttribute(gemm_qkv,
                         cudaFuncAttributeMaxDynamicSharedMemorySize,
                         QG_SMEM_BYTES);
    cudaFuncSetAttribute(gemm_proj,
                         cudaFuncAttributeMaxDynamicSharedMemorySize,
                         P64_SMEM_BYTES);
    cudaFuncSetAttribute(attn_mma,
                         cudaFuncAttributeMaxDynamicSharedMemorySize,
                         ATTN_SMEM_BYTES);

    // 1) merged converts + wind strength (fused)
    convert_all<<<(N4_TOTAL + B_ * N_ + 255) / 256, 256>>>(
        x, wqkv, wproj, uw, vw, xh, wqkvh, wprojh, wprojl, ws_p);

    // 2) fragment-ordered fp16 bias (*log2e)
    bias_perm_kernel<<<B_ * N_ * N_ / 8 / 256, 256>>>(elev, ws_p, alpha, beta,
                                                      bias8_p);

    // 3) qkv = x @ w_qkv^T (single-term fp16; q pre-scaled)
    gemm_qkv<<<dim3(6, 64), 256, QG_SMEM_BYTES>>>(xh, wqkvh, qkvh);

    // 4) pure-fp16 flash attention (log2 softmax, single fp16 out)
    attn_mma<<<dim3(8, NH_, B_), 256, ATTN_SMEM_BYTES>>>(
        qkvh, bias8_p, attnh);

    // 5) out = attn @ w_proj^T + b_proj (2-term)
    gemm_proj<<<dim3(2, 128), 256, P64_SMEM_BYTES>>>(
        attnh, wprojh, wprojl, bproj, out);
}